// round 11
// baseline (speedup 1.0000x reference)
#include <cuda_runtime.h>
#include <cuda_bf16.h>
#include <math.h>
#include <stdint.h>

// ---------------------------------------------------------------------------
// QueryInstanceDecoder: bf16 split-precision mma.sync pipeline, v4.
// v3 + 128x256 tiles for the point pipeline (tpair256, 512 thr), LN/GELU and
// invpe finalization fused into GEMM epilogues (lnprep/combine_ssq removed),
// weights pre-transposed so the new kernel uses only the proven BT=1 layout.
// N=262144, C_IN=72, D=256, Q=128.
// d_out (floats): mask_logits[128*N] | score[128] | point_embed[N*256] | refined[128*256]
// ---------------------------------------------------------------------------

#define DEVI __device__ __forceinline__

DEVI float geluf(float x) { return 0.5f * x * (1.0f + erff(x * 0.70710678118654752f)); }

DEVI unsigned pack2(__nv_bfloat16 a, __nv_bfloat16 b) {
    return (unsigned)__bfloat16_as_ushort(a) | ((unsigned)__bfloat16_as_ushort(b) << 16);
}
DEVI void split2(float x, __nv_bfloat16& h, __nv_bfloat16& l) {
    h = __float2bfloat16(x);
    l = __float2bfloat16(x - __bfloat162float(h));
}
DEVI float upk_lo(unsigned u) { return __bfloat162float(__ushort_as_bfloat16((unsigned short)(u & 0xffff))); }
DEVI float upk_hi(unsigned u) { return __bfloat162float(__ushort_as_bfloat16((unsigned short)(u >> 16))); }

DEVI void mma16816(float* c, const unsigned* a, const unsigned* b) {
    asm volatile(
        "mma.sync.aligned.m16n8k16.row.col.f32.bf16.bf16.f32 "
        "{%0,%1,%2,%3},{%4,%5,%6,%7},{%8,%9},{%0,%1,%2,%3};"
        : "+f"(c[0]), "+f"(c[1]), "+f"(c[2]), "+f"(c[3])
        : "r"(a[0]), "r"(a[1]), "r"(a[2]), "r"(a[3]), "r"(b[0]), "r"(b[1]));
}
DEVI uint32_t smem_u32(const void* p) {
    uint32_t a;
    asm("{ .reg .u64 t; cvta.to.shared.u64 t, %1; cvt.u32.u64 %0, t; }" : "=r"(a) : "l"(p));
    return a;
}
#define LDSM4(r, a) \
    asm volatile("ldmatrix.sync.aligned.m8n8.x4.shared.b16 {%0,%1,%2,%3},[%4];" \
        : "=r"((r)[0]), "=r"((r)[1]), "=r"((r)[2]), "=r"((r)[3]) : "r"(a))
#define LDSM4T(r, a) \
    asm volatile("ldmatrix.sync.aligned.m8n8.x4.trans.shared.b16 {%0,%1,%2,%3},[%4];" \
        : "=r"((r)[0]), "=r"((r)[1]), "=r"((r)[2]), "=r"((r)[3]) : "r"(a))

DEVI void cpasync16(uint32_t dst, const void* src) {
    asm volatile("cp.async.cg.shared.global [%0], [%1], 16;" :: "r"(dst), "l"(src));
}
DEVI void cpcommit() { asm volatile("cp.async.commit_group;"); }
DEVI void cpwait1()  { asm volatile("cp.async.wait_group 1;"); }
DEVI void cpwait0()  { asm volatile("cp.async.wait_group 0;"); }

#define SWZ(o) ((unsigned)(o) ^ ((((unsigned)(o)) >> 3) & 0x70))
#define BSTRIDE0 288

// ---------------- scratch (static device memory; no allocations) -----------
#define NMAX 262144
__device__ __nv_bfloat16 g_pfH[(size_t)NMAX * 96], g_pfL[(size_t)NMAX * 96];
__device__ __nv_bfloat16 g_xH[(size_t)NMAX * 256], g_xL[(size_t)NMAX * 256];
__device__ __nv_bfloat16 g_aH[(size_t)NMAX * 256], g_aL[(size_t)NMAX * 256];
__device__ __nv_bfloat16 g_hH[(size_t)NMAX * 256], g_hL[(size_t)NMAX * 256];
__device__ __nv_bfloat16 g_peH[(size_t)NMAX * 256], g_peL[(size_t)NMAX * 256];
__device__ __nv_bfloat16 g_emH[(size_t)128 * NMAX], g_emL[(size_t)128 * NMAX];
__device__ __nv_bfloat16 g_w1H[256 * 96],  g_w1L[256 * 96];    // transposed [n][k]
__device__ __nv_bfloat16 g_w2H[256 * 256], g_w2L[256 * 256];   // transposed [n][k]
__device__ __nv_bfloat16 g_w3H[256 * 256], g_w3L[256 * 256];
__device__ __nv_bfloat16 g_w4H[256 * 256], g_w4L[256 * 256];
__device__ __nv_bfloat16 g_qmH[128 * 256], g_qmL[128 * 256];
__device__ float g_invpe[NMAX];
__device__ float g_meanQ[128], g_rstdQ[128];
__device__ float g_A2q[128 * 256];
__device__ float g_qe[128 * 256];
__device__ float g_invq[128];
__device__ float g_spart[(size_t)2 * NMAX];
__device__ float g_Ppart[256 * 128 * 256];

// ---------------- epilogue flags --------------------------------------------
#define EPI_BIAS    1
#define EPI_GELU    2
#define EPI_RESIDP  4
#define EPI_OUTF32  8
#define EPI_OUTPAIR 16
#define EPI_SPART   32
#define EPI_CSCALE  64
#define EPI_EXPPAIR 128
#define EPI_SSQ     256
#define EPI_LNPAIR  512
#define EPI_LNGELU  1024

// =============================================================================
// tpair256: C[128 x 256] = A_pairs[128xK] @ B_pairs^T (B image [n][k], BT=1
// layout only). 512 threads, 16 warps (2 x 8), warp tile 64x32.
// Split precision: Ah*Bh + Ah*Bl + Al*Bh. cp.async double-buffered, K-chunk 32.
// Optional fused epilogues: BIAS, GELU, RESIDP(pairs), OUTF32, OUTPAIR,
// LNPAIR(+LNGELU) -> second pair output = (gelu o) LN(v), SSQ -> invout row norms.
// =============================================================================
#define STG256 49152          // per stage: AH 8K | AL 8K | BH 16K | BL 16K
#define SP_OFF (2 * STG256)   // spS 4K | spSS 4K | marr .5K | rarr .5K | gam 1K | bet 1K
#define SMEM256 (SP_OFF + 4096 + 4096 + 512 + 512 + 1024 + 1024)

template <int EPI>
__global__ __launch_bounds__(512, 1)
void tpair256(const __nv_bfloat16* __restrict__ Ah, const __nv_bfloat16* __restrict__ Al, int lda,
              const __nv_bfloat16* __restrict__ Bh, const __nv_bfloat16* __restrict__ Bl, int ldb,
              const float* __restrict__ bias,
              float* __restrict__ outf, size_t ldout,
              __nv_bfloat16* __restrict__ oh, __nv_bfloat16* __restrict__ ol,
              __nv_bfloat16* __restrict__ o2h, __nv_bfloat16* __restrict__ o2l,
              const __nv_bfloat16* __restrict__ resH, const __nv_bfloat16* __restrict__ resL,
              const float* __restrict__ gam, const float* __restrict__ bet,
              float* __restrict__ invout, int Kblk)
{
    extern __shared__ __align__(1024) unsigned char sm[];
    const uint32_t sb = smem_u32(sm);
    float* spS  = (float*)(sm + SP_OFF);
    float* spSS = (float*)(sm + SP_OFF + 4096);
    float* marr = (float*)(sm + SP_OFF + 8192);
    float* rarr = (float*)(sm + SP_OFF + 8704);
    float* sgam = (float*)(sm + SP_OFF + 9216);
    float* sbet = (float*)(sm + SP_OFF + 10240);

    const int tid  = threadIdx.x;
    const int row0 = blockIdx.x * 128;
    const int nch  = Kblk >> 5;

    if (EPI & EPI_LNPAIR) {
        if (tid < 256) { sgam[tid] = gam[tid]; sbet[tid] = bet[tid]; }
    }

    // ---- loader indices ----
    const int arow = tid >> 2, ak0 = (tid & 3) * 8;        // A: 128 rows x 32k, 1 chunk/thread
    const int brow = tid >> 1, bk0 = (tid & 1) * 16;       // B: 256 rows x 32k, 2 chunks/thread
    const unsigned dA  = SWZ(arow * 64 + ak0 * 2);
    const unsigned dB  = SWZ(brow * 64 + bk0 * 2);
    const unsigned dB2 = SWZ(brow * 64 + bk0 * 2 + 16);
    const __nv_bfloat16* ApH = Ah + (size_t)(row0 + arow) * lda + ak0;
    const __nv_bfloat16* ApL = Al + (size_t)(row0 + arow) * lda + ak0;
    const __nv_bfloat16* BpH = Bh + (size_t)brow * ldb + bk0;
    const __nv_bfloat16* BpL = Bl + (size_t)brow * ldb + bk0;

    auto issue = [&](int c) {
        const int kc = c * 32;
        const uint32_t st = sb + (c & 1) * STG256;
        cpasync16(st + dA, ApH + kc);
        cpasync16(st + 8192 + dA, ApL + kc);
        cpasync16(st + 16384 + dB,  BpH + kc);
        cpasync16(st + 16384 + dB2, BpH + kc + 8);
        cpasync16(st + 32768 + dB,  BpL + kc);
        cpasync16(st + 32768 + dB2, BpL + kc + 8);
        cpcommit();
    };

    // ---- compute indices ----
    const int lane = tid & 31, w = tid >> 5;
    const int mw = w >> 3, nw = w & 7;                     // 2 x 8 warps
    const int g = lane >> 2, tig = lane & 3;
    const int lrow = (lane & 7) + ((lane >> 3) & 1) * 8;
    const int lkh  = (lane >> 4) * 16;

    float acc[4][4][4];
#pragma unroll
    for (int mi = 0; mi < 4; mi++)
#pragma unroll
        for (int ni = 0; ni < 4; ni++)
#pragma unroll
            for (int e = 0; e < 4; e++) acc[mi][ni][e] = 0.f;

    auto compute = [&](int c) {
        const uint32_t st = sb + (c & 1) * STG256;
#pragma unroll
        for (int ks = 0; ks < 2; ks++) {
            unsigned ah[4][4], al[4][4];
#pragma unroll
            for (int mi = 0; mi < 4; mi++) {
                const int r = mw * 64 + mi * 16 + lrow;
                const unsigned off = SWZ(r * 64 + ks * 32 + lkh);
                LDSM4(ah[mi], st + off);
                LDSM4(al[mi], st + 8192 + off);
            }
#pragma unroll
            for (int nb = 0; nb < 2; nb++) {
                unsigned bh[4], bl[4];
                const int n = nw * 32 + nb * 16 + lrow;
                const unsigned off = SWZ(n * 64 + ks * 32 + lkh);
                LDSM4(bh, st + 16384 + off);
                LDSM4(bl, st + 32768 + off);
                unsigned beh[2] = {bh[0], bh[2]}, boh[2] = {bh[1], bh[3]};
                unsigned bel[2] = {bl[0], bl[2]}, bol[2] = {bl[1], bl[3]};
#pragma unroll
                for (int mi = 0; mi < 4; mi++) {
                    mma16816(acc[mi][2 * nb],     ah[mi], beh);
                    mma16816(acc[mi][2 * nb],     ah[mi], bel);
                    mma16816(acc[mi][2 * nb],     al[mi], beh);
                    mma16816(acc[mi][2 * nb + 1], ah[mi], boh);
                    mma16816(acc[mi][2 * nb + 1], ah[mi], bol);
                    mma16816(acc[mi][2 * nb + 1], al[mi], boh);
                }
            }
        }
    };

    // ---- pipelined main loop ----
    issue(0);
    for (int c = 0; c < nch; c++) {
        if (c + 1 < nch) { issue(c + 1); cpwait1(); } else { cpwait0(); }
        __syncthreads();
        compute(c);
        __syncthreads();
    }

    // ---- epilogue pass A: finalize v into acc, write OUTF32, gather stats ----
    float sS0[4], sS1[4], sSS0[4], sSS1[4];
#pragma unroll
    for (int mi = 0; mi < 4; mi++) { sS0[mi] = sS1[mi] = sSS0[mi] = sSS1[mi] = 0.f; }

#pragma unroll
    for (int mi = 0; mi < 4; mi++) {
        const int r = row0 + mw * 64 + mi * 16 + g;
#pragma unroll
        for (int ni = 0; ni < 4; ni++) {
            const int colG = nw * 32 + ni * 8 + 2 * tig;
            float v0 = acc[mi][ni][0], v1 = acc[mi][ni][1];
            float v2 = acc[mi][ni][2], v3 = acc[mi][ni][3];
            if (EPI & EPI_BIAS) {
                float2 bb = *(const float2*)(bias + colG);
                v0 += bb.x; v1 += bb.y; v2 += bb.x; v3 += bb.y;
            }
            if (EPI & EPI_GELU) {
                v0 = geluf(v0); v1 = geluf(v1); v2 = geluf(v2); v3 = geluf(v3);
            }
            if (EPI & EPI_RESIDP) {
                unsigned uh0 = *(const unsigned*)(resH + (size_t)r * 256 + colG);
                unsigned ul0 = *(const unsigned*)(resL + (size_t)r * 256 + colG);
                unsigned uh1 = *(const unsigned*)(resH + (size_t)(r + 8) * 256 + colG);
                unsigned ul1 = *(const unsigned*)(resL + (size_t)(r + 8) * 256 + colG);
                v0 += upk_lo(uh0) + upk_lo(ul0); v1 += upk_hi(uh0) + upk_hi(ul0);
                v2 += upk_lo(uh1) + upk_lo(ul1); v3 += upk_hi(uh1) + upk_hi(ul1);
            }
            if (EPI & EPI_OUTF32) {
                *(float2*)(outf + (size_t)r * ldout + colG)       = make_float2(v0, v1);
                *(float2*)(outf + (size_t)(r + 8) * ldout + colG) = make_float2(v2, v3);
            }
            if (EPI & EPI_LNPAIR) {
                sS0[mi] += v0 + v1; sS1[mi] += v2 + v3;
            }
            if (EPI & (EPI_SSQ | EPI_LNPAIR)) {
                sSS0[mi] += v0 * v0 + v1 * v1;
                sSS1[mi] += v2 * v2 + v3 * v3;
            }
            acc[mi][ni][0] = v0; acc[mi][ni][1] = v1;
            acc[mi][ni][2] = v2; acc[mi][ni][3] = v3;
        }
    }

    // ---- reduction (row stats across 8 nw warps + 4 tig lanes) ----
    if (EPI & (EPI_SSQ | EPI_LNPAIR)) {
#pragma unroll
        for (int mi = 0; mi < 4; mi++) {
            float a0 = sS0[mi], a1 = sS1[mi], b0 = sSS0[mi], b1 = sSS1[mi];
            a0 += __shfl_xor_sync(0xffffffffu, a0, 1); a0 += __shfl_xor_sync(0xffffffffu, a0, 2);
            a1 += __shfl_xor_sync(0xffffffffu, a1, 1); a1 += __shfl_xor_sync(0xffffffffu, a1, 2);
            b0 += __shfl_xor_sync(0xffffffffu, b0, 1); b0 += __shfl_xor_sync(0xffffffffu, b0, 2);
            b1 += __shfl_xor_sync(0xffffffffu, b1, 1); b1 += __shfl_xor_sync(0xffffffffu, b1, 2);
            if (tig == 0) {
                const int lr = mw * 64 + mi * 16 + g;
                spS[nw * 128 + lr]      = a0;
                spS[nw * 128 + lr + 8]  = a1;
                spSS[nw * 128 + lr]     = b0;
                spSS[nw * 128 + lr + 8] = b1;
            }
        }
        __syncthreads();
        if (tid < 128) {
            float s = 0.f, ss = 0.f;
#pragma unroll
            for (int ww = 0; ww < 8; ww++) {
                s  += spS[ww * 128 + tid];
                ss += spSS[ww * 128 + tid];
            }
            if (EPI & EPI_LNPAIR) {
                float m = s * (1.0f / 256.0f);
                marr[tid] = m;
                rarr[tid] = rsqrtf(ss * (1.0f / 256.0f) - m * m + 1e-5f);
            }
            if (EPI & EPI_SSQ)
                invout[row0 + tid] = 1.0f / fmaxf(sqrtf(ss), 1e-12f);
        }
        __syncthreads();
    }

    // ---- epilogue pass B: pair writes ----
    if (EPI & (EPI_OUTPAIR | EPI_LNPAIR)) {
#pragma unroll
        for (int mi = 0; mi < 4; mi++) {
            const int lr = mw * 64 + mi * 16 + g;
            const int r = row0 + lr;
            float m0 = 0.f, r0 = 0.f, m1 = 0.f, r1 = 0.f;
            if (EPI & EPI_LNPAIR) {
                m0 = marr[lr]; r0 = rarr[lr];
                m1 = marr[lr + 8]; r1 = rarr[lr + 8];
            }
#pragma unroll
            for (int ni = 0; ni < 4; ni++) {
                const int colG = nw * 32 + ni * 8 + 2 * tig;
                float v0 = acc[mi][ni][0], v1 = acc[mi][ni][1];
                float v2 = acc[mi][ni][2], v3 = acc[mi][ni][3];
                if (EPI & EPI_OUTPAIR) {
                    __nv_bfloat16 h0, l0, h1, l1;
                    split2(v0, h0, l0); split2(v1, h1, l1);
                    *(unsigned*)(oh + (size_t)r * 256 + colG) = pack2(h0, h1);
                    *(unsigned*)(ol + (size_t)r * 256 + colG) = pack2(l0, l1);
                    split2(v2, h0, l0); split2(v3, h1, l1);
                    *(unsigned*)(oh + (size_t)(r + 8) * 256 + colG) = pack2(h0, h1);
                    *(unsigned*)(ol + (size_t)(r + 8) * 256 + colG) = pack2(l0, l1);
                }
                if (EPI & EPI_LNPAIR) {
                    const float g0 = sgam[colG], g1 = sgam[colG + 1];
                    const float b0 = sbet[colG], b1 = sbet[colG + 1];
                    float t0 = (v0 - m0) * r0 * g0 + b0;
                    float t1 = (v1 - m0) * r0 * g1 + b1;
                    float t2 = (v2 - m1) * r1 * g0 + b0;
                    float t3 = (v3 - m1) * r1 * g1 + b1;
                    if (EPI & EPI_LNGELU) {
                        t0 = geluf(t0); t1 = geluf(t1); t2 = geluf(t2); t3 = geluf(t3);
                    }
                    __nv_bfloat16 h0, l0, h1, l1;
                    split2(t0, h0, l0); split2(t1, h1, l1);
                    *(unsigned*)(o2h + (size_t)r * 256 + colG) = pack2(h0, h1);
                    *(unsigned*)(o2l + (size_t)r * 256 + colG) = pack2(l0, l1);
                    split2(t2, h0, l0); split2(t3, h1, l1);
                    *(unsigned*)(o2h + (size_t)(r + 8) * 256 + colG) = pack2(h0, h1);
                    *(unsigned*)(o2l + (size_t)(r + 8) * 256 + colG) = pack2(l0, l1);
                }
            }
        }
    }
}

// =============================================================================
// Old 128x128 pair GEMM (mask + aggregation paths) — unchanged from R9 (passing).
// =============================================================================
template <int EPI, int BT>
__global__ __launch_bounds__(256, 2)
void tpair(const __nv_bfloat16* __restrict__ Ah, const __nv_bfloat16* __restrict__ Al, int lda,
           const __nv_bfloat16* __restrict__ Bh, const __nv_bfloat16* __restrict__ Bl, int ldb,
           const float* __restrict__ bias,
           float* __restrict__ outf, size_t ldout, size_t zstride,
           __nv_bfloat16* __restrict__ oh, __nv_bfloat16* __restrict__ ol, size_t opitch,
           const __nv_bfloat16* __restrict__ resH, const __nv_bfloat16* __restrict__ resL,
           const float* __restrict__ cscale, float* __restrict__ spart, size_t spitch,
           int Kblk)
{
    constexpr int BSZ = BT ? 8192 : 9216;
    constexpr int STG = 16384 + 2 * BSZ;
    extern __shared__ __align__(1024) unsigned char sm[];
    const uint32_t sb = smem_u32(sm);
    float* sp = (float*)(sm + 2 * STG);

    const int tid  = threadIdx.x;
    const int row0 = blockIdx.x * 128;
    const int col0 = blockIdx.y * 128;
    const int kz   = blockIdx.z * Kblk;
    const int nch  = Kblk >> 5;

    const int arow = tid >> 1, ak0 = (tid & 1) * 16;
    const int brow = tid >> 1, bk0 = (tid & 1) * 16;
    const int bkr = tid >> 3, bn0 = (tid & 7) * 16;
    const unsigned dA  = SWZ(arow * 64 + ak0 * 2);
    const unsigned dA2 = SWZ(arow * 64 + ak0 * 2 + 16);
    const unsigned dB  = BT ? SWZ(brow * 64 + bk0 * 2)      : SWZ(bkr * BSTRIDE0 + bn0 * 2);
    const unsigned dB2 = BT ? SWZ(brow * 64 + bk0 * 2 + 16) : SWZ(bkr * BSTRIDE0 + bn0 * 2 + 16);
    const __nv_bfloat16* ApH = Ah + (size_t)(row0 + arow) * lda + kz + ak0;
    const __nv_bfloat16* ApL = Al + (size_t)(row0 + arow) * lda + kz + ak0;
    const __nv_bfloat16* BpH = BT ? Bh + (size_t)(col0 + brow) * ldb + kz + bk0
                                  : Bh + (size_t)(kz + bkr) * ldb + col0 + bn0;
    const __nv_bfloat16* BpL = BT ? Bl + (size_t)(col0 + brow) * ldb + kz + bk0
                                  : Bl + (size_t)(kz + bkr) * ldb + col0 + bn0;

    auto issue = [&](int c) {
        const int kc = c * 32;
        const uint32_t st = sb + (c & 1) * STG;
        cpasync16(st + dA, ApH + kc);            cpasync16(st + dA2, ApH + kc + 8);
        cpasync16(st + 8192 + dA, ApL + kc);     cpasync16(st + 8192 + dA2, ApL + kc + 8);
        const size_t boff = BT ? (size_t)kc : (size_t)kc * ldb;
        cpasync16(st + 16384 + dB, BpH + boff);        cpasync16(st + 16384 + dB2, BpH + boff + 8);
        cpasync16(st + 16384 + BSZ + dB, BpL + boff);  cpasync16(st + 16384 + BSZ + dB2, BpL + boff + 8);
        cpcommit();
    };

    const int lane = tid & 31, w = tid >> 5;
    const int mw = w >> 2, nw = w & 3;
    const int g = lane >> 2, tig = lane & 3;
    const int lrow = (lane & 7) + ((lane >> 3) & 1) * 8;
    const int lkh  = (lane >> 4) * 16;
    const int trow = (lane & 7) + ((lane >> 4) & 1) * 8;
    const int tnh  = ((lane >> 3) & 1) * 16;

    float acc[4][4][4];
#pragma unroll
    for (int mi = 0; mi < 4; mi++)
#pragma unroll
        for (int ni = 0; ni < 4; ni++)
#pragma unroll
            for (int e = 0; e < 4; e++) acc[mi][ni][e] = 0.f;

    auto compute = [&](int c) {
        const uint32_t st = sb + (c & 1) * STG;
#pragma unroll
        for (int ks = 0; ks < 2; ks++) {
            unsigned ah[4][4], al[4][4];
#pragma unroll
            for (int mi = 0; mi < 4; mi++) {
                const int r = mw * 64 + mi * 16 + lrow;
                const unsigned off = SWZ(r * 64 + ks * 32 + lkh);
                LDSM4(ah[mi], st + off);
                LDSM4(al[mi], st + 8192 + off);
            }
#pragma unroll
            for (int nb = 0; nb < 2; nb++) {
                unsigned bh[4], bl[4];
                if (BT) {
                    const int n = nw * 32 + nb * 16 + lrow;
                    const unsigned off = SWZ(n * 64 + ks * 32 + lkh);
                    LDSM4(bh, st + 16384 + off);
                    LDSM4(bl, st + 16384 + BSZ + off);
                } else {
                    const int kr = ks * 16 + trow;
                    const unsigned off = SWZ(kr * BSTRIDE0 + (nw * 32 + nb * 16) * 2 + tnh);
                    LDSM4T(bh, st + 16384 + off);
                    LDSM4T(bl, st + 16384 + BSZ + off);
                }
                unsigned beh[2] = {bh[0], bh[2]}, boh[2] = {bh[1], bh[3]};
                unsigned bel[2] = {bl[0], bl[2]}, bol[2] = {bl[1], bl[3]};
#pragma unroll
                for (int mi = 0; mi < 4; mi++) {
                    mma16816(acc[mi][2 * nb],     ah[mi], beh);
                    mma16816(acc[mi][2 * nb],     ah[mi], bel);
                    mma16816(acc[mi][2 * nb],     al[mi], beh);
                    mma16816(acc[mi][2 * nb + 1], ah[mi], boh);
                    mma16816(acc[mi][2 * nb + 1], ah[mi], bol);
                    mma16816(acc[mi][2 * nb + 1], al[mi], boh);
                }
            }
        }
    };

    issue(0);
    for (int c = 0; c < nch; c++) {
        if (c + 1 < nch) { issue(c + 1); cpwait1(); } else { cpwait0(); }
        __syncthreads();
        compute(c);
        __syncthreads();
    }

    float* outp = outf + (size_t)blockIdx.z * zstride;
    float srow0[4] = {0.f, 0.f, 0.f, 0.f}, srow1[4] = {0.f, 0.f, 0.f, 0.f};
#pragma unroll
    for (int mi = 0; mi < 4; mi++) {
        const int r = row0 + mw * 64 + mi * 16 + g;
#pragma unroll
        for (int ni = 0; ni < 4; ni++) {
            const int colG = col0 + nw * 32 + ni * 8 + 2 * tig;
            float v0 = acc[mi][ni][0], v1 = acc[mi][ni][1];
            float v2 = acc[mi][ni][2], v3 = acc[mi][ni][3];
            if (EPI & EPI_BIAS) {
                float2 bb = *(const float2*)(bias + colG);
                v0 += bb.x; v1 += bb.y; v2 += bb.x; v3 += bb.y;
            }
            if (EPI & EPI_GELU) {
                v0 = geluf(v0); v1 = geluf(v1); v2 = geluf(v2); v3 = geluf(v3);
            }
            if (EPI & EPI_RESIDP) {
                unsigned uh0 = *(const unsigned*)(resH + (size_t)r * 256 + colG);
                unsigned ul0 = *(const unsigned*)(resL + (size_t)r * 256 + colG);
                unsigned uh1 = *(const unsigned*)(resH + (size_t)(r + 8) * 256 + colG);
                unsigned ul1 = *(const unsigned*)(resL + (size_t)(r + 8) * 256 + colG);
                v0 += upk_lo(uh0) + upk_lo(ul0); v1 += upk_hi(uh0) + upk_hi(ul0);
                v2 += upk_lo(uh1) + upk_lo(ul1); v3 += upk_hi(uh1) + upk_hi(ul1);
            }
            if (EPI & EPI_CSCALE) {
                float2 cs = *(const float2*)(cscale + colG);
                v0 *= cs.x; v1 *= cs.y; v2 *= cs.x; v3 *= cs.y;
            }
            if (EPI & EPI_OUTF32) {
                *(float2*)(outp + (size_t)r * ldout + colG)       = make_float2(v0, v1);
                *(float2*)(outp + (size_t)(r + 8) * ldout + colG) = make_float2(v2, v3);
            }
            if (EPI & EPI_SSQ) {
                srow0[mi] += v0 * v0 + v1 * v1;
                srow1[mi] += v2 * v2 + v3 * v3;
            }
            float p0 = v0, p1 = v1, p2 = v2, p3 = v3;
            if (EPI & EPI_EXPPAIR) {
                p0 = expf(v0); p1 = expf(v1); p2 = expf(v2); p3 = expf(v3);
                if (EPI & EPI_SPART) { srow0[mi] += p0 + p1; srow1[mi] += p2 + p3; }
            }
            if (EPI & (EPI_OUTPAIR | EPI_EXPPAIR)) {
                __nv_bfloat16 h0, l0, h1, l1;
                split2(p0, h0, l0); split2(p1, h1, l1);
                *(unsigned*)(oh + (size_t)r * opitch + colG) = pack2(h0, h1);
                *(unsigned*)(ol + (size_t)r * opitch + colG) = pack2(l0, l1);
                split2(p2, h0, l0); split2(p3, h1, l1);
                *(unsigned*)(oh + (size_t)(r + 8) * opitch + colG) = pack2(h0, h1);
                *(unsigned*)(ol + (size_t)(r + 8) * opitch + colG) = pack2(l0, l1);
            }
        }
    }
    if (EPI & (EPI_SPART | EPI_SSQ)) {
        float (*spp)[128] = (float(*)[128])sp;
#pragma unroll
        for (int mi = 0; mi < 4; mi++) {
            float s0 = srow0[mi], s1 = srow1[mi];
            s0 += __shfl_xor_sync(0xffffffffu, s0, 1);
            s0 += __shfl_xor_sync(0xffffffffu, s0, 2);
            s1 += __shfl_xor_sync(0xffffffffu, s1, 1);
            s1 += __shfl_xor_sync(0xffffffffu, s1, 2);
            if (tig == 0) {
                spp[nw][mw * 64 + mi * 16 + g]     = s0;
                spp[nw][mw * 64 + mi * 16 + g + 8] = s1;
            }
        }
        __syncthreads();
        if (tid < 128)
            spart[(size_t)blockIdx.y * spitch + row0 + tid] =
                spp[0][tid] + spp[1][tid] + spp[2][tid] + spp[3][tid];
    }
}

// ---------------------------------------------------------------------------
// Legacy fp32-input GEMM (query/score path only). LN on A input only.
// ---------------------------------------------------------------------------
enum { AOP_ID = 0, AOP_LN = 1 };
#define LEPI_BIAS  1
#define LEPI_GELU  2
#define LEPI_RESID 4

template <int AOP, int EPI>
__global__ __launch_bounds__(256)
void tlegacy(const float* __restrict__ A, int lda,
             const float* __restrict__ B, int ldb,
             const float* __restrict__ bias,
             float* __restrict__ out, size_t ldout, int Kblk,
             const float* __restrict__ mean, const float* __restrict__ rstd,
             const float* __restrict__ lng, const float* __restrict__ lnb,
             const float* __restrict__ resid)
{
    __shared__ __align__(1024) unsigned char sm[16384 + 2 * 9216];
    const uint32_t sb = smem_u32(sm);
    const int tid = threadIdx.x;
    const int row0 = blockIdx.x * 128;
    const int col0 = blockIdx.y * 128;
    const int nch = Kblk >> 5;

    __shared__ float sgam[256], sbet[256];
    if (AOP == AOP_LN) {
        if (tid < Kblk) { sgam[tid] = lng[tid]; sbet[tid] = lnb[tid]; }
    }

    const int arow = tid >> 1, ak0 = (tid & 1) * 16;
    float mr = 0.f, rr = 0.f;
    if (AOP == AOP_LN) { mr = mean[row0 + arow]; rr = rstd[row0 + arow]; }
    const float* Ap = A + (size_t)(row0 + arow) * lda;
    const int bkr = tid >> 3, bn0 = (tid & 7) * 16;
    const float* Bp0 = B + (size_t)bkr * ldb + col0 + bn0;

    const int lane = tid & 31, w = tid >> 5;
    const int mw = w >> 2, nw = w & 3;
    const int g = lane >> 2, tig = lane & 3;
    const int lrow = (lane & 7) + ((lane >> 3) & 1) * 8;
    const int lkh = (lane >> 4) * 16;
    const int trow = (lane & 7) + ((lane >> 4) & 1) * 8;
    const int tnh = ((lane >> 3) & 1) * 16;

    float acc[4][4][4];
#pragma unroll
    for (int mi = 0; mi < 4; mi++)
#pragma unroll
        for (int ni = 0; ni < 4; ni++)
#pragma unroll
            for (int e = 0; e < 4; e++) acc[mi][ni][e] = 0.f;

    for (int c = 0; c < nch; c++) {
        const int kc = c * 32;
        __syncthreads();
#pragma unroll
        for (int i = 0; i < 4; i++) {
            float4 t = *(const float4*)(Ap + kc + ak0 + i * 4);
            float v[4] = {t.x, t.y, t.z, t.w};
            if (AOP == AOP_LN) {
#pragma unroll
                for (int j = 0; j < 4; j++) {
                    const int kg = kc + ak0 + i * 4 + j;
                    v[j] = (v[j] - mr) * rr * sgam[kg] + sbet[kg];
                }
            }
            const unsigned base = arow * 64 + (ak0 + i * 4) * 2;
            __nv_bfloat16 h0, l0, h1, l1;
            split2(v[0], h0, l0); split2(v[1], h1, l1);
            *(unsigned*)(sm + SWZ(base)) = pack2(h0, h1);
            *(unsigned*)(sm + 8192 + SWZ(base)) = pack2(l0, l1);
            split2(v[2], h0, l0); split2(v[3], h1, l1);
            *(unsigned*)(sm + SWZ(base + 4)) = pack2(h0, h1);
            *(unsigned*)(sm + 8192 + SWZ(base + 4)) = pack2(l0, l1);
        }
#pragma unroll
        for (int i = 0; i < 4; i++) {
            float4 t = *(const float4*)(Bp0 + (size_t)kc * ldb + i * 4);
            float v[4] = {t.x, t.y, t.z, t.w};
            const unsigned base = bkr * BSTRIDE0 + (bn0 + i * 4) * 2;
            __nv_bfloat16 h0, l0, h1, l1;
            split2(v[0], h0, l0); split2(v[1], h1, l1);
            *(unsigned*)(sm + 16384 + SWZ(base)) = pack2(h0, h1);
            *(unsigned*)(sm + 16384 + 9216 + SWZ(base)) = pack2(l0, l1);
            split2(v[2], h0, l0); split2(v[3], h1, l1);
            *(unsigned*)(sm + 16384 + SWZ(base + 4)) = pack2(h0, h1);
            *(unsigned*)(sm + 16384 + 9216 + SWZ(base + 4)) = pack2(l0, l1);
        }
        __syncthreads();
#pragma unroll
        for (int ks = 0; ks < 2; ks++) {
            unsigned ah[4][4], al[4][4];
#pragma unroll
            for (int mi = 0; mi < 4; mi++) {
                const int r = mw * 64 + mi * 16 + lrow;
                const unsigned off = SWZ(r * 64 + ks * 32 + lkh);
                LDSM4(ah[mi], sb + off);
                LDSM4(al[mi], sb + 8192 + off);
            }
#pragma unroll
            for (int nb = 0; nb < 2; nb++) {
                unsigned bh[4], bl[4];
                const int kr = ks * 16 + trow;
                const unsigned off = SWZ(kr * BSTRIDE0 + (nw * 32 + nb * 16) * 2 + tnh);
                LDSM4T(bh, sb + 16384 + off);
                LDSM4T(bl, sb + 16384 + 9216 + off);
                unsigned beh[2] = {bh[0], bh[2]}, boh[2] = {bh[1], bh[3]};
                unsigned bel[2] = {bl[0], bl[2]}, bol[2] = {bl[1], bl[3]};
#pragma unroll
                for (int mi = 0; mi < 4; mi++) {
                    mma16816(acc[mi][2 * nb],     ah[mi], beh);
                    mma16816(acc[mi][2 * nb],     ah[mi], bel);
                    mma16816(acc[mi][2 * nb],     al[mi], beh);
                    mma16816(acc[mi][2 * nb + 1], ah[mi], boh);
                    mma16816(acc[mi][2 * nb + 1], ah[mi], bol);
                    mma16816(acc[mi][2 * nb + 1], al[mi], boh);
                }
            }
        }
    }

#pragma unroll
    for (int mi = 0; mi < 4; mi++) {
        const int r = row0 + mw * 64 + mi * 16 + g;
#pragma unroll
        for (int ni = 0; ni < 4; ni++) {
            const int colG = col0 + nw * 32 + ni * 8 + 2 * tig;
            float v0 = acc[mi][ni][0], v1 = acc[mi][ni][1];
            float v2 = acc[mi][ni][2], v3 = acc[mi][ni][3];
            if (EPI & LEPI_BIAS) {
                float2 bb = *(const float2*)(bias + colG);
                v0 += bb.x; v1 += bb.y; v2 += bb.x; v3 += bb.y;
            }
            if (EPI & LEPI_GELU) {
                v0 = geluf(v0); v1 = geluf(v1); v2 = geluf(v2); v3 = geluf(v3);
            }
            if (EPI & LEPI_RESID) {
                float2 ra = *(const float2*)(resid + (size_t)r * 256 + colG);
                float2 rb = *(const float2*)(resid + (size_t)(r + 8) * 256 + colG);
                v0 += ra.x; v1 += ra.y; v2 += rb.x; v3 += rb.y;
            }
            *(float2*)(out + (size_t)r * ldout + colG)       = make_float2(v0, v1);
            *(float2*)(out + (size_t)(r + 8) * ldout + colG) = make_float2(v2, v3);
        }
    }
}

// ---------------- prep kernels ----------------------------------------------
__global__ void prep_pf(const float* __restrict__ pf,
                        __nv_bfloat16* __restrict__ H, __nv_bfloat16* __restrict__ L, int N)
{
    int idx = blockIdx.x * 256 + threadIdx.x;
    int row = idx / 12, c8 = (idx % 12) * 8;
    if (row >= N) return;
    __nv_bfloat16 h[8], l[8];
#pragma unroll
    for (int j = 0; j < 8; j++) {
        int k = c8 + j;
        float v = (k < 72) ? pf[(size_t)row * 72 + k] : 0.f;
        split2(v, h[j], l[j]);
    }
    *(uint4*)(H + (size_t)row * 96 + c8) = *(uint4*)h;
    *(uint4*)(L + (size_t)row * 96 + c8) = *(uint4*)l;
}

// weight W[k][n] fp32 (k=realk rows, n=256) -> TRANSPOSED pair image [n=256][kpad]
__global__ void prep_wT(const float* __restrict__ W,
                        __nv_bfloat16* __restrict__ H, __nv_bfloat16* __restrict__ L,
                        int kpad, int realk)
{
    int idx = blockIdx.x * 256 + threadIdx.x;   // 256 * (kpad/8) threads
    int n = idx / (kpad / 8), c8 = (idx % (kpad / 8)) * 8;
    if (n >= 256) return;
    __nv_bfloat16 h[8], l[8];
#pragma unroll
    for (int j = 0; j < 8; j++) {
        int k = c8 + j;
        float v = (k < realk) ? W[(size_t)k * 256 + n] : 0.f;
        split2(v, h[j], l[j]);
    }
    *(uint4*)(H + (size_t)n * kpad + c8) = *(uint4*)h;
    *(uint4*)(L + (size_t)n * kpad + c8) = *(uint4*)l;
}

// ---------------- misc small kernels ----------------------------------------
__global__ __launch_bounds__(256)
void ln_stats(const float* __restrict__ X, float* __restrict__ mean,
              float* __restrict__ rstd, int M)
{
    int warp = (blockIdx.x * blockDim.x + threadIdx.x) >> 5;
    if (warp >= M) return;
    int lane = threadIdx.x & 31;
    const float* row = X + (size_t)warp * 256;
    float s = 0.f, ss = 0.f;
#pragma unroll
    for (int j = 0; j < 8; j++) { float v = row[lane + 32 * j]; s += v; ss += v * v; }
#pragma unroll
    for (int o = 16; o; o >>= 1) {
        s  += __shfl_xor_sync(0xffffffffu, s, o);
        ss += __shfl_xor_sync(0xffffffffu, ss, o);
    }
    if (lane == 0) {
        float m = s * (1.0f / 256.0f);
        mean[warp] = m;
        rstd[warp] = rsqrtf(ss * (1.0f / 256.0f) - m * m + 1e-5f);
    }
}

__global__ __launch_bounds__(256)
void rownorm(const float* __restrict__ X, float* __restrict__ inv, int M)
{
    int warp = (blockIdx.x * blockDim.x + threadIdx.x) >> 5;
    if (warp >= M) return;
    int lane = threadIdx.x & 31;
    const float* row = X + (size_t)warp * 256;
    float ss = 0.f;
#pragma unroll
    for (int j = 0; j < 8; j++) { float v = row[lane + 32 * j]; ss += v * v; }
#pragma unroll
    for (int o = 16; o; o >>= 1) ss += __shfl_xor_sync(0xffffffffu, ss, o);
    if (lane == 0) inv[warp] = 1.0f / fmaxf(sqrtf(ss), 1e-12f);
}

__global__ void qmpair(const float* __restrict__ qe, const float* __restrict__ invq,
                       const float* __restrict__ lsc,
                       __nv_bfloat16* __restrict__ H, __nv_bfloat16* __restrict__ L)
{
    int idx = blockIdx.x * 256 + threadIdx.x;
    int r = idx >> 8;
    float v = qe[idx] * invq[r] * expf(lsc[0]);
    __nv_bfloat16 h, l;
    split2(v, h, l);
    H[idx] = h; L[idx] = l;
}

__global__ __launch_bounds__(256)
void reduce_refined(const float* __restrict__ Ppart, const float* __restrict__ spart,
                    const float* __restrict__ qe, float* __restrict__ refined,
                    int CH, int NB)
{
    const int q = blockIdx.x;
    const int d = threadIdx.x;
    __shared__ float sh[256];
    float s = 0.f;
    for (int i = d; i < NB; i += 256) s += spart[(size_t)i * 128 + q];
    sh[d] = s;
    __syncthreads();
    for (int o = 128; o; o >>= 1) {
        if (d < o) sh[d] += sh[d + o];
        __syncthreads();
    }
    const float stot = sh[0];
    float p = 0.f;
    for (int c = 0; c < CH; c++) p += Ppart[((size_t)c * 128 + q) * 256 + d];
    refined[(size_t)q * 256 + d] = qe[(size_t)q * 256 + d] + p / stot;
}

__global__ __launch_bounds__(256)
void score_kernel(const float* __restrict__ A2s, const float* __restrict__ w2,
                  const float* __restrict__ b2, float* __restrict__ out)
{
    const int q = blockIdx.x;
    const int d = threadIdx.x;
    __shared__ float sh[256];
    sh[d] = A2s[(size_t)q * 256 + d] * w2[d];
    __syncthreads();
    for (int o = 128; o; o >>= 1) {
        if (d < o) sh[d] += sh[d + o];
        __syncthreads();
    }
    if (d == 0) out[q] = sh[0] + b2[0];
}

// ---------------------------------------------------------------------------
extern "C" void kernel_launch(void* const* d_in, const int* in_sizes, int n_in,
                              void* d_out, int out_size)
{
    const float* point_feat = (const float*)d_in[0];
    const float* ip_w1 = (const float*)d_in[1];
    const float* ip_b1 = (const float*)d_in[2];
    const float* ip_ln_g = (const float*)d_in[3];
    const float* ip_ln_b = (const float*)d_in[4];
    const float* ip_w2 = (const float*)d_in[5];
    const float* ip_b2 = (const float*)d_in[6];
    const float* ph_ln_g = (const float*)d_in[7];
    const float* ph_ln_b = (const float*)d_in[8];
    const float* ph_w1 = (const float*)d_in[9];
    const float* ph_b1 = (const float*)d_in[10];
    const float* ph_w2 = (const float*)d_in[11];
    const float* ph_b2 = (const float*)d_in[12];
    const float* q_embed = (const float*)d_in[13];
    const float* qh_ln_g = (const float*)d_in[14];
    const float* qh_ln_b = (const float*)d_in[15];
    const float* qh_w1 = (const float*)d_in[16];
    const float* qh_b1 = (const float*)d_in[17];
    const float* qh_w2 = (const float*)d_in[18];
    const float* qh_b2 = (const float*)d_in[19];
    const float* sh_ln_g = (const float*)d_in[20];
    const float* sh_ln_b = (const float*)d_in[21];
    const float* sh_w1 = (const float*)d_in[22];
    const float* sh_b1 = (const float*)d_in[23];
    const float* sh_w2 = (const float*)d_in[24];
    const float* sh_b2 = (const float*)d_in[25];
    const float* logit_scale = (const float*)d_in[26];

    const int N = in_sizes[0] / 72;

    float* out = (float*)d_out;
    const size_t offScore = (size_t)128 * N;
    const size_t offPE = offScore + 128;
    const size_t offRef = offPE + (size_t)N * 256;
    float* mask = out;
    float* score = out + offScore;
    float* pe = out + offPE;
    float* refined = out + offRef;

    __nv_bfloat16 *pfH, *pfL, *xH, *xL, *aH, *aL, *hH, *hL, *peH, *peL, *emH, *emL;
    __nv_bfloat16 *w1H, *w1L, *w2H, *w2L, *w3H, *w3L, *w4H, *w4L, *qmH, *qmL;
    float *invpe, *meanQ, *rstdQ, *A2q, *qe, *invq, *spart, *Ppart;
    cudaGetSymbolAddress((void**)&pfH, g_pfH); cudaGetSymbolAddress((void**)&pfL, g_pfL);
    cudaGetSymbolAddress((void**)&xH, g_xH);   cudaGetSymbolAddress((void**)&xL, g_xL);
    cudaGetSymbolAddress((void**)&aH, g_aH);   cudaGetSymbolAddress((void**)&aL, g_aL);
    cudaGetSymbolAddress((void**)&hH, g_hH);   cudaGetSymbolAddress((void**)&hL, g_hL);
    cudaGetSymbolAddress((void**)&peH, g_peH); cudaGetSymbolAddress((void**)&peL, g_peL);
    cudaGetSymbolAddress((void**)&emH, g_emH); cudaGetSymbolAddress((void**)&emL, g_emL);
    cudaGetSymbolAddress((void**)&w1H, g_w1H); cudaGetSymbolAddress((void**)&w1L, g_w1L);
    cudaGetSymbolAddress((void**)&w2H, g_w2H); cudaGetSymbolAddress((void**)&w2L, g_w2L);
    cudaGetSymbolAddress((void**)&w3H, g_w3H); cudaGetSymbolAddress((void**)&w3L, g_w3L);
    cudaGetSymbolAddress((void**)&w4H, g_w4H); cudaGetSymbolAddress((void**)&w4L, g_w4L);
    cudaGetSymbolAddress((void**)&qmH, g_qmH); cudaGetSymbolAddress((void**)&qmL, g_qmL);
    cudaGetSymbolAddress((void**)&invpe, g_invpe);
    cudaGetSymbolAddress((void**)&meanQ, g_meanQ); cudaGetSymbolAddress((void**)&rstdQ, g_rstdQ);
    cudaGetSymbolAddress((void**)&A2q, g_A2q); cudaGetSymbolAddress((void**)&qe, g_qe);
    cudaGetSymbolAddress((void**)&invq, g_invq);
    cudaGetSymbolAddress((void**)&spart, g_spart); cudaGetSymbolAddress((void**)&Ppart, g_Ppart);

    // dynamic smem opt-in
    const int SMEM_BT0 = 2 * (16384 + 2 * 9216) + 2048;
    const int SMEM_BT1 = 2 * (16384 + 2 * 8192) + 2048;
    cudaFuncSetAttribute(tpair256<EPI_BIAS | EPI_LNPAIR | EPI_LNGELU>,
                         cudaFuncAttributeMaxDynamicSharedMemorySize, SMEM256);
    cudaFuncSetAttribute(tpair256<EPI_BIAS | EPI_OUTPAIR | EPI_LNPAIR>,
                         cudaFuncAttributeMaxDynamicSharedMemorySize, SMEM256);
    cudaFuncSetAttribute(tpair256<EPI_BIAS | EPI_GELU | EPI_OUTPAIR>,
                         cudaFuncAttributeMaxDynamicSharedMemorySize, SMEM256);
    cudaFuncSetAttribute(tpair256<EPI_BIAS | EPI_RESIDP | EPI_OUTF32 | EPI_OUTPAIR | EPI_SSQ>,
                         cudaFuncAttributeMaxDynamicSharedMemorySize, SMEM256);
    cudaFuncSetAttribute(tpair<EPI_CSCALE | EPI_OUTF32 | EPI_EXPPAIR | EPI_SPART, 1>,
                         cudaFuncAttributeMaxDynamicSharedMemorySize, SMEM_BT1);
    cudaFuncSetAttribute(tpair<EPI_OUTF32, 0>,
                         cudaFuncAttributeMaxDynamicSharedMemorySize, SMEM_BT0);

    // -------- preps --------
    prep_pf<<<(N * 12 + 255) / 256, 256>>>(point_feat, pfH, pfL, N);
    prep_wT<<<12, 256>>>(ip_w1, w1H, w1L, 96, 72);
    prep_wT<<<32, 256>>>(ip_w2, w2H, w2L, 256, 256);
    prep_wT<<<32, 256>>>(ph_w1, w3H, w3L, 256, 256);
    prep_wT<<<32, 256>>>(ph_w2, w4H, w4L, 256, 256);

    const dim3 gP(N / 128);

    // -------- point pipeline (128x256 tiles, LN fused) --------
    // a = gelu(LN(pf @ ip_w1 + ip_b1))   (pairs; x intermediate eliminated)
    tpair256<EPI_BIAS | EPI_LNPAIR | EPI_LNGELU><<<gP, 512, SMEM256>>>(
        pfH, pfL, 96, w1H, w1L, 96, ip_b1,
        nullptr, 0, nullptr, nullptr, aH, aL,
        nullptr, nullptr, ip_ln_g, ip_ln_b, nullptr, 96);
    // h = a @ ip_w2 + ip_b2 (pairs) ; a = LN(h) (pairs, in-place safe per-block)
    tpair256<EPI_BIAS | EPI_OUTPAIR | EPI_LNPAIR><<<gP, 512, SMEM256>>>(
        aH, aL, 256, w2H, w2L, 256, ip_b2,
        nullptr, 0, hH, hL, aH, aL,
        nullptr, nullptr, ph_ln_g, ph_ln_b, nullptr, 256);
    // x = gelu(a @ ph_w1 + ph_b1) (pairs)
    tpair256<EPI_BIAS | EPI_GELU | EPI_OUTPAIR><<<gP, 512, SMEM256>>>(
        aH, aL, 256, w3H, w3L, 256, ph_b1,
        nullptr, 0, xH, xL, nullptr, nullptr,
        nullptr, nullptr, nullptr, nullptr, nullptr, 256);
    // pe = h + x @ ph_w2 + ph_b2 (fp32 + pairs + fused invpe)
    tpair256<EPI_BIAS | EPI_RESIDP | EPI_OUTF32 | EPI_OUTPAIR | EPI_SSQ><<<gP, 512, SMEM256>>>(
        xH, xL, 256, w4H, w4L, 256, ph_b2,
        pe, 256, peH, peL, nullptr, nullptr,
        hH, hL, nullptr, nullptr, invpe, 256);

    // -------- query pipeline (legacy, tiny) --------
    ln_stats<<<16, 256>>>(q_embed, meanQ, rstdQ, 128);
    tlegacy<AOP_LN, LEPI_BIAS | LEPI_GELU><<<dim3(1, 2), 256>>>(
        q_embed, 256, qh_w1, 256, qh_b1, A2q, 256, 256,
        meanQ, rstdQ, qh_ln_g, qh_ln_b, nullptr);
    tlegacy<AOP_ID, LEPI_BIAS | LEPI_RESID><<<dim3(1, 2), 256>>>(
        A2q, 256, qh_w2, 256, qh_b2, qe, 256, 256,
        nullptr, nullptr, nullptr, nullptr, q_embed);
    rownorm<<<16, 256>>>(qe, invq, 128);
    qmpair<<<128, 256>>>(qe, invq, logit_scale, qmH, qmL);

    // -------- mask logits + exp pairs + softmax partial sums --------
    tpair<EPI_CSCALE | EPI_OUTF32 | EPI_EXPPAIR | EPI_SPART, 1><<<dim3(1, N / 128), 256, SMEM_BT1>>>(
        qmH, qmL, 256, peH, peL, 256, nullptr,
        mask, (size_t)N, 0, emH, emL, (size_t)N, nullptr, nullptr, invpe, spart, 128, 256);

    // -------- weighted aggregation: Ppart[z] = em chunk @ pe chunk ----------
    tpair<EPI_OUTF32, 0><<<dim3(1, 2, 256), 256, SMEM_BT0>>>(
        emH, emL, N, peH, peL, 256, nullptr,
        Ppart, 256, (size_t)128 * 256, nullptr, nullptr, 0,
        nullptr, nullptr, nullptr, nullptr, 0, 1024);
    reduce_refined<<<128, 256>>>(Ppart, spart, qe, refined, 256, N / 128);

    // -------- score head (legacy) --------
    ln_stats<<<16, 256>>>(refined, meanQ, rstdQ, 128);
    tlegacy<AOP_LN, LEPI_BIAS | LEPI_GELU><<<dim3(1, 2), 256>>>(
        refined, 256, sh_w1, 256, sh_b1, A2q, 256, 256,
        meanQ, rstdQ, sh_ln_g, sh_ln_b, nullptr);
    score_kernel<<<128, 256>>>(A2q, sh_w2, sh_b2, score);
}

// round 12
// speedup vs baseline: 1.0249x; 1.0249x over previous
#include <cuda_runtime.h>
#include <cuda_bf16.h>
#include <math.h>
#include <stdint.h>

// ---------------------------------------------------------------------------
// QueryInstanceDecoder: bf16 split-precision mma.sync pipeline, v5.
// = R9 (best passing: pair images in DRAM, 128x128 tiles, 2 CTAs/SM, fused
//   SSQ) with the mainloop upgraded from 2-stage/2-sync to 3-stage/1-sync
//   cp.async pipelining (latency-bound fix; R10 showed GEMMs are not DRAM-bound).
// N=262144, C_IN=72, D=256, Q=128.
// d_out (floats): mask_logits[128*N] | score[128] | point_embed[N*256] | refined[128*256]
// ---------------------------------------------------------------------------

#define DEVI __device__ __forceinline__

DEVI float geluf(float x) { return 0.5f * x * (1.0f + erff(x * 0.70710678118654752f)); }

DEVI unsigned pack2(__nv_bfloat16 a, __nv_bfloat16 b) {
    return (unsigned)__bfloat16_as_ushort(a) | ((unsigned)__bfloat16_as_ushort(b) << 16);
}
DEVI void split2(float x, __nv_bfloat16& h, __nv_bfloat16& l) {
    h = __float2bfloat16(x);
    l = __float2bfloat16(x - __bfloat162float(h));
}
DEVI float upk_lo(unsigned u) { return __bfloat162float(__ushort_as_bfloat16((unsigned short)(u & 0xffff))); }
DEVI float upk_hi(unsigned u) { return __bfloat162float(__ushort_as_bfloat16((unsigned short)(u >> 16))); }

DEVI void mma16816(float* c, const unsigned* a, const unsigned* b) {
    asm volatile(
        "mma.sync.aligned.m16n8k16.row.col.f32.bf16.bf16.f32 "
        "{%0,%1,%2,%3},{%4,%5,%6,%7},{%8,%9},{%0,%1,%2,%3};"
        : "+f"(c[0]), "+f"(c[1]), "+f"(c[2]), "+f"(c[3])
        : "r"(a[0]), "r"(a[1]), "r"(a[2]), "r"(a[3]), "r"(b[0]), "r"(b[1]));
}
DEVI uint32_t smem_u32(const void* p) {
    uint32_t a;
    asm("{ .reg .u64 t; cvta.to.shared.u64 t, %1; cvt.u32.u64 %0, t; }" : "=r"(a) : "l"(p));
    return a;
}
#define LDSM4(r, a) \
    asm volatile("ldmatrix.sync.aligned.m8n8.x4.shared.b16 {%0,%1,%2,%3},[%4];" \
        : "=r"((r)[0]), "=r"((r)[1]), "=r"((r)[2]), "=r"((r)[3]) : "r"(a))
#define LDSM4T(r, a) \
    asm volatile("ldmatrix.sync.aligned.m8n8.x4.trans.shared.b16 {%0,%1,%2,%3},[%4];" \
        : "=r"((r)[0]), "=r"((r)[1]), "=r"((r)[2]), "=r"((r)[3]) : "r"(a))

DEVI void cpasync16(uint32_t dst, const void* src) {
    asm volatile("cp.async.cg.shared.global [%0], [%1], 16;" :: "r"(dst), "l"(src));
}
DEVI void cpcommit() { asm volatile("cp.async.commit_group;"); }
DEVI void cpwait1()  { asm volatile("cp.async.wait_group 1;"); }
DEVI void cpwait0()  { asm volatile("cp.async.wait_group 0;"); }

#define SWZ(o) ((unsigned)(o) ^ ((((unsigned)(o)) >> 3) & 0x70))
#define BSTRIDE0 288

// ---------------- scratch (static device memory; no allocations) -----------
#define NMAX 262144
__device__ __nv_bfloat16 g_pfH[(size_t)NMAX * 96], g_pfL[(size_t)NMAX * 96];
__device__ __nv_bfloat16 g_xH[(size_t)NMAX * 256], g_xL[(size_t)NMAX * 256];
__device__ __nv_bfloat16 g_aH[(size_t)NMAX * 256], g_aL[(size_t)NMAX * 256];
__device__ __nv_bfloat16 g_hH[(size_t)NMAX * 256], g_hL[(size_t)NMAX * 256];
__device__ __nv_bfloat16 g_peH[(size_t)NMAX * 256], g_peL[(size_t)NMAX * 256];
__device__ __nv_bfloat16 g_emH[(size_t)128 * NMAX], g_emL[(size_t)128 * NMAX];
__device__ __nv_bfloat16 g_w1H[96 * 256], g_w1L[96 * 256];
__device__ __nv_bfloat16 g_w2H[256 * 256], g_w2L[256 * 256];
__device__ __nv_bfloat16 g_w3H[256 * 256], g_w3L[256 * 256];
__device__ __nv_bfloat16 g_w4H[256 * 256], g_w4L[256 * 256];
__device__ __nv_bfloat16 g_qmH[128 * 256], g_qmL[128 * 256];
__device__ float g_invpe[NMAX];
__device__ float g_meanQ[128], g_rstdQ[128];
__device__ float g_A2q[128 * 256];
__device__ float g_qe[128 * 256];
__device__ float g_invq[128];
__device__ float g_spart[(size_t)2 * NMAX];
__device__ float g_Ppart[256 * 128 * 256];

// ---------------- epilogue flags --------------------------------------------
#define EPI_BIAS    1
#define EPI_GELU    2
#define EPI_RESIDP  4
#define EPI_OUTF32  8
#define EPI_OUTPAIR 16
#define EPI_SPART   32
#define EPI_CSCALE  64
#define EPI_EXPPAIR 128
#define EPI_SSQ     256

// ---------------------------------------------------------------------------
// Pair-image GEMM: C[128x128] = A_pairs[128xK] @ B_pairs^T, split precision
// (Ah*Bh + Ah*Bl + Al*Bh). cp.async 3-stage pipeline, K-chunk 32, ONE sync
// per chunk. BT=1: B image [n][k]. BT=0: B image [k][n]. 2 CTAs/SM forced.
// ---------------------------------------------------------------------------
template <int EPI, int BT>
__global__ __launch_bounds__(256, 2)
void tpair(const __nv_bfloat16* __restrict__ Ah, const __nv_bfloat16* __restrict__ Al, int lda,
           const __nv_bfloat16* __restrict__ Bh, const __nv_bfloat16* __restrict__ Bl, int ldb,
           const float* __restrict__ bias,
           float* __restrict__ outf, size_t ldout, size_t zstride,
           __nv_bfloat16* __restrict__ oh, __nv_bfloat16* __restrict__ ol, size_t opitch,
           const __nv_bfloat16* __restrict__ resH, const __nv_bfloat16* __restrict__ resL,
           const float* __restrict__ cscale, float* __restrict__ spart, size_t spitch,
           int Kblk)
{
    constexpr int BSZ = BT ? 8192 : 9216;
    constexpr int STG = 16384 + 2 * BSZ;     // AH 8K | AL 8K | BH | BL
    extern __shared__ __align__(1024) unsigned char sm[];
    const uint32_t sb = smem_u32(sm);
    float* sp = (float*)(sm + 3 * STG);      // [4][128]

    const int tid  = threadIdx.x;
    const int row0 = blockIdx.x * 128;
    const int col0 = blockIdx.y * 128;
    const int kz   = blockIdx.z * Kblk;
    const int nch  = Kblk >> 5;

    // loader indices
    const int arow = tid >> 1, ak0 = (tid & 1) * 16;
    const int brow = tid >> 1, bk0 = (tid & 1) * 16;   // BT=1
    const int bkr = tid >> 3, bn0 = (tid & 7) * 16;    // BT=0
    const unsigned dA  = SWZ(arow * 64 + ak0 * 2);
    const unsigned dA2 = SWZ(arow * 64 + ak0 * 2 + 16);
    const unsigned dB  = BT ? SWZ(brow * 64 + bk0 * 2)      : SWZ(bkr * BSTRIDE0 + bn0 * 2);
    const unsigned dB2 = BT ? SWZ(brow * 64 + bk0 * 2 + 16) : SWZ(bkr * BSTRIDE0 + bn0 * 2 + 16);
    const __nv_bfloat16* ApH = Ah + (size_t)(row0 + arow) * lda + kz + ak0;
    const __nv_bfloat16* ApL = Al + (size_t)(row0 + arow) * lda + kz + ak0;
    const __nv_bfloat16* BpH = BT ? Bh + (size_t)(col0 + brow) * ldb + kz + bk0
                                  : Bh + (size_t)(kz + bkr) * ldb + col0 + bn0;
    const __nv_bfloat16* BpL = BT ? Bl + (size_t)(col0 + brow) * ldb + kz + bk0
                                  : Bl + (size_t)(kz + bkr) * ldb + col0 + bn0;

    auto issue = [&](int c) {
        const int kc = c * 32;
        const uint32_t st = sb + (c % 3) * STG;
        cpasync16(st + dA, ApH + kc);            cpasync16(st + dA2, ApH + kc + 8);
        cpasync16(st + 8192 + dA, ApL + kc);     cpasync16(st + 8192 + dA2, ApL + kc + 8);
        const size_t boff = BT ? (size_t)kc : (size_t)kc * ldb;
        cpasync16(st + 16384 + dB, BpH + boff);        cpasync16(st + 16384 + dB2, BpH + boff + 8);
        cpasync16(st + 16384 + BSZ + dB, BpL + boff);  cpasync16(st + 16384 + BSZ + dB2, BpL + boff + 8);
        cpcommit();
    };

    // compute indices
    const int lane = tid & 31, w = tid >> 5;
    const int mw = w >> 2, nw = w & 3;
    const int g = lane >> 2, tig = lane & 3;
    const int lrow = (lane & 7) + ((lane >> 3) & 1) * 8;
    const int lkh  = (lane >> 4) * 16;
    const int trow = (lane & 7) + ((lane >> 4) & 1) * 8;
    const int tnh  = ((lane >> 3) & 1) * 16;

    float acc[4][4][4];
#pragma unroll
    for (int mi = 0; mi < 4; mi++)
#pragma unroll
        for (int ni = 0; ni < 4; ni++)
#pragma unroll
            for (int e = 0; e < 4; e++) acc[mi][ni][e] = 0.f;

    auto compute = [&](int c) {
        const uint32_t st = sb + (c % 3) * STG;
#pragma unroll
        for (int ks = 0; ks < 2; ks++) {
            unsigned ah[4][4], al[4][4];
#pragma unroll
            for (int mi = 0; mi < 4; mi++) {
                const int r = mw * 64 + mi * 16 + lrow;
                const unsigned off = SWZ(r * 64 + ks * 32 + lkh);
                LDSM4(ah[mi], st + off);
                LDSM4(al[mi], st + 8192 + off);
            }
#pragma unroll
            for (int nb = 0; nb < 2; nb++) {
                unsigned bh[4], bl[4];
                if (BT) {
                    const int n = nw * 32 + nb * 16 + lrow;
                    const unsigned off = SWZ(n * 64 + ks * 32 + lkh);
                    LDSM4(bh, st + 16384 + off);
                    LDSM4(bl, st + 16384 + BSZ + off);
                } else {
                    const int kr = ks * 16 + trow;
                    const unsigned off = SWZ(kr * BSTRIDE0 + (nw * 32 + nb * 16) * 2 + tnh);
                    LDSM4T(bh, st + 16384 + off);
                    LDSM4T(bl, st + 16384 + BSZ + off);
                }
                unsigned beh[2] = {bh[0], bh[2]}, boh[2] = {bh[1], bh[3]};
                unsigned bel[2] = {bl[0], bl[2]}, bol[2] = {bl[1], bl[3]};
#pragma unroll
                for (int mi = 0; mi < 4; mi++) {
                    mma16816(acc[mi][2 * nb],     ah[mi], beh);
                    mma16816(acc[mi][2 * nb],     ah[mi], bel);
                    mma16816(acc[mi][2 * nb],     al[mi], beh);
                    mma16816(acc[mi][2 * nb + 1], ah[mi], boh);
                    mma16816(acc[mi][2 * nb + 1], ah[mi], bol);
                    mma16816(acc[mi][2 * nb + 1], al[mi], boh);
                }
            }
        }
    };

    // ---- 3-stage pipelined main loop, ONE sync per chunk ----
    // Invariant at top of iter c: groups c and (c+1 if exists) are issued.
    // issue(c+2) targets stage (c-1)%3, whose compute finished in iter c-1
    // and is fenced by this iteration's __syncthreads().
    issue(0);
    if (nch > 1) issue(1);
    for (int c = 0; c < nch; c++) {
        if (c + 1 < nch) cpwait1(); else cpwait0();
        __syncthreads();
        if (c + 2 < nch) issue(c + 2);
        compute(c);
    }

    // ---- epilogue ----
    float* outp = outf + (size_t)blockIdx.z * zstride;
    float srow0[4] = {0.f, 0.f, 0.f, 0.f}, srow1[4] = {0.f, 0.f, 0.f, 0.f};
#pragma unroll
    for (int mi = 0; mi < 4; mi++) {
        const int r = row0 + mw * 64 + mi * 16 + g;
#pragma unroll
        for (int ni = 0; ni < 4; ni++) {
            const int colG = col0 + nw * 32 + ni * 8 + 2 * tig;
            float v0 = acc[mi][ni][0], v1 = acc[mi][ni][1];
            float v2 = acc[mi][ni][2], v3 = acc[mi][ni][3];
            if (EPI & EPI_BIAS) {
                float2 bb = *(const float2*)(bias + colG);
                v0 += bb.x; v1 += bb.y; v2 += bb.x; v3 += bb.y;
            }
            if (EPI & EPI_GELU) {
                v0 = geluf(v0); v1 = geluf(v1); v2 = geluf(v2); v3 = geluf(v3);
            }
            if (EPI & EPI_RESIDP) {
                unsigned uh0 = *(const unsigned*)(resH + (size_t)r * 256 + colG);
                unsigned ul0 = *(const unsigned*)(resL + (size_t)r * 256 + colG);
                unsigned uh1 = *(const unsigned*)(resH + (size_t)(r + 8) * 256 + colG);
                unsigned ul1 = *(const unsigned*)(resL + (size_t)(r + 8) * 256 + colG);
                v0 += upk_lo(uh0) + upk_lo(ul0); v1 += upk_hi(uh0) + upk_hi(ul0);
                v2 += upk_lo(uh1) + upk_lo(ul1); v3 += upk_hi(uh1) + upk_hi(ul1);
            }
            if (EPI & EPI_CSCALE) {
                float2 cs = *(const float2*)(cscale + colG);
                v0 *= cs.x; v1 *= cs.y; v2 *= cs.x; v3 *= cs.y;
            }
            if (EPI & EPI_OUTF32) {
                *(float2*)(outp + (size_t)r * ldout + colG)       = make_float2(v0, v1);
                *(float2*)(outp + (size_t)(r + 8) * ldout + colG) = make_float2(v2, v3);
            }
            if (EPI & EPI_SSQ) {
                srow0[mi] += v0 * v0 + v1 * v1;
                srow1[mi] += v2 * v2 + v3 * v3;
            }
            float p0 = v0, p1 = v1, p2 = v2, p3 = v3;
            if (EPI & EPI_EXPPAIR) {
                p0 = expf(v0); p1 = expf(v1); p2 = expf(v2); p3 = expf(v3);
                if (EPI & EPI_SPART) { srow0[mi] += p0 + p1; srow1[mi] += p2 + p3; }
            }
            if (EPI & (EPI_OUTPAIR | EPI_EXPPAIR)) {
                __nv_bfloat16 h0, l0, h1, l1;
                split2(p0, h0, l0); split2(p1, h1, l1);
                *(unsigned*)(oh + (size_t)r * opitch + colG) = pack2(h0, h1);
                *(unsigned*)(ol + (size_t)r * opitch + colG) = pack2(l0, l1);
                split2(p2, h0, l0); split2(p3, h1, l1);
                *(unsigned*)(oh + (size_t)(r + 8) * opitch + colG) = pack2(h0, h1);
                *(unsigned*)(ol + (size_t)(r + 8) * opitch + colG) = pack2(l0, l1);
            }
        }
    }
    if (EPI & (EPI_SPART | EPI_SSQ)) {
        float (*spp)[128] = (float(*)[128])sp;
#pragma unroll
        for (int mi = 0; mi < 4; mi++) {
            float s0 = srow0[mi], s1 = srow1[mi];
            s0 += __shfl_xor_sync(0xffffffffu, s0, 1);
            s0 += __shfl_xor_sync(0xffffffffu, s0, 2);
            s1 += __shfl_xor_sync(0xffffffffu, s1, 1);
            s1 += __shfl_xor_sync(0xffffffffu, s1, 2);
            if (tig == 0) {
                spp[nw][mw * 64 + mi * 16 + g]     = s0;
                spp[nw][mw * 64 + mi * 16 + g + 8] = s1;
            }
        }
        __syncthreads();
        if (tid < 128)
            spart[(size_t)blockIdx.y * spitch + row0 + tid] =
                spp[0][tid] + spp[1][tid] + spp[2][tid] + spp[3][tid];
    }
}

// ---------------------------------------------------------------------------
// Legacy fp32-input GEMM (query/score path only). LN on A input only.
// ---------------------------------------------------------------------------
enum { AOP_ID = 0, AOP_LN = 1 };
#define LEPI_BIAS  1
#define LEPI_GELU  2
#define LEPI_RESID 4

template <int AOP, int EPI>
__global__ __launch_bounds__(256)
void tlegacy(const float* __restrict__ A, int lda,
             const float* __restrict__ B, int ldb,
             const float* __restrict__ bias,
             float* __restrict__ out, size_t ldout, int Kblk,
             const float* __restrict__ mean, const float* __restrict__ rstd,
             const float* __restrict__ lng, const float* __restrict__ lnb,
             const float* __restrict__ resid)
{
    __shared__ __align__(1024) unsigned char sm[16384 + 2 * 9216];
    const uint32_t sb = smem_u32(sm);
    const int tid = threadIdx.x;
    const int row0 = blockIdx.x * 128;
    const int col0 = blockIdx.y * 128;
    const int nch = Kblk >> 5;

    __shared__ float sgam[256], sbet[256];
    if (AOP == AOP_LN) {
        if (tid < Kblk) { sgam[tid] = lng[tid]; sbet[tid] = lnb[tid]; }
    }

    const int arow = tid >> 1, ak0 = (tid & 1) * 16;
    float mr = 0.f, rr = 0.f;
    if (AOP == AOP_LN) { mr = mean[row0 + arow]; rr = rstd[row0 + arow]; }
    const float* Ap = A + (size_t)(row0 + arow) * lda;
    const int bkr = tid >> 3, bn0 = (tid & 7) * 16;
    const float* Bp0 = B + (size_t)bkr * ldb + col0 + bn0;

    const int lane = tid & 31, w = tid >> 5;
    const int mw = w >> 2, nw = w & 3;
    const int g = lane >> 2, tig = lane & 3;
    const int lrow = (lane & 7) + ((lane >> 3) & 1) * 8;
    const int lkh = (lane >> 4) * 16;
    const int trow = (lane & 7) + ((lane >> 4) & 1) * 8;
    const int tnh = ((lane >> 3) & 1) * 16;

    float acc[4][4][4];
#pragma unroll
    for (int mi = 0; mi < 4; mi++)
#pragma unroll
        for (int ni = 0; ni < 4; ni++)
#pragma unroll
            for (int e = 0; e < 4; e++) acc[mi][ni][e] = 0.f;

    for (int c = 0; c < nch; c++) {
        const int kc = c * 32;
        __syncthreads();
#pragma unroll
        for (int i = 0; i < 4; i++) {
            float4 t = *(const float4*)(Ap + kc + ak0 + i * 4);
            float v[4] = {t.x, t.y, t.z, t.w};
            if (AOP == AOP_LN) {
#pragma unroll
                for (int j = 0; j < 4; j++) {
                    const int kg = kc + ak0 + i * 4 + j;
                    v[j] = (v[j] - mr) * rr * sgam[kg] + sbet[kg];
                }
            }
            const unsigned base = arow * 64 + (ak0 + i * 4) * 2;
            __nv_bfloat16 h0, l0, h1, l1;
            split2(v[0], h0, l0); split2(v[1], h1, l1);
            *(unsigned*)(sm + SWZ(base)) = pack2(h0, h1);
            *(unsigned*)(sm + 8192 + SWZ(base)) = pack2(l0, l1);
            split2(v[2], h0, l0); split2(v[3], h1, l1);
            *(unsigned*)(sm + SWZ(base + 4)) = pack2(h0, h1);
            *(unsigned*)(sm + 8192 + SWZ(base + 4)) = pack2(l0, l1);
        }
#pragma unroll
        for (int i = 0; i < 4; i++) {
            float4 t = *(const float4*)(Bp0 + (size_t)kc * ldb + i * 4);
            float v[4] = {t.x, t.y, t.z, t.w};
            const unsigned base = bkr * BSTRIDE0 + (bn0 + i * 4) * 2;
            __nv_bfloat16 h0, l0, h1, l1;
            split2(v[0], h0, l0); split2(v[1], h1, l1);
            *(unsigned*)(sm + 16384 + SWZ(base)) = pack2(h0, h1);
            *(unsigned*)(sm + 16384 + 9216 + SWZ(base)) = pack2(l0, l1);
            split2(v[2], h0, l0); split2(v[3], h1, l1);
            *(unsigned*)(sm + 16384 + SWZ(base + 4)) = pack2(h0, h1);
            *(unsigned*)(sm + 16384 + 9216 + SWZ(base + 4)) = pack2(l0, l1);
        }
        __syncthreads();
#pragma unroll
        for (int ks = 0; ks < 2; ks++) {
            unsigned ah[4][4], al[4][4];
#pragma unroll
            for (int mi = 0; mi < 4; mi++) {
                const int r = mw * 64 + mi * 16 + lrow;
                const unsigned off = SWZ(r * 64 + ks * 32 + lkh);
                LDSM4(ah[mi], sb + off);
                LDSM4(al[mi], sb + 8192 + off);
            }
#pragma unroll
            for (int nb = 0; nb < 2; nb++) {
                unsigned bh[4], bl[4];
                const int kr = ks * 16 + trow;
                const unsigned off = SWZ(kr * BSTRIDE0 + (nw * 32 + nb * 16) * 2 + tnh);
                LDSM4T(bh, sb + 16384 + off);
                LDSM4T(bl, sb + 16384 + 9216 + off);
                unsigned beh[2] = {bh[0], bh[2]}, boh[2] = {bh[1], bh[3]};
                unsigned bel[2] = {bl[0], bl[2]}, bol[2] = {bl[1], bl[3]};
#pragma unroll
                for (int mi = 0; mi < 4; mi++) {
                    mma16816(acc[mi][2 * nb],     ah[mi], beh);
                    mma16816(acc[mi][2 * nb],     ah[mi], bel);
                    mma16816(acc[mi][2 * nb],     al[mi], beh);
                    mma16816(acc[mi][2 * nb + 1], ah[mi], boh);
                    mma16816(acc[mi][2 * nb + 1], ah[mi], bol);
                    mma16816(acc[mi][2 * nb + 1], al[mi], boh);
                }
            }
        }
    }

#pragma unroll
    for (int mi = 0; mi < 4; mi++) {
        const int r = row0 + mw * 64 + mi * 16 + g;
#pragma unroll
        for (int ni = 0; ni < 4; ni++) {
            const int colG = col0 + nw * 32 + ni * 8 + 2 * tig;
            float v0 = acc[mi][ni][0], v1 = acc[mi][ni][1];
            float v2 = acc[mi][ni][2], v3 = acc[mi][ni][3];
            if (EPI & LEPI_BIAS) {
                float2 bb = *(const float2*)(bias + colG);
                v0 += bb.x; v1 += bb.y; v2 += bb.x; v3 += bb.y;
            }
            if (EPI & LEPI_GELU) {
                v0 = geluf(v0); v1 = geluf(v1); v2 = geluf(v2); v3 = geluf(v3);
            }
            if (EPI & LEPI_RESID) {
                float2 ra = *(const float2*)(resid + (size_t)r * 256 + colG);
                float2 rb = *(const float2*)(resid + (size_t)(r + 8) * 256 + colG);
                v0 += ra.x; v1 += ra.y; v2 += rb.x; v3 += rb.y;
            }
            *(float2*)(out + (size_t)r * ldout + colG)       = make_float2(v0, v1);
            *(float2*)(out + (size_t)(r + 8) * ldout + colG) = make_float2(v2, v3);
        }
    }
}

// ---------------- prep kernels ----------------------------------------------
__global__ void prep_pf(const float* __restrict__ pf,
                        __nv_bfloat16* __restrict__ H, __nv_bfloat16* __restrict__ L, int N)
{
    int idx = blockIdx.x * 256 + threadIdx.x;
    int row = idx / 12, c8 = (idx % 12) * 8;
    if (row >= N) return;
    __nv_bfloat16 h[8], l[8];
#pragma unroll
    for (int j = 0; j < 8; j++) {
        int k = c8 + j;
        float v = (k < 72) ? pf[(size_t)row * 72 + k] : 0.f;
        split2(v, h[j], l[j]);
    }
    *(uint4*)(H + (size_t)row * 96 + c8) = *(uint4*)h;
    *(uint4*)(L + (size_t)row * 96 + c8) = *(uint4*)l;
}

__global__ void prep_w(const float* __restrict__ W,
                       __nv_bfloat16* __restrict__ H, __nv_bfloat16* __restrict__ L,
                       int rows, int realrows)
{
    int idx = blockIdx.x * 256 + threadIdx.x;
    int row = idx / 32, c8 = (idx % 32) * 8;
    if (row >= rows) return;
    __nv_bfloat16 h[8], l[8];
#pragma unroll
    for (int j = 0; j < 8; j++) {
        float v = (row < realrows) ? W[(size_t)row * 256 + c8 + j] : 0.f;
        split2(v, h[j], l[j]);
    }
    *(uint4*)(H + (size_t)row * 256 + c8) = *(uint4*)h;
    *(uint4*)(L + (size_t)row * 256 + c8) = *(uint4*)l;
}

template <bool GELU>
__global__ __launch_bounds__(256)
void lnprep(const __nv_bfloat16* __restrict__ inH, const __nv_bfloat16* __restrict__ inL,
            const float* __restrict__ gam, const float* __restrict__ bet,
            __nv_bfloat16* __restrict__ outH, __nv_bfloat16* __restrict__ outL, int M)
{
    const int wid = threadIdx.x >> 5, lane = threadIdx.x & 31;
    const int row = blockIdx.x * 8 + wid;
    if (row >= M) return;
    const int c8 = lane * 8;
    uint4 uh = *(const uint4*)(inH + (size_t)row * 256 + c8);
    uint4 ul = *(const uint4*)(inL + (size_t)row * 256 + c8);
    const __nv_bfloat16* ph = (const __nv_bfloat16*)&uh;
    const __nv_bfloat16* pl = (const __nv_bfloat16*)&ul;
    float v[8];
    float s = 0.f, ss = 0.f;
#pragma unroll
    for (int j = 0; j < 8; j++) {
        v[j] = __bfloat162float(ph[j]) + __bfloat162float(pl[j]);
        s += v[j]; ss += v[j] * v[j];
    }
#pragma unroll
    for (int o = 16; o; o >>= 1) {
        s  += __shfl_xor_sync(0xffffffffu, s, o);
        ss += __shfl_xor_sync(0xffffffffu, ss, o);
    }
    const float m = s * (1.0f / 256.0f);
    const float r = rsqrtf(ss * (1.0f / 256.0f) - m * m + 1e-5f);
    float4 g0 = *(const float4*)(gam + c8), g1 = *(const float4*)(gam + c8 + 4);
    float4 b0 = *(const float4*)(bet + c8), b1 = *(const float4*)(bet + c8 + 4);
    float gg[8] = {g0.x, g0.y, g0.z, g0.w, g1.x, g1.y, g1.z, g1.w};
    float bb[8] = {b0.x, b0.y, b0.z, b0.w, b1.x, b1.y, b1.z, b1.w};
    __nv_bfloat16 oh[8], ol[8];
#pragma unroll
    for (int j = 0; j < 8; j++) {
        float x = (v[j] - m) * r * gg[j] + bb[j];
        if (GELU) x = geluf(x);
        split2(x, oh[j], ol[j]);
    }
    *(uint4*)(outH + (size_t)row * 256 + c8) = *(uint4*)oh;
    *(uint4*)(outL + (size_t)row * 256 + c8) = *(uint4*)ol;
}

// ---------------- misc small kernels ----------------------------------------
__global__ __launch_bounds__(256)
void ln_stats(const float* __restrict__ X, float* __restrict__ mean,
              float* __restrict__ rstd, int M)
{
    int warp = (blockIdx.x * blockDim.x + threadIdx.x) >> 5;
    if (warp >= M) return;
    int lane = threadIdx.x & 31;
    const float* row = X + (size_t)warp * 256;
    float s = 0.f, ss = 0.f;
#pragma unroll
    for (int j = 0; j < 8; j++) { float v = row[lane + 32 * j]; s += v; ss += v * v; }
#pragma unroll
    for (int o = 16; o; o >>= 1) {
        s  += __shfl_xor_sync(0xffffffffu, s, o);
        ss += __shfl_xor_sync(0xffffffffu, ss, o);
    }
    if (lane == 0) {
        float m = s * (1.0f / 256.0f);
        mean[warp] = m;
        rstd[warp] = rsqrtf(ss * (1.0f / 256.0f) - m * m + 1e-5f);
    }
}

__global__ __launch_bounds__(256)
void rownorm(const float* __restrict__ X, float* __restrict__ inv, int M)
{
    int warp = (blockIdx.x * blockDim.x + threadIdx.x) >> 5;
    if (warp >= M) return;
    int lane = threadIdx.x & 31;
    const float* row = X + (size_t)warp * 256;
    float ss = 0.f;
#pragma unroll
    for (int j = 0; j < 8; j++) { float v = row[lane + 32 * j]; ss += v * v; }
#pragma unroll
    for (int o = 16; o; o >>= 1) ss += __shfl_xor_sync(0xffffffffu, ss, o);
    if (lane == 0) inv[warp] = 1.0f / fmaxf(sqrtf(ss), 1e-12f);
}

// combine GEMM4's per-half row SSQ partials into invpe
__global__ void combine_ssq(const float* __restrict__ ssqp, float* __restrict__ inv, int N)
{
    int i = blockIdx.x * 256 + threadIdx.x;
    if (i < N) inv[i] = 1.0f / fmaxf(sqrtf(ssqp[i] + ssqp[(size_t)N + i]), 1e-12f);
}

__global__ void qmpair(const float* __restrict__ qe, const float* __restrict__ invq,
                       const float* __restrict__ lsc,
                       __nv_bfloat16* __restrict__ H, __nv_bfloat16* __restrict__ L)
{
    int idx = blockIdx.x * 256 + threadIdx.x;
    int r = idx >> 8;
    float v = qe[idx] * invq[r] * expf(lsc[0]);
    __nv_bfloat16 h, l;
    split2(v, h, l);
    H[idx] = h; L[idx] = l;
}

__global__ __launch_bounds__(256)
void reduce_refined(const float* __restrict__ Ppart, const float* __restrict__ spart,
                    const float* __restrict__ qe, float* __restrict__ refined,
                    int CH, int NB)
{
    const int q = blockIdx.x;
    const int d = threadIdx.x;
    __shared__ float sh[256];
    float s = 0.f;
    for (int i = d; i < NB; i += 256) s += spart[(size_t)i * 128 + q];
    sh[d] = s;
    __syncthreads();
    for (int o = 128; o; o >>= 1) {
        if (d < o) sh[d] += sh[d + o];
        __syncthreads();
    }
    const float stot = sh[0];
    float p = 0.f;
    for (int c = 0; c < CH; c++) p += Ppart[((size_t)c * 128 + q) * 256 + d];
    refined[(size_t)q * 256 + d] = qe[(size_t)q * 256 + d] + p / stot;
}

__global__ __launch_bounds__(256)
void score_kernel(const float* __restrict__ A2s, const float* __restrict__ w2,
                  const float* __restrict__ b2, float* __restrict__ out)
{
    const int q = blockIdx.x;
    const int d = threadIdx.x;
    __shared__ float sh[256];
    sh[d] = A2s[(size_t)q * 256 + d] * w2[d];
    __syncthreads();
    for (int o = 128; o; o >>= 1) {
        if (d < o) sh[d] += sh[d + o];
        __syncthreads();
    }
    if (d == 0) out[q] = sh[0] + b2[0];
}

// ---------------------------------------------------------------------------
extern "C" void kernel_launch(void* const* d_in, const int* in_sizes, int n_in,
                              void* d_out, int out_size)
{
    const float* point_feat = (const float*)d_in[0];
    const float* ip_w1 = (const float*)d_in[1];
    const float* ip_b1 = (const float*)d_in[2];
    const float* ip_ln_g = (const float*)d_in[3];
    const float* ip_ln_b = (const float*)d_in[4];
    const float* ip_w2 = (const float*)d_in[5];
    const float* ip_b2 = (const float*)d_in[6];
    const float* ph_ln_g = (const float*)d_in[7];
    const float* ph_ln_b = (const float*)d_in[8];
    const float* ph_w1 = (const float*)d_in[9];
    const float* ph_b1 = (const float*)d_in[10];
    const float* ph_w2 = (const float*)d_in[11];
    const float* ph_b2 = (const float*)d_in[12];
    const float* q_embed = (const float*)d_in[13];
    const float* qh_ln_g = (const float*)d_in[14];
    const float* qh_ln_b = (const float*)d_in[15];
    const float* qh_w1 = (const float*)d_in[16];
    const float* qh_b1 = (const float*)d_in[17];
    const float* qh_w2 = (const float*)d_in[18];
    const float* qh_b2 = (const float*)d_in[19];
    const float* sh_ln_g = (const float*)d_in[20];
    const float* sh_ln_b = (const float*)d_in[21];
    const float* sh_w1 = (const float*)d_in[22];
    const float* sh_b1 = (const float*)d_in[23];
    const float* sh_w2 = (const float*)d_in[24];
    const float* sh_b2 = (const float*)d_in[25];
    const float* logit_scale = (const float*)d_in[26];

    const int N = in_sizes[0] / 72;

    float* out = (float*)d_out;
    const size_t offScore = (size_t)128 * N;
    const size_t offPE = offScore + 128;
    const size_t offRef = offPE + (size_t)N * 256;
    float* mask = out;
    float* score = out + offScore;
    float* pe = out + offPE;
    float* refined = out + offRef;

    __nv_bfloat16 *pfH, *pfL, *xH, *xL, *aH, *aL, *hH, *hL, *peH, *peL, *emH, *emL;
    __nv_bfloat16 *w1H, *w1L, *w2H, *w2L, *w3H, *w3L, *w4H, *w4L, *qmH, *qmL;
    float *invpe, *meanQ, *rstdQ, *A2q, *qe, *invq, *spart, *Ppart;
    cudaGetSymbolAddress((void**)&pfH, g_pfH); cudaGetSymbolAddress((void**)&pfL, g_pfL);
    cudaGetSymbolAddress((void**)&xH, g_xH);   cudaGetSymbolAddress((void**)&xL, g_xL);
    cudaGetSymbolAddress((void**)&aH, g_aH);   cudaGetSymbolAddress((void**)&aL, g_aL);
    cudaGetSymbolAddress((void**)&hH, g_hH);   cudaGetSymbolAddress((void**)&hL, g_hL);
    cudaGetSymbolAddress((void**)&peH, g_peH); cudaGetSymbolAddress((void**)&peL, g_peL);
    cudaGetSymbolAddress((void**)&emH, g_emH); cudaGetSymbolAddress((void**)&emL, g_emL);
    cudaGetSymbolAddress((void**)&w1H, g_w1H); cudaGetSymbolAddress((void**)&w1L, g_w1L);
    cudaGetSymbolAddress((void**)&w2H, g_w2H); cudaGetSymbolAddress((void**)&w2L, g_w2L);
    cudaGetSymbolAddress((void**)&w3H, g_w3H); cudaGetSymbolAddress((void**)&w3L, g_w3L);
    cudaGetSymbolAddress((void**)&w4H, g_w4H); cudaGetSymbolAddress((void**)&w4L, g_w4L);
    cudaGetSymbolAddress((void**)&qmH, g_qmH); cudaGetSymbolAddress((void**)&qmL, g_qmL);
    cudaGetSymbolAddress((void**)&invpe, g_invpe);
    cudaGetSymbolAddress((void**)&meanQ, g_meanQ); cudaGetSymbolAddress((void**)&rstdQ, g_rstdQ);
    cudaGetSymbolAddress((void**)&A2q, g_A2q); cudaGetSymbolAddress((void**)&qe, g_qe);
    cudaGetSymbolAddress((void**)&invq, g_invq);
    cudaGetSymbolAddress((void**)&spart, g_spart); cudaGetSymbolAddress((void**)&Ppart, g_Ppart);

    // dynamic smem opt-in (3 stages)
    const int SMEM_BT0 = 3 * (16384 + 2 * 9216) + 2048;   // 106496
    const int SMEM_BT1 = 3 * (16384 + 2 * 8192) + 2048;   // 100352
    cudaFuncSetAttribute(tpair<EPI_BIAS | EPI_OUTPAIR, 0>,
                         cudaFuncAttributeMaxDynamicSharedMemorySize, SMEM_BT0);
    cudaFuncSetAttribute(tpair<EPI_BIAS | EPI_GELU | EPI_OUTPAIR, 0>,
                         cudaFuncAttributeMaxDynamicSharedMemorySize, SMEM_BT0);
    cudaFuncSetAttribute(tpair<EPI_BIAS | EPI_RESIDP | EPI_OUTF32 | EPI_OUTPAIR | EPI_SSQ, 0>,
                         cudaFuncAttributeMaxDynamicSharedMemorySize, SMEM_BT0);
    cudaFuncSetAttribute(tpair<EPI_CSCALE | EPI_OUTF32 | EPI_EXPPAIR | EPI_SPART, 1>,
                         cudaFuncAttributeMaxDynamicSharedMemorySize, SMEM_BT1);
    cudaFuncSetAttribute(tpair<EPI_OUTF32, 0>,
                         cudaFuncAttributeMaxDynamicSharedMemorySize, SMEM_BT0);

    // -------- preps --------
    prep_pf<<<(N * 12 + 255) / 256, 256>>>(point_feat, pfH, pfL, N);
    prep_w<<<12, 256>>>(ip_w1, w1H, w1L, 96, 72);
    prep_w<<<32, 256>>>(ip_w2, w2H, w2L, 256, 256);
    prep_w<<<32, 256>>>(ph_w1, w3H, w3L, 256, 256);
    prep_w<<<32, 256>>>(ph_w2, w4H, w4L, 256, 256);

    const dim3 gBig(N / 128, 2);

    // -------- point pipeline --------
    // x = point_feat @ ip_w1 + ip_b1  (pairs)
    tpair<EPI_BIAS | EPI_OUTPAIR, 0><<<gBig, 256, SMEM_BT0>>>(
        pfH, pfL, 96, w1H, w1L, 256, ip_b1,
        nullptr, 0, 0, xH, xL, 256, nullptr, nullptr, nullptr, nullptr, 0, 96);
    // a = gelu(LN(x)) (pairs)
    lnprep<true><<<N / 8, 256>>>(xH, xL, ip_ln_g, ip_ln_b, aH, aL, N);
    // h = a @ ip_w2 + ip_b2 (pairs)
    tpair<EPI_BIAS | EPI_OUTPAIR, 0><<<gBig, 256, SMEM_BT0>>>(
        aH, aL, 256, w2H, w2L, 256, ip_b2,
        nullptr, 0, 0, hH, hL, 256, nullptr, nullptr, nullptr, nullptr, 0, 256);
    // a = LN(h) (pairs)
    lnprep<false><<<N / 8, 256>>>(hH, hL, ph_ln_g, ph_ln_b, aH, aL, N);
    // x = gelu(a @ ph_w1 + ph_b1) (pairs)
    tpair<EPI_BIAS | EPI_GELU | EPI_OUTPAIR, 0><<<gBig, 256, SMEM_BT0>>>(
        aH, aL, 256, w3H, w3L, 256, ph_b1,
        nullptr, 0, 0, xH, xL, 256, nullptr, nullptr, nullptr, nullptr, 0, 256);
    // pe = h + x @ ph_w2 + ph_b2 (fp32 to d_out + pairs + fused row-SSQ)
    tpair<EPI_BIAS | EPI_RESIDP | EPI_OUTF32 | EPI_OUTPAIR | EPI_SSQ, 0><<<gBig, 256, SMEM_BT0>>>(
        xH, xL, 256, w4H, w4L, 256, ph_b2,
        pe, 256, 0, peH, peL, 256, hH, hL, nullptr, spart, (size_t)N, 256);
    combine_ssq<<<(N + 255) / 256, 256>>>(spart, invpe, N);

    // -------- query pipeline (legacy, tiny) --------
    ln_stats<<<16, 256>>>(q_embed, meanQ, rstdQ, 128);
    tlegacy<AOP_LN, LEPI_BIAS | LEPI_GELU><<<dim3(1, 2), 256>>>(
        q_embed, 256, qh_w1, 256, qh_b1, A2q, 256, 256,
        meanQ, rstdQ, qh_ln_g, qh_ln_b, nullptr);
    tlegacy<AOP_ID, LEPI_BIAS | LEPI_RESID><<<dim3(1, 2), 256>>>(
        A2q, 256, qh_w2, 256, qh_b2, qe, 256, 256,
        nullptr, nullptr, nullptr, nullptr, q_embed);
    rownorm<<<16, 256>>>(qe, invq, 128);
    qmpair<<<128, 256>>>(qe, invq, logit_scale, qmH, qmL);

    // -------- mask logits + exp pairs + softmax partial sums --------
    tpair<EPI_CSCALE | EPI_OUTF32 | EPI_EXPPAIR | EPI_SPART, 1><<<dim3(1, N / 128), 256, SMEM_BT1>>>(
        qmH, qmL, 256, peH, peL, 256, nullptr,
        mask, (size_t)N, 0, emH, emL, (size_t)N, nullptr, nullptr, invpe, spart, 128, 256);

    // -------- weighted aggregation: Ppart[z] = em chunk @ pe chunk ----------
    tpair<EPI_OUTF32, 0><<<dim3(1, 2, 256), 256, SMEM_BT0>>>(
        emH, emL, N, peH, peL, 256, nullptr,
        Ppart, 256, (size_t)128 * 256, nullptr, nullptr, 0,
        nullptr, nullptr, nullptr, nullptr, 0, 1024);
    reduce_refined<<<128, 256>>>(Ppart, spart, qe, refined, 256, N / 128);

    // -------- score head (legacy) --------
    ln_stats<<<16, 256>>>(refined, meanQ, rstdQ, 128);
    tlegacy<AOP_LN, LEPI_BIAS | LEPI_GELU><<<dim3(1, 2), 256>>>(
        refined, 256, sh_w1, 256, sh_b1, A2q, 256, 256,
        meanQ, rstdQ, sh_ln_g, sh_ln_b, nullptr);
    score_kernel<<<128, 256>>>(A2q, sh_w2, sh_b2, score);
}

// round 13
// speedup vs baseline: 1.0676x; 1.0417x over previous
#include <cuda_runtime.h>
#include <cuda_bf16.h>
#include <math.h>
#include <stdint.h>

// ---------------------------------------------------------------------------
// QueryInstanceDecoder: bf16 split-precision mma.sync pipeline, v6.
// = R9 (best passing) + GEMM1 fused with gelu(LN(.)) via R10's verified
//   tpair256 path (kills lnprep#1 and the x-pair DRAM round trip), + __expf.
// N=262144, C_IN=72, D=256, Q=128.
// d_out (floats): mask_logits[128*N] | score[128] | point_embed[N*256] | refined[128*256]
// ---------------------------------------------------------------------------

#define DEVI __device__ __forceinline__

DEVI float geluf(float x) { return 0.5f * x * (1.0f + erff(x * 0.70710678118654752f)); }

DEVI unsigned pack2(__nv_bfloat16 a, __nv_bfloat16 b) {
    return (unsigned)__bfloat16_as_ushort(a) | ((unsigned)__bfloat16_as_ushort(b) << 16);
}
DEVI void split2(float x, __nv_bfloat16& h, __nv_bfloat16& l) {
    h = __float2bfloat16(x);
    l = __float2bfloat16(x - __bfloat162float(h));
}
DEVI float upk_lo(unsigned u) { return __bfloat162float(__ushort_as_bfloat16((unsigned short)(u & 0xffff))); }
DEVI float upk_hi(unsigned u) { return __bfloat162float(__ushort_as_bfloat16((unsigned short)(u >> 16))); }

DEVI void mma16816(float* c, const unsigned* a, const unsigned* b) {
    asm volatile(
        "mma.sync.aligned.m16n8k16.row.col.f32.bf16.bf16.f32 "
        "{%0,%1,%2,%3},{%4,%5,%6,%7},{%8,%9},{%0,%1,%2,%3};"
        : "+f"(c[0]), "+f"(c[1]), "+f"(c[2]), "+f"(c[3])
        : "r"(a[0]), "r"(a[1]), "r"(a[2]), "r"(a[3]), "r"(b[0]), "r"(b[1]));
}
DEVI uint32_t smem_u32(const void* p) {
    uint32_t a;
    asm("{ .reg .u64 t; cvta.to.shared.u64 t, %1; cvt.u32.u64 %0, t; }" : "=r"(a) : "l"(p));
    return a;
}
#define LDSM4(r, a) \
    asm volatile("ldmatrix.sync.aligned.m8n8.x4.shared.b16 {%0,%1,%2,%3},[%4];" \
        : "=r"((r)[0]), "=r"((r)[1]), "=r"((r)[2]), "=r"((r)[3]) : "r"(a))
#define LDSM4T(r, a) \
    asm volatile("ldmatrix.sync.aligned.m8n8.x4.trans.shared.b16 {%0,%1,%2,%3},[%4];" \
        : "=r"((r)[0]), "=r"((r)[1]), "=r"((r)[2]), "=r"((r)[3]) : "r"(a))

DEVI void cpasync16(uint32_t dst, const void* src) {
    asm volatile("cp.async.cg.shared.global [%0], [%1], 16;" :: "r"(dst), "l"(src));
}
DEVI void cpcommit() { asm volatile("cp.async.commit_group;"); }
DEVI void cpwait1()  { asm volatile("cp.async.wait_group 1;"); }
DEVI void cpwait0()  { asm volatile("cp.async.wait_group 0;"); }

#define SWZ(o) ((unsigned)(o) ^ ((((unsigned)(o)) >> 3) & 0x70))
#define BSTRIDE0 288

// ---------------- scratch (static device memory; no allocations) -----------
#define NMAX 262144
__device__ __nv_bfloat16 g_pfH[(size_t)NMAX * 96], g_pfL[(size_t)NMAX * 96];
__device__ __nv_bfloat16 g_xH[(size_t)NMAX * 256], g_xL[(size_t)NMAX * 256];
__device__ __nv_bfloat16 g_aH[(size_t)NMAX * 256], g_aL[(size_t)NMAX * 256];
__device__ __nv_bfloat16 g_hH[(size_t)NMAX * 256], g_hL[(size_t)NMAX * 256];
__device__ __nv_bfloat16 g_peH[(size_t)NMAX * 256], g_peL[(size_t)NMAX * 256];
__device__ __nv_bfloat16 g_emH[(size_t)128 * NMAX], g_emL[(size_t)128 * NMAX];
__device__ __nv_bfloat16 g_w1H[96 * 256], g_w1L[96 * 256];     // [n=256][k=96] transposed
__device__ __nv_bfloat16 g_w2H[256 * 256], g_w2L[256 * 256];   // [k][n]
__device__ __nv_bfloat16 g_w3H[256 * 256], g_w3L[256 * 256];
__device__ __nv_bfloat16 g_w4H[256 * 256], g_w4L[256 * 256];
__device__ __nv_bfloat16 g_qmH[128 * 256], g_qmL[128 * 256];
__device__ float g_invpe[NMAX];
__device__ float g_meanQ[128], g_rstdQ[128];
__device__ float g_A2q[128 * 256];
__device__ float g_qe[128 * 256];
__device__ float g_invq[128];
__device__ float g_spart[(size_t)2 * NMAX];
__device__ float g_Ppart[256 * 128 * 256];

// ---------------- epilogue flags --------------------------------------------
#define EPI_BIAS    1
#define EPI_GELU    2
#define EPI_RESIDP  4
#define EPI_OUTF32  8
#define EPI_OUTPAIR 16
#define EPI_SPART   32
#define EPI_CSCALE  64
#define EPI_EXPPAIR 128
#define EPI_SSQ     256
#define EPI_LNPAIR  512
#define EPI_LNGELU  1024

// =============================================================================
// tpair256 (verified in R10): C[128x256] = A_pairs[128xK] @ B_pairs^T
// (B image [n][k]). 512 threads, 16 warps (2x8), warp 64x32, 2-stage cp.async.
// Used ONLY for GEMM1 (K=96) with BIAS+LNPAIR+LNGELU fused epilogue.
// =============================================================================
#define STG256 49152
#define SP_OFF (2 * STG256)
#define SMEM256 (SP_OFF + 4096 + 4096 + 512 + 512 + 1024 + 1024)

template <int EPI>
__global__ __launch_bounds__(512, 1)
void tpair256(const __nv_bfloat16* __restrict__ Ah, const __nv_bfloat16* __restrict__ Al, int lda,
              const __nv_bfloat16* __restrict__ Bh, const __nv_bfloat16* __restrict__ Bl, int ldb,
              const float* __restrict__ bias,
              float* __restrict__ outf, size_t ldout,
              __nv_bfloat16* __restrict__ oh, __nv_bfloat16* __restrict__ ol,
              __nv_bfloat16* __restrict__ o2h, __nv_bfloat16* __restrict__ o2l,
              const __nv_bfloat16* __restrict__ resH, const __nv_bfloat16* __restrict__ resL,
              const float* __restrict__ gam, const float* __restrict__ bet,
              float* __restrict__ invout, int Kblk)
{
    extern __shared__ __align__(1024) unsigned char sm[];
    const uint32_t sb = smem_u32(sm);
    float* spS  = (float*)(sm + SP_OFF);
    float* spSS = (float*)(sm + SP_OFF + 4096);
    float* marr = (float*)(sm + SP_OFF + 8192);
    float* rarr = (float*)(sm + SP_OFF + 8704);
    float* sgam = (float*)(sm + SP_OFF + 9216);
    float* sbet = (float*)(sm + SP_OFF + 10240);

    const int tid  = threadIdx.x;
    const int row0 = blockIdx.x * 128;
    const int nch  = Kblk >> 5;

    if (EPI & EPI_LNPAIR) {
        if (tid < 256) { sgam[tid] = gam[tid]; sbet[tid] = bet[tid]; }
    }

    const int arow = tid >> 2, ak0 = (tid & 3) * 8;
    const int brow = tid >> 1, bk0 = (tid & 1) * 16;
    const unsigned dA  = SWZ(arow * 64 + ak0 * 2);
    const unsigned dB  = SWZ(brow * 64 + bk0 * 2);
    const unsigned dB2 = SWZ(brow * 64 + bk0 * 2 + 16);
    const __nv_bfloat16* ApH = Ah + (size_t)(row0 + arow) * lda + ak0;
    const __nv_bfloat16* ApL = Al + (size_t)(row0 + arow) * lda + ak0;
    const __nv_bfloat16* BpH = Bh + (size_t)brow * ldb + bk0;
    const __nv_bfloat16* BpL = Bl + (size_t)brow * ldb + bk0;

    auto issue = [&](int c) {
        const int kc = c * 32;
        const uint32_t st = sb + (c & 1) * STG256;
        cpasync16(st + dA, ApH + kc);
        cpasync16(st + 8192 + dA, ApL + kc);
        cpasync16(st + 16384 + dB,  BpH + kc);
        cpasync16(st + 16384 + dB2, BpH + kc + 8);
        cpasync16(st + 32768 + dB,  BpL + kc);
        cpasync16(st + 32768 + dB2, BpL + kc + 8);
        cpcommit();
    };

    const int lane = tid & 31, w = tid >> 5;
    const int mw = w >> 3, nw = w & 7;
    const int g = lane >> 2, tig = lane & 3;
    const int lrow = (lane & 7) + ((lane >> 3) & 1) * 8;
    const int lkh  = (lane >> 4) * 16;

    float acc[4][4][4];
#pragma unroll
    for (int mi = 0; mi < 4; mi++)
#pragma unroll
        for (int ni = 0; ni < 4; ni++)
#pragma unroll
            for (int e = 0; e < 4; e++) acc[mi][ni][e] = 0.f;

    auto compute = [&](int c) {
        const uint32_t st = sb + (c & 1) * STG256;
#pragma unroll
        for (int ks = 0; ks < 2; ks++) {
            unsigned ah[4][4], al[4][4];
#pragma unroll
            for (int mi = 0; mi < 4; mi++) {
                const int r = mw * 64 + mi * 16 + lrow;
                const unsigned off = SWZ(r * 64 + ks * 32 + lkh);
                LDSM4(ah[mi], st + off);
                LDSM4(al[mi], st + 8192 + off);
            }
#pragma unroll
            for (int nb = 0; nb < 2; nb++) {
                unsigned bh[4], bl[4];
                const int n = nw * 32 + nb * 16 + lrow;
                const unsigned off = SWZ(n * 64 + ks * 32 + lkh);
                LDSM4(bh, st + 16384 + off);
                LDSM4(bl, st + 32768 + off);
                unsigned beh[2] = {bh[0], bh[2]}, boh[2] = {bh[1], bh[3]};
                unsigned bel[2] = {bl[0], bl[2]}, bol[2] = {bl[1], bl[3]};
#pragma unroll
                for (int mi = 0; mi < 4; mi++) {
                    mma16816(acc[mi][2 * nb],     ah[mi], beh);
                    mma16816(acc[mi][2 * nb],     ah[mi], bel);
                    mma16816(acc[mi][2 * nb],     al[mi], beh);
                    mma16816(acc[mi][2 * nb + 1], ah[mi], boh);
                    mma16816(acc[mi][2 * nb + 1], ah[mi], bol);
                    mma16816(acc[mi][2 * nb + 1], al[mi], boh);
                }
            }
        }
    };

    issue(0);
    for (int c = 0; c < nch; c++) {
        if (c + 1 < nch) { issue(c + 1); cpwait1(); } else { cpwait0(); }
        __syncthreads();
        compute(c);
        __syncthreads();
    }

    // pass A: finalize, stats
    float sS0[4], sS1[4], sSS0[4], sSS1[4];
#pragma unroll
    for (int mi = 0; mi < 4; mi++) { sS0[mi] = sS1[mi] = sSS0[mi] = sSS1[mi] = 0.f; }

#pragma unroll
    for (int mi = 0; mi < 4; mi++) {
        const int r = row0 + mw * 64 + mi * 16 + g;
#pragma unroll
        for (int ni = 0; ni < 4; ni++) {
            const int colG = nw * 32 + ni * 8 + 2 * tig;
            float v0 = acc[mi][ni][0], v1 = acc[mi][ni][1];
            float v2 = acc[mi][ni][2], v3 = acc[mi][ni][3];
            if (EPI & EPI_BIAS) {
                float2 bb = *(const float2*)(bias + colG);
                v0 += bb.x; v1 += bb.y; v2 += bb.x; v3 += bb.y;
            }
            if (EPI & EPI_GELU) {
                v0 = geluf(v0); v1 = geluf(v1); v2 = geluf(v2); v3 = geluf(v3);
            }
            if (EPI & EPI_RESIDP) {
                unsigned uh0 = *(const unsigned*)(resH + (size_t)r * 256 + colG);
                unsigned ul0 = *(const unsigned*)(resL + (size_t)r * 256 + colG);
                unsigned uh1 = *(const unsigned*)(resH + (size_t)(r + 8) * 256 + colG);
                unsigned ul1 = *(const unsigned*)(resL + (size_t)(r + 8) * 256 + colG);
                v0 += upk_lo(uh0) + upk_lo(ul0); v1 += upk_hi(uh0) + upk_hi(ul0);
                v2 += upk_lo(uh1) + upk_lo(ul1); v3 += upk_hi(uh1) + upk_hi(ul1);
            }
            if (EPI & EPI_OUTF32) {
                *(float2*)(outf + (size_t)r * ldout + colG)       = make_float2(v0, v1);
                *(float2*)(outf + (size_t)(r + 8) * ldout + colG) = make_float2(v2, v3);
            }
            if (EPI & EPI_LNPAIR) { sS0[mi] += v0 + v1; sS1[mi] += v2 + v3; }
            if (EPI & (EPI_SSQ | EPI_LNPAIR)) {
                sSS0[mi] += v0 * v0 + v1 * v1;
                sSS1[mi] += v2 * v2 + v3 * v3;
            }
            acc[mi][ni][0] = v0; acc[mi][ni][1] = v1;
            acc[mi][ni][2] = v2; acc[mi][ni][3] = v3;
        }
    }

    if (EPI & (EPI_SSQ | EPI_LNPAIR)) {
#pragma unroll
        for (int mi = 0; mi < 4; mi++) {
            float a0 = sS0[mi], a1 = sS1[mi], b0 = sSS0[mi], b1 = sSS1[mi];
            a0 += __shfl_xor_sync(0xffffffffu, a0, 1); a0 += __shfl_xor_sync(0xffffffffu, a0, 2);
            a1 += __shfl_xor_sync(0xffffffffu, a1, 1); a1 += __shfl_xor_sync(0xffffffffu, a1, 2);
            b0 += __shfl_xor_sync(0xffffffffu, b0, 1); b0 += __shfl_xor_sync(0xffffffffu, b0, 2);
            b1 += __shfl_xor_sync(0xffffffffu, b1, 1); b1 += __shfl_xor_sync(0xffffffffu, b1, 2);
            if (tig == 0) {
                const int lr = mw * 64 + mi * 16 + g;
                spS[nw * 128 + lr]      = a0;
                spS[nw * 128 + lr + 8]  = a1;
                spSS[nw * 128 + lr]     = b0;
                spSS[nw * 128 + lr + 8] = b1;
            }
        }
        __syncthreads();
        if (tid < 128) {
            float s = 0.f, ss = 0.f;
#pragma unroll
            for (int ww = 0; ww < 8; ww++) {
                s  += spS[ww * 128 + tid];
                ss += spSS[ww * 128 + tid];
            }
            if (EPI & EPI_LNPAIR) {
                float m = s * (1.0f / 256.0f);
                marr[tid] = m;
                rarr[tid] = rsqrtf(ss * (1.0f / 256.0f) - m * m + 1e-5f);
            }
            if (EPI & EPI_SSQ)
                invout[row0 + tid] = 1.0f / fmaxf(sqrtf(ss), 1e-12f);
        }
        __syncthreads();
    }

    if (EPI & (EPI_OUTPAIR | EPI_LNPAIR)) {
#pragma unroll
        for (int mi = 0; mi < 4; mi++) {
            const int lr = mw * 64 + mi * 16 + g;
            const int r = row0 + lr;
            float m0 = 0.f, r0 = 0.f, m1 = 0.f, r1 = 0.f;
            if (EPI & EPI_LNPAIR) {
                m0 = marr[lr]; r0 = rarr[lr];
                m1 = marr[lr + 8]; r1 = rarr[lr + 8];
            }
#pragma unroll
            for (int ni = 0; ni < 4; ni++) {
                const int colG = nw * 32 + ni * 8 + 2 * tig;
                float v0 = acc[mi][ni][0], v1 = acc[mi][ni][1];
                float v2 = acc[mi][ni][2], v3 = acc[mi][ni][3];
                if (EPI & EPI_OUTPAIR) {
                    __nv_bfloat16 h0, l0, h1, l1;
                    split2(v0, h0, l0); split2(v1, h1, l1);
                    *(unsigned*)(oh + (size_t)r * 256 + colG) = pack2(h0, h1);
                    *(unsigned*)(ol + (size_t)r * 256 + colG) = pack2(l0, l1);
                    split2(v2, h0, l0); split2(v3, h1, l1);
                    *(unsigned*)(oh + (size_t)(r + 8) * 256 + colG) = pack2(h0, h1);
                    *(unsigned*)(ol + (size_t)(r + 8) * 256 + colG) = pack2(l0, l1);
                }
                if (EPI & EPI_LNPAIR) {
                    const float g0 = sgam[colG], g1 = sgam[colG + 1];
                    const float b0 = sbet[colG], b1 = sbet[colG + 1];
                    float t0 = (v0 - m0) * r0 * g0 + b0;
                    float t1 = (v1 - m0) * r0 * g1 + b1;
                    float t2 = (v2 - m1) * r1 * g0 + b0;
                    float t3 = (v3 - m1) * r1 * g1 + b1;
                    if (EPI & EPI_LNGELU) {
                        t0 = geluf(t0); t1 = geluf(t1); t2 = geluf(t2); t3 = geluf(t3);
                    }
                    __nv_bfloat16 h0, l0, h1, l1;
                    split2(t0, h0, l0); split2(t1, h1, l1);
                    *(unsigned*)(o2h + (size_t)r * 256 + colG) = pack2(h0, h1);
                    *(unsigned*)(o2l + (size_t)r * 256 + colG) = pack2(l0, l1);
                    split2(t2, h0, l0); split2(t3, h1, l1);
                    *(unsigned*)(o2h + (size_t)(r + 8) * 256 + colG) = pack2(h0, h1);
                    *(unsigned*)(o2l + (size_t)(r + 8) * 256 + colG) = pack2(l0, l1);
                }
            }
        }
    }
}

// =============================================================================
// R9 pair GEMM (2-stage, 2 CTAs/SM) — best-measured mainloop, unchanged.
// =============================================================================
template <int EPI, int BT>
__global__ __launch_bounds__(256, 2)
void tpair(const __nv_bfloat16* __restrict__ Ah, const __nv_bfloat16* __restrict__ Al, int lda,
           const __nv_bfloat16* __restrict__ Bh, const __nv_bfloat16* __restrict__ Bl, int ldb,
           const float* __restrict__ bias,
           float* __restrict__ outf, size_t ldout, size_t zstride,
           __nv_bfloat16* __restrict__ oh, __nv_bfloat16* __restrict__ ol, size_t opitch,
           const __nv_bfloat16* __restrict__ resH, const __nv_bfloat16* __restrict__ resL,
           const float* __restrict__ cscale, float* __restrict__ spart, size_t spitch,
           int Kblk)
{
    constexpr int BSZ = BT ? 8192 : 9216;
    constexpr int STG = 16384 + 2 * BSZ;
    extern __shared__ __align__(1024) unsigned char sm[];
    const uint32_t sb = smem_u32(sm);
    float* sp = (float*)(sm + 2 * STG);

    const int tid  = threadIdx.x;
    const int row0 = blockIdx.x * 128;
    const int col0 = blockIdx.y * 128;
    const int kz   = blockIdx.z * Kblk;
    const int nch  = Kblk >> 5;

    const int arow = tid >> 1, ak0 = (tid & 1) * 16;
    const int brow = tid >> 1, bk0 = (tid & 1) * 16;
    const int bkr = tid >> 3, bn0 = (tid & 7) * 16;
    const unsigned dA  = SWZ(arow * 64 + ak0 * 2);
    const unsigned dA2 = SWZ(arow * 64 + ak0 * 2 + 16);
    const unsigned dB  = BT ? SWZ(brow * 64 + bk0 * 2)      : SWZ(bkr * BSTRIDE0 + bn0 * 2);
    const unsigned dB2 = BT ? SWZ(brow * 64 + bk0 * 2 + 16) : SWZ(bkr * BSTRIDE0 + bn0 * 2 + 16);
    const __nv_bfloat16* ApH = Ah + (size_t)(row0 + arow) * lda + kz + ak0;
    const __nv_bfloat16* ApL = Al + (size_t)(row0 + arow) * lda + kz + ak0;
    const __nv_bfloat16* BpH = BT ? Bh + (size_t)(col0 + brow) * ldb + kz + bk0
                                  : Bh + (size_t)(kz + bkr) * ldb + col0 + bn0;
    const __nv_bfloat16* BpL = BT ? Bl + (size_t)(col0 + brow) * ldb + kz + bk0
                                  : Bl + (size_t)(kz + bkr) * ldb + col0 + bn0;

    auto issue = [&](int c) {
        const int kc = c * 32;
        const uint32_t st = sb + (c & 1) * STG;
        cpasync16(st + dA, ApH + kc);            cpasync16(st + dA2, ApH + kc + 8);
        cpasync16(st + 8192 + dA, ApL + kc);     cpasync16(st + 8192 + dA2, ApL + kc + 8);
        const size_t boff = BT ? (size_t)kc : (size_t)kc * ldb;
        cpasync16(st + 16384 + dB, BpH + boff);        cpasync16(st + 16384 + dB2, BpH + boff + 8);
        cpasync16(st + 16384 + BSZ + dB, BpL + boff);  cpasync16(st + 16384 + BSZ + dB2, BpL + boff + 8);
        cpcommit();
    };

    const int lane = tid & 31, w = tid >> 5;
    const int mw = w >> 2, nw = w & 3;
    const int g = lane >> 2, tig = lane & 3;
    const int lrow = (lane & 7) + ((lane >> 3) & 1) * 8;
    const int lkh  = (lane >> 4) * 16;
    const int trow = (lane & 7) + ((lane >> 4) & 1) * 8;
    const int tnh  = ((lane >> 3) & 1) * 16;

    float acc[4][4][4];
#pragma unroll
    for (int mi = 0; mi < 4; mi++)
#pragma unroll
        for (int ni = 0; ni < 4; ni++)
#pragma unroll
            for (int e = 0; e < 4; e++) acc[mi][ni][e] = 0.f;

    auto compute = [&](int c) {
        const uint32_t st = sb + (c & 1) * STG;
#pragma unroll
        for (int ks = 0; ks < 2; ks++) {
            unsigned ah[4][4], al[4][4];
#pragma unroll
            for (int mi = 0; mi < 4; mi++) {
                const int r = mw * 64 + mi * 16 + lrow;
                const unsigned off = SWZ(r * 64 + ks * 32 + lkh);
                LDSM4(ah[mi], st + off);
                LDSM4(al[mi], st + 8192 + off);
            }
#pragma unroll
            for (int nb = 0; nb < 2; nb++) {
                unsigned bh[4], bl[4];
                if (BT) {
                    const int n = nw * 32 + nb * 16 + lrow;
                    const unsigned off = SWZ(n * 64 + ks * 32 + lkh);
                    LDSM4(bh, st + 16384 + off);
                    LDSM4(bl, st + 16384 + BSZ + off);
                } else {
                    const int kr = ks * 16 + trow;
                    const unsigned off = SWZ(kr * BSTRIDE0 + (nw * 32 + nb * 16) * 2 + tnh);
                    LDSM4T(bh, st + 16384 + off);
                    LDSM4T(bl, st + 16384 + BSZ + off);
                }
                unsigned beh[2] = {bh[0], bh[2]}, boh[2] = {bh[1], bh[3]};
                unsigned bel[2] = {bl[0], bl[2]}, bol[2] = {bl[1], bl[3]};
#pragma unroll
                for (int mi = 0; mi < 4; mi++) {
                    mma16816(acc[mi][2 * nb],     ah[mi], beh);
                    mma16816(acc[mi][2 * nb],     ah[mi], bel);
                    mma16816(acc[mi][2 * nb],     al[mi], beh);
                    mma16816(acc[mi][2 * nb + 1], ah[mi], boh);
                    mma16816(acc[mi][2 * nb + 1], ah[mi], bol);
                    mma16816(acc[mi][2 * nb + 1], al[mi], boh);
                }
            }
        }
    };

    issue(0);
    for (int c = 0; c < nch; c++) {
        if (c + 1 < nch) { issue(c + 1); cpwait1(); } else { cpwait0(); }
        __syncthreads();
        compute(c);
        __syncthreads();
    }

    float* outp = outf + (size_t)blockIdx.z * zstride;
    float srow0[4] = {0.f, 0.f, 0.f, 0.f}, srow1[4] = {0.f, 0.f, 0.f, 0.f};
#pragma unroll
    for (int mi = 0; mi < 4; mi++) {
        const int r = row0 + mw * 64 + mi * 16 + g;
#pragma unroll
        for (int ni = 0; ni < 4; ni++) {
            const int colG = col0 + nw * 32 + ni * 8 + 2 * tig;
            float v0 = acc[mi][ni][0], v1 = acc[mi][ni][1];
            float v2 = acc[mi][ni][2], v3 = acc[mi][ni][3];
            if (EPI & EPI_BIAS) {
                float2 bb = *(const float2*)(bias + colG);
                v0 += bb.x; v1 += bb.y; v2 += bb.x; v3 += bb.y;
            }
            if (EPI & EPI_GELU) {
                v0 = geluf(v0); v1 = geluf(v1); v2 = geluf(v2); v3 = geluf(v3);
            }
            if (EPI & EPI_RESIDP) {
                unsigned uh0 = *(const unsigned*)(resH + (size_t)r * 256 + colG);
                unsigned ul0 = *(const unsigned*)(resL + (size_t)r * 256 + colG);
                unsigned uh1 = *(const unsigned*)(resH + (size_t)(r + 8) * 256 + colG);
                unsigned ul1 = *(const unsigned*)(resL + (size_t)(r + 8) * 256 + colG);
                v0 += upk_lo(uh0) + upk_lo(ul0); v1 += upk_hi(uh0) + upk_hi(ul0);
                v2 += upk_lo(uh1) + upk_lo(ul1); v3 += upk_hi(uh1) + upk_hi(ul1);
            }
            if (EPI & EPI_CSCALE) {
                float2 cs = *(const float2*)(cscale + colG);
                v0 *= cs.x; v1 *= cs.y; v2 *= cs.x; v3 *= cs.y;
            }
            if (EPI & EPI_OUTF32) {
                *(float2*)(outp + (size_t)r * ldout + colG)       = make_float2(v0, v1);
                *(float2*)(outp + (size_t)(r + 8) * ldout + colG) = make_float2(v2, v3);
            }
            if (EPI & EPI_SSQ) {
                srow0[mi] += v0 * v0 + v1 * v1;
                srow1[mi] += v2 * v2 + v3 * v3;
            }
            float p0 = v0, p1 = v1, p2 = v2, p3 = v3;
            if (EPI & EPI_EXPPAIR) {
                p0 = __expf(v0); p1 = __expf(v1); p2 = __expf(v2); p3 = __expf(v3);
                if (EPI & EPI_SPART) { srow0[mi] += p0 + p1; srow1[mi] += p2 + p3; }
            }
            if (EPI & (EPI_OUTPAIR | EPI_EXPPAIR)) {
                __nv_bfloat16 h0, l0, h1, l1;
                split2(p0, h0, l0); split2(p1, h1, l1);
                *(unsigned*)(oh + (size_t)r * opitch + colG) = pack2(h0, h1);
                *(unsigned*)(ol + (size_t)r * opitch + colG) = pack2(l0, l1);
                split2(p2, h0, l0); split2(p3, h1, l1);
                *(unsigned*)(oh + (size_t)(r + 8) * opitch + colG) = pack2(h0, h1);
                *(unsigned*)(ol + (size_t)(r + 8) * opitch + colG) = pack2(l0, l1);
            }
        }
    }
    if (EPI & (EPI_SPART | EPI_SSQ)) {
        float (*spp)[128] = (float(*)[128])sp;
#pragma unroll
        for (int mi = 0; mi < 4; mi++) {
            float s0 = srow0[mi], s1 = srow1[mi];
            s0 += __shfl_xor_sync(0xffffffffu, s0, 1);
            s0 += __shfl_xor_sync(0xffffffffu, s0, 2);
            s1 += __shfl_xor_sync(0xffffffffu, s1, 1);
            s1 += __shfl_xor_sync(0xffffffffu, s1, 2);
            if (tig == 0) {
                spp[nw][mw * 64 + mi * 16 + g]     = s0;
                spp[nw][mw * 64 + mi * 16 + g + 8] = s1;
            }
        }
        __syncthreads();
        if (tid < 128)
            spart[(size_t)blockIdx.y * spitch + row0 + tid] =
                spp[0][tid] + spp[1][tid] + spp[2][tid] + spp[3][tid];
    }
}

// ---------------------------------------------------------------------------
// Legacy fp32-input GEMM (query/score path only). LN on A input only.
// ---------------------------------------------------------------------------
enum { AOP_ID = 0, AOP_LN = 1 };
#define LEPI_BIAS  1
#define LEPI_GELU  2
#define LEPI_RESID 4

template <int AOP, int EPI>
__global__ __launch_bounds__(256)
void tlegacy(const float* __restrict__ A, int lda,
             const float* __restrict__ B, int ldb,
             const float* __restrict__ bias,
             float* __restrict__ out, size_t ldout, int Kblk,
             const float* __restrict__ mean, const float* __restrict__ rstd,
             const float* __restrict__ lng, const float* __restrict__ lnb,
             const float* __restrict__ resid)
{
    __shared__ __align__(1024) unsigned char sm[16384 + 2 * 9216];
    const uint32_t sb = smem_u32(sm);
    const int tid = threadIdx.x;
    const int row0 = blockIdx.x * 128;
    const int col0 = blockIdx.y * 128;
    const int nch = Kblk >> 5;

    __shared__ float sgam[256], sbet[256];
    if (AOP == AOP_LN) {
        if (tid < Kblk) { sgam[tid] = lng[tid]; sbet[tid] = lnb[tid]; }
    }

    const int arow = tid >> 1, ak0 = (tid & 1) * 16;
    float mr = 0.f, rr = 0.f;
    if (AOP == AOP_LN) { mr = mean[row0 + arow]; rr = rstd[row0 + arow]; }
    const float* Ap = A + (size_t)(row0 + arow) * lda;
    const int bkr = tid >> 3, bn0 = (tid & 7) * 16;
    const float* Bp0 = B + (size_t)bkr * ldb + col0 + bn0;

    const int lane = tid & 31, w = tid >> 5;
    const int mw = w >> 2, nw = w & 3;
    const int g = lane >> 2, tig = lane & 3;
    const int lrow = (lane & 7) + ((lane >> 3) & 1) * 8;
    const int lkh = (lane >> 4) * 16;
    const int trow = (lane & 7) + ((lane >> 4) & 1) * 8;
    const int tnh = ((lane >> 3) & 1) * 16;

    float acc[4][4][4];
#pragma unroll
    for (int mi = 0; mi < 4; mi++)
#pragma unroll
        for (int ni = 0; ni < 4; ni++)
#pragma unroll
            for (int e = 0; e < 4; e++) acc[mi][ni][e] = 0.f;

    for (int c = 0; c < nch; c++) {
        const int kc = c * 32;
        __syncthreads();
#pragma unroll
        for (int i = 0; i < 4; i++) {
            float4 t = *(const float4*)(Ap + kc + ak0 + i * 4);
            float v[4] = {t.x, t.y, t.z, t.w};
            if (AOP == AOP_LN) {
#pragma unroll
                for (int j = 0; j < 4; j++) {
                    const int kg = kc + ak0 + i * 4 + j;
                    v[j] = (v[j] - mr) * rr * sgam[kg] + sbet[kg];
                }
            }
            const unsigned base = arow * 64 + (ak0 + i * 4) * 2;
            __nv_bfloat16 h0, l0, h1, l1;
            split2(v[0], h0, l0); split2(v[1], h1, l1);
            *(unsigned*)(sm + SWZ(base)) = pack2(h0, h1);
            *(unsigned*)(sm + 8192 + SWZ(base)) = pack2(l0, l1);
            split2(v[2], h0, l0); split2(v[3], h1, l1);
            *(unsigned*)(sm + SWZ(base + 4)) = pack2(h0, h1);
            *(unsigned*)(sm + 8192 + SWZ(base + 4)) = pack2(l0, l1);
        }
#pragma unroll
        for (int i = 0; i < 4; i++) {
            float4 t = *(const float4*)(Bp0 + (size_t)kc * ldb + i * 4);
            float v[4] = {t.x, t.y, t.z, t.w};
            const unsigned base = bkr * BSTRIDE0 + (bn0 + i * 4) * 2;
            __nv_bfloat16 h0, l0, h1, l1;
            split2(v[0], h0, l0); split2(v[1], h1, l1);
            *(unsigned*)(sm + 16384 + SWZ(base)) = pack2(h0, h1);
            *(unsigned*)(sm + 16384 + 9216 + SWZ(base)) = pack2(l0, l1);
            split2(v[2], h0, l0); split2(v[3], h1, l1);
            *(unsigned*)(sm + 16384 + SWZ(base + 4)) = pack2(h0, h1);
            *(unsigned*)(sm + 16384 + 9216 + SWZ(base + 4)) = pack2(l0, l1);
        }
        __syncthreads();
#pragma unroll
        for (int ks = 0; ks < 2; ks++) {
            unsigned ah[4][4], al[4][4];
#pragma unroll
            for (int mi = 0; mi < 4; mi++) {
                const int r = mw * 64 + mi * 16 + lrow;
                const unsigned off = SWZ(r * 64 + ks * 32 + lkh);
                LDSM4(ah[mi], sb + off);
                LDSM4(al[mi], sb + 8192 + off);
            }
#pragma unroll
            for (int nb = 0; nb < 2; nb++) {
                unsigned bh[4], bl[4];
                const int kr = ks * 16 + trow;
                const unsigned off = SWZ(kr * BSTRIDE0 + (nw * 32 + nb * 16) * 2 + tnh);
                LDSM4T(bh, sb + 16384 + off);
                LDSM4T(bl, sb + 16384 + 9216 + off);
                unsigned beh[2] = {bh[0], bh[2]}, boh[2] = {bh[1], bh[3]};
                unsigned bel[2] = {bl[0], bl[2]}, bol[2] = {bl[1], bl[3]};
#pragma unroll
                for (int mi = 0; mi < 4; mi++) {
                    mma16816(acc[mi][2 * nb],     ah[mi], beh);
                    mma16816(acc[mi][2 * nb],     ah[mi], bel);
                    mma16816(acc[mi][2 * nb],     al[mi], beh);
                    mma16816(acc[mi][2 * nb + 1], ah[mi], boh);
                    mma16816(acc[mi][2 * nb + 1], ah[mi], bol);
                    mma16816(acc[mi][2 * nb + 1], al[mi], boh);
                }
            }
        }
    }

#pragma unroll
    for (int mi = 0; mi < 4; mi++) {
        const int r = row0 + mw * 64 + mi * 16 + g;
#pragma unroll
        for (int ni = 0; ni < 4; ni++) {
            const int colG = col0 + nw * 32 + ni * 8 + 2 * tig;
            float v0 = acc[mi][ni][0], v1 = acc[mi][ni][1];
            float v2 = acc[mi][ni][2], v3 = acc[mi][ni][3];
            if (EPI & LEPI_BIAS) {
                float2 bb = *(const float2*)(bias + colG);
                v0 += bb.x; v1 += bb.y; v2 += bb.x; v3 += bb.y;
            }
            if (EPI & LEPI_GELU) {
                v0 = geluf(v0); v1 = geluf(v1); v2 = geluf(v2); v3 = geluf(v3);
            }
            if (EPI & LEPI_RESID) {
                float2 ra = *(const float2*)(resid + (size_t)r * 256 + colG);
                float2 rb = *(const float2*)(resid + (size_t)(r + 8) * 256 + colG);
                v0 += ra.x; v1 += ra.y; v2 += rb.x; v3 += rb.y;
            }
            *(float2*)(out + (size_t)r * ldout + colG)       = make_float2(v0, v1);
            *(float2*)(out + (size_t)(r + 8) * ldout + colG) = make_float2(v2, v3);
        }
    }
}

// ---------------- prep kernels ----------------------------------------------
__global__ void prep_pf(const float* __restrict__ pf,
                        __nv_bfloat16* __restrict__ H, __nv_bfloat16* __restrict__ L, int N)
{
    int idx = blockIdx.x * 256 + threadIdx.x;
    int row = idx / 12, c8 = (idx % 12) * 8;
    if (row >= N) return;
    __nv_bfloat16 h[8], l[8];
#pragma unroll
    for (int j = 0; j < 8; j++) {
        int k = c8 + j;
        float v = (k < 72) ? pf[(size_t)row * 72 + k] : 0.f;
        split2(v, h[j], l[j]);
    }
    *(uint4*)(H + (size_t)row * 96 + c8) = *(uint4*)h;
    *(uint4*)(L + (size_t)row * 96 + c8) = *(uint4*)l;
}

// weight [realrows][256] -> pair image [rows][256] ([k][n], BT0)
__global__ void prep_w(const float* __restrict__ W,
                       __nv_bfloat16* __restrict__ H, __nv_bfloat16* __restrict__ L,
                       int rows, int realrows)
{
    int idx = blockIdx.x * 256 + threadIdx.x;
    int row = idx / 32, c8 = (idx % 32) * 8;
    if (row >= rows) return;
    __nv_bfloat16 h[8], l[8];
#pragma unroll
    for (int j = 0; j < 8; j++) {
        float v = (row < realrows) ? W[(size_t)row * 256 + c8 + j] : 0.f;
        split2(v, h[j], l[j]);
    }
    *(uint4*)(H + (size_t)row * 256 + c8) = *(uint4*)h;
    *(uint4*)(L + (size_t)row * 256 + c8) = *(uint4*)l;
}

// weight W[k][256] -> TRANSPOSED pair image [n=256][kpad] (BT1, GEMM1 only)
__global__ void prep_wT(const float* __restrict__ W,
                        __nv_bfloat16* __restrict__ H, __nv_bfloat16* __restrict__ L,
                        int kpad, int realk)
{
    int idx = blockIdx.x * 256 + threadIdx.x;
    int n = idx / (kpad / 8), c8 = (idx % (kpad / 8)) * 8;
    if (n >= 256) return;
    __nv_bfloat16 h[8], l[8];
#pragma unroll
    for (int j = 0; j < 8; j++) {
        int k = c8 + j;
        float v = (k < realk) ? W[(size_t)k * 256 + n] : 0.f;
        split2(v, h[j], l[j]);
    }
    *(uint4*)(H + (size_t)n * kpad + c8) = *(uint4*)h;
    *(uint4*)(L + (size_t)n * kpad + c8) = *(uint4*)l;
}

// fused LN over pair image rows (apply-only LN #2 path)
template <bool GELU>
__global__ __launch_bounds__(256)
void lnprep(const __nv_bfloat16* __restrict__ inH, const __nv_bfloat16* __restrict__ inL,
            const float* __restrict__ gam, const float* __restrict__ bet,
            __nv_bfloat16* __restrict__ outH, __nv_bfloat16* __restrict__ outL, int M)
{
    const int wid = threadIdx.x >> 5, lane = threadIdx.x & 31;
    const int row = blockIdx.x * 8 + wid;
    if (row >= M) return;
    const int c8 = lane * 8;
    uint4 uh = *(const uint4*)(inH + (size_t)row * 256 + c8);
    uint4 ul = *(const uint4*)(inL + (size_t)row * 256 + c8);
    const __nv_bfloat16* ph = (const __nv_bfloat16*)&uh;
    const __nv_bfloat16* pl = (const __nv_bfloat16*)&ul;
    float v[8];
    float s = 0.f, ss = 0.f;
#pragma unroll
    for (int j = 0; j < 8; j++) {
        v[j] = __bfloat162float(ph[j]) + __bfloat162float(pl[j]);
        s += v[j]; ss += v[j] * v[j];
    }
#pragma unroll
    for (int o = 16; o; o >>= 1) {
        s  += __shfl_xor_sync(0xffffffffu, s, o);
        ss += __shfl_xor_sync(0xffffffffu, ss, o);
    }
    const float m = s * (1.0f / 256.0f);
    const float r = rsqrtf(ss * (1.0f / 256.0f) - m * m + 1e-5f);
    float4 g0 = *(const float4*)(gam + c8), g1 = *(const float4*)(gam + c8 + 4);
    float4 b0 = *(const float4*)(bet + c8), b1 = *(const float4*)(bet + c8 + 4);
    float gg[8] = {g0.x, g0.y, g0.z, g0.w, g1.x, g1.y, g1.z, g1.w};
    float bb[8] = {b0.x, b0.y, b0.z, b0.w, b1.x, b1.y, b1.z, b1.w};
    __nv_bfloat16 oh[8], ol[8];
#pragma unroll
    for (int j = 0; j < 8; j++) {
        float x = (v[j] - m) * r * gg[j] + bb[j];
        if (GELU) x = geluf(x);
        split2(x, oh[j], ol[j]);
    }
    *(uint4*)(outH + (size_t)row * 256 + c8) = *(uint4*)oh;
    *(uint4*)(outL + (size_t)row * 256 + c8) = *(uint4*)ol;
}

// ---------------- misc small kernels ----------------------------------------
__global__ __launch_bounds__(256)
void ln_stats(const float* __restrict__ X, float* __restrict__ mean,
              float* __restrict__ rstd, int M)
{
    int warp = (blockIdx.x * blockDim.x + threadIdx.x) >> 5;
    if (warp >= M) return;
    int lane = threadIdx.x & 31;
    const float* row = X + (size_t)warp * 256;
    float s = 0.f, ss = 0.f;
#pragma unroll
    for (int j = 0; j < 8; j++) { float v = row[lane + 32 * j]; s += v; ss += v * v; }
#pragma unroll
    for (int o = 16; o; o >>= 1) {
        s  += __shfl_xor_sync(0xffffffffu, s, o);
        ss += __shfl_xor_sync(0xffffffffu, ss, o);
    }
    if (lane == 0) {
        float m = s * (1.0f / 256.0f);
        mean[warp] = m;
        rstd[warp] = rsqrtf(ss * (1.0f / 256.0f) - m * m + 1e-5f);
    }
}

__global__ __launch_bounds__(256)
void rownorm(const float* __restrict__ X, float* __restrict__ inv, int M)
{
    int warp = (blockIdx.x * blockDim.x + threadIdx.x) >> 5;
    if (warp >= M) return;
    int lane = threadIdx.x & 31;
    const float* row = X + (size_t)warp * 256;
    float ss = 0.f;
#pragma unroll
    for (int j = 0; j < 8; j++) { float v = row[lane + 32 * j]; ss += v * v; }
#pragma unroll
    for (int o = 16; o; o >>= 1) ss += __shfl_xor_sync(0xffffffffu, ss, o);
    if (lane == 0) inv[warp] = 1.0f / fmaxf(sqrtf(ss), 1e-12f);
}

__global__ void combine_ssq(const float* __restrict__ ssqp, float* __restrict__ inv, int N)
{
    int i = blockIdx.x * 256 + threadIdx.x;
    if (i < N) inv[i] = 1.0f / fmaxf(sqrtf(ssqp[i] + ssqp[(size_t)N + i]), 1e-12f);
}

__global__ void qmpair(const float* __restrict__ qe, const float* __restrict__ invq,
                       const float* __restrict__ lsc,
                       __nv_bfloat16* __restrict__ H, __nv_bfloat16* __restrict__ L)
{
    int idx = blockIdx.x * 256 + threadIdx.x;
    int r = idx >> 8;
    float v = qe[idx] * invq[r] * expf(lsc[0]);
    __nv_bfloat16 h, l;
    split2(v, h, l);
    H[idx] = h; L[idx] = l;
}

__global__ __launch_bounds__(256)
void reduce_refined(const float* __restrict__ Ppart, const float* __restrict__ spart,
                    const float* __restrict__ qe, float* __restrict__ refined,
                    int CH, int NB)
{
    const int q = blockIdx.x;
    const int d = threadIdx.x;
    __shared__ float sh[256];
    float s = 0.f;
    for (int i = d; i < NB; i += 256) s += spart[(size_t)i * 128 + q];
    sh[d] = s;
    __syncthreads();
    for (int o = 128; o; o >>= 1) {
        if (d < o) sh[d] += sh[d + o];
        __syncthreads();
    }
    const float stot = sh[0];
    float p = 0.f;
    for (int c = 0; c < CH; c++) p += Ppart[((size_t)c * 128 + q) * 256 + d];
    refined[(size_t)q * 256 + d] = qe[(size_t)q * 256 + d] + p / stot;
}

__global__ __launch_bounds__(256)
void score_kernel(const float* __restrict__ A2s, const float* __restrict__ w2,
                  const float* __restrict__ b2, float* __restrict__ out)
{
    const int q = blockIdx.x;
    const int d = threadIdx.x;
    __shared__ float sh[256];
    sh[d] = A2s[(size_t)q * 256 + d] * w2[d];
    __syncthreads();
    for (int o = 128; o; o >>= 1) {
        if (d < o) sh[d] += sh[d + o];
        __syncthreads();
    }
    if (d == 0) out[q] = sh[0] + b2[0];
}

// ---------------------------------------------------------------------------
extern "C" void kernel_launch(void* const* d_in, const int* in_sizes, int n_in,
                              void* d_out, int out_size)
{
    const float* point_feat = (const float*)d_in[0];
    const float* ip_w1 = (const float*)d_in[1];
    const float* ip_b1 = (const float*)d_in[2];
    const float* ip_ln_g = (const float*)d_in[3];
    const float* ip_ln_b = (const float*)d_in[4];
    const float* ip_w2 = (const float*)d_in[5];
    const float* ip_b2 = (const float*)d_in[6];
    const float* ph_ln_g = (const float*)d_in[7];
    const float* ph_ln_b = (const float*)d_in[8];
    const float* ph_w1 = (const float*)d_in[9];
    const float* ph_b1 = (const float*)d_in[10];
    const float* ph_w2 = (const float*)d_in[11];
    const float* ph_b2 = (const float*)d_in[12];
    const float* q_embed = (const float*)d_in[13];
    const float* qh_ln_g = (const float*)d_in[14];
    const float* qh_ln_b = (const float*)d_in[15];
    const float* qh_w1 = (const float*)d_in[16];
    const float* qh_b1 = (const float*)d_in[17];
    const float* qh_w2 = (const float*)d_in[18];
    const float* qh_b2 = (const float*)d_in[19];
    const float* sh_ln_g = (const float*)d_in[20];
    const float* sh_ln_b = (const float*)d_in[21];
    const float* sh_w1 = (const float*)d_in[22];
    const float* sh_b1 = (const float*)d_in[23];
    const float* sh_w2 = (const float*)d_in[24];
    const float* sh_b2 = (const float*)d_in[25];
    const float* logit_scale = (const float*)d_in[26];

    const int N = in_sizes[0] / 72;

    float* out = (float*)d_out;
    const size_t offScore = (size_t)128 * N;
    const size_t offPE = offScore + 128;
    const size_t offRef = offPE + (size_t)N * 256;
    float* mask = out;
    float* score = out + offScore;
    float* pe = out + offPE;
    float* refined = out + offRef;

    __nv_bfloat16 *pfH, *pfL, *xH, *xL, *aH, *aL, *hH, *hL, *peH, *peL, *emH, *emL;
    __nv_bfloat16 *w1H, *w1L, *w2H, *w2L, *w3H, *w3L, *w4H, *w4L, *qmH, *qmL;
    float *invpe, *meanQ, *rstdQ, *A2q, *qe, *invq, *spart, *Ppart;
    cudaGetSymbolAddress((void**)&pfH, g_pfH); cudaGetSymbolAddress((void**)&pfL, g_pfL);
    cudaGetSymbolAddress((void**)&xH, g_xH);   cudaGetSymbolAddress((void**)&xL, g_xL);
    cudaGetSymbolAddress((void**)&aH, g_aH);   cudaGetSymbolAddress((void**)&aL, g_aL);
    cudaGetSymbolAddress((void**)&hH, g_hH);   cudaGetSymbolAddress((void**)&hL, g_hL);
    cudaGetSymbolAddress((void**)&peH, g_peH); cudaGetSymbolAddress((void**)&peL, g_peL);
    cudaGetSymbolAddress((void**)&emH, g_emH); cudaGetSymbolAddress((void**)&emL, g_emL);
    cudaGetSymbolAddress((void**)&w1H, g_w1H); cudaGetSymbolAddress((void**)&w1L, g_w1L);
    cudaGetSymbolAddress((void**)&w2H, g_w2H); cudaGetSymbolAddress((void**)&w2L, g_w2L);
    cudaGetSymbolAddress((void**)&w3H, g_w3H); cudaGetSymbolAddress((void**)&w3L, g_w3L);
    cudaGetSymbolAddress((void**)&w4H, g_w4H); cudaGetSymbolAddress((void**)&w4L, g_w4L);
    cudaGetSymbolAddress((void**)&qmH, g_qmH); cudaGetSymbolAddress((void**)&qmL, g_qmL);
    cudaGetSymbolAddress((void**)&invpe, g_invpe);
    cudaGetSymbolAddress((void**)&meanQ, g_meanQ); cudaGetSymbolAddress((void**)&rstdQ, g_rstdQ);
    cudaGetSymbolAddress((void**)&A2q, g_A2q); cudaGetSymbolAddress((void**)&qe, g_qe);
    cudaGetSymbolAddress((void**)&invq, g_invq);
    cudaGetSymbolAddress((void**)&spart, g_spart); cudaGetSymbolAddress((void**)&Ppart, g_Ppart);

    // dynamic smem opt-in (R9 2-stage sizes + tpair256)
    const int SMEM_BT0 = 2 * (16384 + 2 * 9216) + 2048;   // 71680
    const int SMEM_BT1 = 2 * (16384 + 2 * 8192) + 2048;   // 67584
    cudaFuncSetAttribute(tpair256<EPI_BIAS | EPI_LNPAIR | EPI_LNGELU>,
                         cudaFuncAttributeMaxDynamicSharedMemorySize, SMEM256);
    cudaFuncSetAttribute(tpair<EPI_BIAS | EPI_OUTPAIR, 0>,
                         cudaFuncAttributeMaxDynamicSharedMemorySize, SMEM_BT0);
    cudaFuncSetAttribute(tpair<EPI_BIAS | EPI_GELU | EPI_OUTPAIR, 0>,
                         cudaFuncAttributeMaxDynamicSharedMemorySize, SMEM_BT0);
    cudaFuncSetAttribute(tpair<EPI_BIAS | EPI_RESIDP | EPI_OUTF32 | EPI_OUTPAIR | EPI_SSQ, 0>,
                         cudaFuncAttributeMaxDynamicSharedMemorySize, SMEM_BT0);
    cudaFuncSetAttribute(tpair<EPI_CSCALE | EPI_OUTF32 | EPI_EXPPAIR | EPI_SPART, 1>,
                         cudaFuncAttributeMaxDynamicSharedMemorySize, SMEM_BT1);
    cudaFuncSetAttribute(tpair<EPI_OUTF32, 0>,
                         cudaFuncAttributeMaxDynamicSharedMemorySize, SMEM_BT0);

    // -------- preps --------
    prep_pf<<<(N * 12 + 255) / 256, 256>>>(point_feat, pfH, pfL, N);
    prep_wT<<<12, 256>>>(ip_w1, w1H, w1L, 96, 72);       // [n][k] for tpair256
    prep_w<<<32, 256>>>(ip_w2, w2H, w2L, 256, 256);
    prep_w<<<32, 256>>>(ph_w1, w3H, w3L, 256, 256);
    prep_w<<<32, 256>>>(ph_w2, w4H, w4L, 256, 256);

    const dim3 gBig(N / 128, 2);

    // -------- point pipeline --------
    // a = gelu(LN(pf @ ip_w1 + ip_b1))  -- fused (R10-verified path), kills
    // lnprep#1 and the x-pair round trip.
    tpair256<EPI_BIAS | EPI_LNPAIR | EPI_LNGELU><<<N / 128, 512, SMEM256>>>(
        pfH, pfL, 96, w1H, w1L, 96, ip_b1,
        nullptr, 0, nullptr, nullptr, aH, aL,
        nullptr, nullptr, ip_ln_g, ip_ln_b, nullptr, 96);
    // h = a @ ip_w2 + ip_b2 (pairs)
    tpair<EPI_BIAS | EPI_OUTPAIR, 0><<<gBig, 256, SMEM_BT0>>>(
        aH, aL, 256, w2H, w2L, 256, ip_b2,
        nullptr, 0, 0, hH, hL, 256, nullptr, nullptr, nullptr, nullptr, 0, 256);
    // a = LN(h) (pairs)
    lnprep<false><<<N / 8, 256>>>(hH, hL, ph_ln_g, ph_ln_b, aH, aL, N);
    // x = gelu(a @ ph_w1 + ph_b1) (pairs)
    tpair<EPI_BIAS | EPI_GELU | EPI_OUTPAIR, 0><<<gBig, 256, SMEM_BT0>>>(
        aH, aL, 256, w3H, w3L, 256, ph_b1,
        nullptr, 0, 0, xH, xL, 256, nullptr, nullptr, nullptr, nullptr, 0, 256);
    // pe = h + x @ ph_w2 + ph_b2 (fp32 to d_out + pairs + fused row-SSQ)
    tpair<EPI_BIAS | EPI_RESIDP | EPI_OUTF32 | EPI_OUTPAIR | EPI_SSQ, 0><<<gBig, 256, SMEM_BT0>>>(
        xH, xL, 256, w4H, w4L, 256, ph_b2,
        pe, 256, 0, peH, peL, 256, hH, hL, nullptr, spart, (size_t)N, 256);
    combine_ssq<<<(N + 255) / 256, 256>>>(spart, invpe, N);

    // -------- query pipeline (legacy, tiny) --------
    ln_stats<<<16, 256>>>(q_embed, meanQ, rstdQ, 128);
    tlegacy<AOP_LN, LEPI_BIAS | LEPI_GELU><<<dim3(1, 2), 256>>>(
        q_embed, 256, qh_w1, 256, qh_b1, A2q, 256, 256,
        meanQ, rstdQ, qh_ln_g, qh_ln_b, nullptr);
    tlegacy<AOP_ID, LEPI_BIAS | LEPI_RESID><<<dim3(1, 2), 256>>>(
        A2q, 256, qh_w2, 256, qh_b2, qe, 256, 256,
        nullptr, nullptr, nullptr, nullptr, q_embed);
    rownorm<<<16, 256>>>(qe, invq, 128);
    qmpair<<<128, 256>>>(qe, invq, logit_scale, qmH, qmL);

    // -------- mask logits + exp pairs + softmax partial sums --------
    tpair<EPI_CSCALE | EPI_OUTF32 | EPI_EXPPAIR | EPI_SPART, 1><<<dim3(1, N / 128), 256, SMEM_BT1>>>(
        qmH, qmL, 256, peH, peL, 256, nullptr,
        mask, (size_t)N, 0, emH, emL, (size_t)N, nullptr, nullptr, invpe, spart, 128, 256);

    // -------- weighted aggregation: Ppart[z] = em chunk @ pe chunk ----------
    tpair<EPI_OUTF32, 0><<<dim3(1, 2, 256), 256, SMEM_BT0>>>(
        emH, emL, N, peH, peL, 256, nullptr,
        Ppart, 256, (size_t)128 * 256, nullptr, nullptr, 0,
        nullptr, nullptr, nullptr, nullptr, 0, 1024);
    reduce_refined<<<128, 256>>>(Ppart, spart, qe, refined, 256, N / 128);

    // -------- score head (legacy) --------
    ln_stats<<<16, 256>>>(refined, meanQ, rstdQ, 128);
    tlegacy<AOP_LN, LEPI_BIAS | LEPI_GELU><<<dim3(1, 2), 256>>>(
        refined, 256, sh_w1, 256, sh_b1, A2q, 256, 256,
        meanQ, rstdQ, sh_ln_g, sh_ln_b, nullptr);
    score_kernel<<<128, 256>>>(A2q, sh_w2, sh_b2, score);
}

// round 14
// speedup vs baseline: 1.1089x; 1.0387x over previous
#include <cuda_runtime.h>
#include <cuda_bf16.h>
#include <math.h>
#include <stdint.h>

// ---------------------------------------------------------------------------
// QueryInstanceDecoder: bf16 split-precision mma.sync pipeline, v7.
// = R12 (best passing) + single-bf16 em image with CONSISTENT spart
//   (numerator/denominator use identical quantized softmax weights) and a
//   2-term aggregation GEMM (A-single): -1/3 agg MMAs, -134MB em traffic.
// N=262144, C_IN=72, D=256, Q=128.
// d_out (floats): mask_logits[128*N] | score[128] | point_embed[N*256] | refined[128*256]
// ---------------------------------------------------------------------------

#define DEVI __device__ __forceinline__

DEVI float geluf(float x) { return 0.5f * x * (1.0f + erff(x * 0.70710678118654752f)); }

DEVI unsigned pack2(__nv_bfloat16 a, __nv_bfloat16 b) {
    return (unsigned)__bfloat16_as_ushort(a) | ((unsigned)__bfloat16_as_ushort(b) << 16);
}
DEVI void split2(float x, __nv_bfloat16& h, __nv_bfloat16& l) {
    h = __float2bfloat16(x);
    l = __float2bfloat16(x - __bfloat162float(h));
}
DEVI float upk_lo(unsigned u) { return __bfloat162float(__ushort_as_bfloat16((unsigned short)(u & 0xffff))); }
DEVI float upk_hi(unsigned u) { return __bfloat162float(__ushort_as_bfloat16((unsigned short)(u >> 16))); }

DEVI void mma16816(float* c, const unsigned* a, const unsigned* b) {
    asm volatile(
        "mma.sync.aligned.m16n8k16.row.col.f32.bf16.bf16.f32 "
        "{%0,%1,%2,%3},{%4,%5,%6,%7},{%8,%9},{%0,%1,%2,%3};"
        : "+f"(c[0]), "+f"(c[1]), "+f"(c[2]), "+f"(c[3])
        : "r"(a[0]), "r"(a[1]), "r"(a[2]), "r"(a[3]), "r"(b[0]), "r"(b[1]));
}
DEVI uint32_t smem_u32(const void* p) {
    uint32_t a;
    asm("{ .reg .u64 t; cvta.to.shared.u64 t, %1; cvt.u32.u64 %0, t; }" : "=r"(a) : "l"(p));
    return a;
}
#define LDSM4(r, a) \
    asm volatile("ldmatrix.sync.aligned.m8n8.x4.shared.b16 {%0,%1,%2,%3},[%4];" \
        : "=r"((r)[0]), "=r"((r)[1]), "=r"((r)[2]), "=r"((r)[3]) : "r"(a))
#define LDSM4T(r, a) \
    asm volatile("ldmatrix.sync.aligned.m8n8.x4.trans.shared.b16 {%0,%1,%2,%3},[%4];" \
        : "=r"((r)[0]), "=r"((r)[1]), "=r"((r)[2]), "=r"((r)[3]) : "r"(a))

DEVI void cpasync16(uint32_t dst, const void* src) {
    asm volatile("cp.async.cg.shared.global [%0], [%1], 16;" :: "r"(dst), "l"(src));
}
DEVI void cpcommit() { asm volatile("cp.async.commit_group;"); }
DEVI void cpwait1()  { asm volatile("cp.async.wait_group 1;"); }
DEVI void cpwait0()  { asm volatile("cp.async.wait_group 0;"); }

#define SWZ(o) ((unsigned)(o) ^ ((((unsigned)(o)) >> 3) & 0x70))
#define BSTRIDE0 288

// ---------------- scratch (static device memory; no allocations) -----------
#define NMAX 262144
__device__ __nv_bfloat16 g_pfH[(size_t)NMAX * 96], g_pfL[(size_t)NMAX * 96];
__device__ __nv_bfloat16 g_xH[(size_t)NMAX * 256], g_xL[(size_t)NMAX * 256];
__device__ __nv_bfloat16 g_aH[(size_t)NMAX * 256], g_aL[(size_t)NMAX * 256];
__device__ __nv_bfloat16 g_hH[(size_t)NMAX * 256], g_hL[(size_t)NMAX * 256];
__device__ __nv_bfloat16 g_peH[(size_t)NMAX * 256], g_peL[(size_t)NMAX * 256];
__device__ __nv_bfloat16 g_emH[(size_t)128 * NMAX];
__device__ __nv_bfloat16 g_w1H[96 * 256], g_w1L[96 * 256];     // [n=256][k=96] transposed
__device__ __nv_bfloat16 g_w2H[256 * 256], g_w2L[256 * 256];   // [k][n]
__device__ __nv_bfloat16 g_w3H[256 * 256], g_w3L[256 * 256];
__device__ __nv_bfloat16 g_w4H[256 * 256], g_w4L[256 * 256];
__device__ __nv_bfloat16 g_qmH[128 * 256], g_qmL[128 * 256];
__device__ float g_invpe[NMAX];
__device__ float g_meanQ[128], g_rstdQ[128];
__device__ float g_A2q[128 * 256];
__device__ float g_qe[128 * 256];
__device__ float g_invq[128];
__device__ float g_spart[(size_t)2 * NMAX];
__device__ float g_Ppart[256 * 128 * 256];

// ---------------- epilogue flags --------------------------------------------
#define EPI_BIAS    1
#define EPI_GELU    2
#define EPI_RESIDP  4
#define EPI_OUTF32  8
#define EPI_OUTPAIR 16
#define EPI_SPART   32
#define EPI_CSCALE  64
#define EPI_SSQ     256
#define EPI_LNPAIR  512
#define EPI_LNGELU  1024
#define EPI_EXP1    2048    // store bf16(exp(v)) single; spart from ROUNDED values

// =============================================================================
// tpair256 (verified): C[128x256] = A_pairs @ B_pairs^T (B image [n][k]).
// 512 threads, 16 warps (2x8), warp 64x32, 2-stage cp.async.
// Used ONLY for GEMM1 (K=96) with BIAS+LNPAIR+LNGELU fused epilogue.
// =============================================================================
#define STG256 49152
#define SP_OFF (2 * STG256)
#define SMEM256 (SP_OFF + 4096 + 4096 + 512 + 512 + 1024 + 1024)

template <int EPI>
__global__ __launch_bounds__(512, 1)
void tpair256(const __nv_bfloat16* __restrict__ Ah, const __nv_bfloat16* __restrict__ Al, int lda,
              const __nv_bfloat16* __restrict__ Bh, const __nv_bfloat16* __restrict__ Bl, int ldb,
              const float* __restrict__ bias,
              float* __restrict__ outf, size_t ldout,
              __nv_bfloat16* __restrict__ oh, __nv_bfloat16* __restrict__ ol,
              __nv_bfloat16* __restrict__ o2h, __nv_bfloat16* __restrict__ o2l,
              const __nv_bfloat16* __restrict__ resH, const __nv_bfloat16* __restrict__ resL,
              const float* __restrict__ gam, const float* __restrict__ bet,
              float* __restrict__ invout, int Kblk)
{
    extern __shared__ __align__(1024) unsigned char sm[];
    const uint32_t sb = smem_u32(sm);
    float* spS  = (float*)(sm + SP_OFF);
    float* spSS = (float*)(sm + SP_OFF + 4096);
    float* marr = (float*)(sm + SP_OFF + 8192);
    float* rarr = (float*)(sm + SP_OFF + 8704);
    float* sgam = (float*)(sm + SP_OFF + 9216);
    float* sbet = (float*)(sm + SP_OFF + 10240);

    const int tid  = threadIdx.x;
    const int row0 = blockIdx.x * 128;
    const int nch  = Kblk >> 5;

    if (EPI & EPI_LNPAIR) {
        if (tid < 256) { sgam[tid] = gam[tid]; sbet[tid] = bet[tid]; }
    }

    const int arow = tid >> 2, ak0 = (tid & 3) * 8;
    const int brow = tid >> 1, bk0 = (tid & 1) * 16;
    const unsigned dA  = SWZ(arow * 64 + ak0 * 2);
    const unsigned dB  = SWZ(brow * 64 + bk0 * 2);
    const unsigned dB2 = SWZ(brow * 64 + bk0 * 2 + 16);
    const __nv_bfloat16* ApH = Ah + (size_t)(row0 + arow) * lda + ak0;
    const __nv_bfloat16* ApL = Al + (size_t)(row0 + arow) * lda + ak0;
    const __nv_bfloat16* BpH = Bh + (size_t)brow * ldb + bk0;
    const __nv_bfloat16* BpL = Bl + (size_t)brow * ldb + bk0;

    auto issue = [&](int c) {
        const int kc = c * 32;
        const uint32_t st = sb + (c & 1) * STG256;
        cpasync16(st + dA, ApH + kc);
        cpasync16(st + 8192 + dA, ApL + kc);
        cpasync16(st + 16384 + dB,  BpH + kc);
        cpasync16(st + 16384 + dB2, BpH + kc + 8);
        cpasync16(st + 32768 + dB,  BpL + kc);
        cpasync16(st + 32768 + dB2, BpL + kc + 8);
        cpcommit();
    };

    const int lane = tid & 31, w = tid >> 5;
    const int mw = w >> 3, nw = w & 7;
    const int g = lane >> 2, tig = lane & 3;
    const int lrow = (lane & 7) + ((lane >> 3) & 1) * 8;
    const int lkh  = (lane >> 4) * 16;

    float acc[4][4][4];
#pragma unroll
    for (int mi = 0; mi < 4; mi++)
#pragma unroll
        for (int ni = 0; ni < 4; ni++)
#pragma unroll
            for (int e = 0; e < 4; e++) acc[mi][ni][e] = 0.f;

    auto compute = [&](int c) {
        const uint32_t st = sb + (c & 1) * STG256;
#pragma unroll
        for (int ks = 0; ks < 2; ks++) {
            unsigned ah[4][4], al[4][4];
#pragma unroll
            for (int mi = 0; mi < 4; mi++) {
                const int r = mw * 64 + mi * 16 + lrow;
                const unsigned off = SWZ(r * 64 + ks * 32 + lkh);
                LDSM4(ah[mi], st + off);
                LDSM4(al[mi], st + 8192 + off);
            }
#pragma unroll
            for (int nb = 0; nb < 2; nb++) {
                unsigned bh[4], bl[4];
                const int n = nw * 32 + nb * 16 + lrow;
                const unsigned off = SWZ(n * 64 + ks * 32 + lkh);
                LDSM4(bh, st + 16384 + off);
                LDSM4(bl, st + 32768 + off);
                unsigned beh[2] = {bh[0], bh[2]}, boh[2] = {bh[1], bh[3]};
                unsigned bel[2] = {bl[0], bl[2]}, bol[2] = {bl[1], bl[3]};
#pragma unroll
                for (int mi = 0; mi < 4; mi++) {
                    mma16816(acc[mi][2 * nb],     ah[mi], beh);
                    mma16816(acc[mi][2 * nb],     ah[mi], bel);
                    mma16816(acc[mi][2 * nb],     al[mi], beh);
                    mma16816(acc[mi][2 * nb + 1], ah[mi], boh);
                    mma16816(acc[mi][2 * nb + 1], ah[mi], bol);
                    mma16816(acc[mi][2 * nb + 1], al[mi], boh);
                }
            }
        }
    };

    issue(0);
    for (int c = 0; c < nch; c++) {
        if (c + 1 < nch) { issue(c + 1); cpwait1(); } else { cpwait0(); }
        __syncthreads();
        compute(c);
        __syncthreads();
    }

    // pass A: finalize, stats
    float sS0[4], sS1[4], sSS0[4], sSS1[4];
#pragma unroll
    for (int mi = 0; mi < 4; mi++) { sS0[mi] = sS1[mi] = sSS0[mi] = sSS1[mi] = 0.f; }

#pragma unroll
    for (int mi = 0; mi < 4; mi++) {
        const int r = row0 + mw * 64 + mi * 16 + g;
#pragma unroll
        for (int ni = 0; ni < 4; ni++) {
            const int colG = nw * 32 + ni * 8 + 2 * tig;
            float v0 = acc[mi][ni][0], v1 = acc[mi][ni][1];
            float v2 = acc[mi][ni][2], v3 = acc[mi][ni][3];
            if (EPI & EPI_BIAS) {
                float2 bb = *(const float2*)(bias + colG);
                v0 += bb.x; v1 += bb.y; v2 += bb.x; v3 += bb.y;
            }
            if (EPI & EPI_GELU) {
                v0 = geluf(v0); v1 = geluf(v1); v2 = geluf(v2); v3 = geluf(v3);
            }
            if (EPI & EPI_RESIDP) {
                unsigned uh0 = *(const unsigned*)(resH + (size_t)r * 256 + colG);
                unsigned ul0 = *(const unsigned*)(resL + (size_t)r * 256 + colG);
                unsigned uh1 = *(const unsigned*)(resH + (size_t)(r + 8) * 256 + colG);
                unsigned ul1 = *(const unsigned*)(resL + (size_t)(r + 8) * 256 + colG);
                v0 += upk_lo(uh0) + upk_lo(ul0); v1 += upk_hi(uh0) + upk_hi(ul0);
                v2 += upk_lo(uh1) + upk_lo(ul1); v3 += upk_hi(uh1) + upk_hi(ul1);
            }
            if (EPI & EPI_OUTF32) {
                *(float2*)(outf + (size_t)r * ldout + colG)       = make_float2(v0, v1);
                *(float2*)(outf + (size_t)(r + 8) * ldout + colG) = make_float2(v2, v3);
            }
            if (EPI & EPI_LNPAIR) { sS0[mi] += v0 + v1; sS1[mi] += v2 + v3; }
            if (EPI & (EPI_SSQ | EPI_LNPAIR)) {
                sSS0[mi] += v0 * v0 + v1 * v1;
                sSS1[mi] += v2 * v2 + v3 * v3;
            }
            acc[mi][ni][0] = v0; acc[mi][ni][1] = v1;
            acc[mi][ni][2] = v2; acc[mi][ni][3] = v3;
        }
    }

    if (EPI & (EPI_SSQ | EPI_LNPAIR)) {
#pragma unroll
        for (int mi = 0; mi < 4; mi++) {
            float a0 = sS0[mi], a1 = sS1[mi], b0 = sSS0[mi], b1 = sSS1[mi];
            a0 += __shfl_xor_sync(0xffffffffu, a0, 1); a0 += __shfl_xor_sync(0xffffffffu, a0, 2);
            a1 += __shfl_xor_sync(0xffffffffu, a1, 1); a1 += __shfl_xor_sync(0xffffffffu, a1, 2);
            b0 += __shfl_xor_sync(0xffffffffu, b0, 1); b0 += __shfl_xor_sync(0xffffffffu, b0, 2);
            b1 += __shfl_xor_sync(0xffffffffu, b1, 1); b1 += __shfl_xor_sync(0xffffffffu, b1, 2);
            if (tig == 0) {
                const int lr = mw * 64 + mi * 16 + g;
                spS[nw * 128 + lr]      = a0;
                spS[nw * 128 + lr + 8]  = a1;
                spSS[nw * 128 + lr]     = b0;
                spSS[nw * 128 + lr + 8] = b1;
            }
        }
        __syncthreads();
        if (tid < 128) {
            float s = 0.f, ss = 0.f;
#pragma unroll
            for (int ww = 0; ww < 8; ww++) {
                s  += spS[ww * 128 + tid];
                ss += spSS[ww * 128 + tid];
            }
            if (EPI & EPI_LNPAIR) {
                float m = s * (1.0f / 256.0f);
                marr[tid] = m;
                rarr[tid] = rsqrtf(ss * (1.0f / 256.0f) - m * m + 1e-5f);
            }
            if (EPI & EPI_SSQ)
                invout[row0 + tid] = 1.0f / fmaxf(sqrtf(ss), 1e-12f);
        }
        __syncthreads();
    }

    if (EPI & (EPI_OUTPAIR | EPI_LNPAIR)) {
#pragma unroll
        for (int mi = 0; mi < 4; mi++) {
            const int lr = mw * 64 + mi * 16 + g;
            const int r = row0 + lr;
            float m0 = 0.f, r0 = 0.f, m1 = 0.f, r1 = 0.f;
            if (EPI & EPI_LNPAIR) {
                m0 = marr[lr]; r0 = rarr[lr];
                m1 = marr[lr + 8]; r1 = rarr[lr + 8];
            }
#pragma unroll
            for (int ni = 0; ni < 4; ni++) {
                const int colG = nw * 32 + ni * 8 + 2 * tig;
                float v0 = acc[mi][ni][0], v1 = acc[mi][ni][1];
                float v2 = acc[mi][ni][2], v3 = acc[mi][ni][3];
                if (EPI & EPI_OUTPAIR) {
                    __nv_bfloat16 h0, l0, h1, l1;
                    split2(v0, h0, l0); split2(v1, h1, l1);
                    *(unsigned*)(oh + (size_t)r * 256 + colG) = pack2(h0, h1);
                    *(unsigned*)(ol + (size_t)r * 256 + colG) = pack2(l0, l1);
                    split2(v2, h0, l0); split2(v3, h1, l1);
                    *(unsigned*)(oh + (size_t)(r + 8) * 256 + colG) = pack2(h0, h1);
                    *(unsigned*)(ol + (size_t)(r + 8) * 256 + colG) = pack2(l0, l1);
                }
                if (EPI & EPI_LNPAIR) {
                    const float g0 = sgam[colG], g1 = sgam[colG + 1];
                    const float b0 = sbet[colG], b1 = sbet[colG + 1];
                    float t0 = (v0 - m0) * r0 * g0 + b0;
                    float t1 = (v1 - m0) * r0 * g1 + b1;
                    float t2 = (v2 - m1) * r1 * g0 + b0;
                    float t3 = (v3 - m1) * r1 * g1 + b1;
                    if (EPI & EPI_LNGELU) {
                        t0 = geluf(t0); t1 = geluf(t1); t2 = geluf(t2); t3 = geluf(t3);
                    }
                    __nv_bfloat16 h0, l0, h1, l1;
                    split2(t0, h0, l0); split2(t1, h1, l1);
                    *(unsigned*)(o2h + (size_t)r * 256 + colG) = pack2(h0, h1);
                    *(unsigned*)(o2l + (size_t)r * 256 + colG) = pack2(l0, l1);
                    split2(t2, h0, l0); split2(t3, h1, l1);
                    *(unsigned*)(o2h + (size_t)(r + 8) * 256 + colG) = pack2(h0, h1);
                    *(unsigned*)(o2l + (size_t)(r + 8) * 256 + colG) = pack2(l0, l1);
                }
            }
        }
    }
}

// =============================================================================
// R9 pair GEMM (2-stage, 2 CTAs/SM). New template param AS: A-single image
// (2-term split D = Ah*Bh + Ah*Bl) — used by the aggregation GEMM.
// =============================================================================
template <int EPI, int BT, int AS = 0>
__global__ __launch_bounds__(256, 2)
void tpair(const __nv_bfloat16* __restrict__ Ah, const __nv_bfloat16* __restrict__ Al, int lda,
           const __nv_bfloat16* __restrict__ Bh, const __nv_bfloat16* __restrict__ Bl, int ldb,
           const float* __restrict__ bias,
           float* __restrict__ outf, size_t ldout, size_t zstride,
           __nv_bfloat16* __restrict__ oh, __nv_bfloat16* __restrict__ ol, size_t opitch,
           const __nv_bfloat16* __restrict__ resH, const __nv_bfloat16* __restrict__ resL,
           const float* __restrict__ cscale, float* __restrict__ spart, size_t spitch,
           int Kblk)
{
    constexpr int BSZ = BT ? 8192 : 9216;
    constexpr int STG = 16384 + 2 * BSZ;
    extern __shared__ __align__(1024) unsigned char sm[];
    const uint32_t sb = smem_u32(sm);
    float* sp = (float*)(sm + 2 * STG);

    const int tid  = threadIdx.x;
    const int row0 = blockIdx.x * 128;
    const int col0 = blockIdx.y * 128;
    const int kz   = blockIdx.z * Kblk;
    const int nch  = Kblk >> 5;

    const int arow = tid >> 1, ak0 = (tid & 1) * 16;
    const int brow = tid >> 1, bk0 = (tid & 1) * 16;
    const int bkr = tid >> 3, bn0 = (tid & 7) * 16;
    const unsigned dA  = SWZ(arow * 64 + ak0 * 2);
    const unsigned dA2 = SWZ(arow * 64 + ak0 * 2 + 16);
    const unsigned dB  = BT ? SWZ(brow * 64 + bk0 * 2)      : SWZ(bkr * BSTRIDE0 + bn0 * 2);
    const unsigned dB2 = BT ? SWZ(brow * 64 + bk0 * 2 + 16) : SWZ(bkr * BSTRIDE0 + bn0 * 2 + 16);
    const __nv_bfloat16* ApH = Ah + (size_t)(row0 + arow) * lda + kz + ak0;
    const __nv_bfloat16* ApL = AS ? nullptr : Al + (size_t)(row0 + arow) * lda + kz + ak0;
    const __nv_bfloat16* BpH = BT ? Bh + (size_t)(col0 + brow) * ldb + kz + bk0
                                  : Bh + (size_t)(kz + bkr) * ldb + col0 + bn0;
    const __nv_bfloat16* BpL = BT ? Bl + (size_t)(col0 + brow) * ldb + kz + bk0
                                  : Bl + (size_t)(kz + bkr) * ldb + col0 + bn0;

    auto issue = [&](int c) {
        const int kc = c * 32;
        const uint32_t st = sb + (c & 1) * STG;
        cpasync16(st + dA, ApH + kc);            cpasync16(st + dA2, ApH + kc + 8);
        if (!AS) {
            cpasync16(st + 8192 + dA, ApL + kc);
            cpasync16(st + 8192 + dA2, ApL + kc + 8);
        }
        const size_t boff = BT ? (size_t)kc : (size_t)kc * ldb;
        cpasync16(st + 16384 + dB, BpH + boff);        cpasync16(st + 16384 + dB2, BpH + boff + 8);
        cpasync16(st + 16384 + BSZ + dB, BpL + boff);  cpasync16(st + 16384 + BSZ + dB2, BpL + boff + 8);
        cpcommit();
    };

    const int lane = tid & 31, w = tid >> 5;
    const int mw = w >> 2, nw = w & 3;
    const int g = lane >> 2, tig = lane & 3;
    const int lrow = (lane & 7) + ((lane >> 3) & 1) * 8;
    const int lkh  = (lane >> 4) * 16;
    const int trow = (lane & 7) + ((lane >> 4) & 1) * 8;
    const int tnh  = ((lane >> 3) & 1) * 16;

    float acc[4][4][4];
#pragma unroll
    for (int mi = 0; mi < 4; mi++)
#pragma unroll
        for (int ni = 0; ni < 4; ni++)
#pragma unroll
            for (int e = 0; e < 4; e++) acc[mi][ni][e] = 0.f;

    auto compute = [&](int c) {
        const uint32_t st = sb + (c & 1) * STG;
#pragma unroll
        for (int ks = 0; ks < 2; ks++) {
            unsigned ah[4][4], al[4][4];
#pragma unroll
            for (int mi = 0; mi < 4; mi++) {
                const int r = mw * 64 + mi * 16 + lrow;
                const unsigned off = SWZ(r * 64 + ks * 32 + lkh);
                LDSM4(ah[mi], st + off);
                if (!AS) LDSM4(al[mi], st + 8192 + off);
            }
#pragma unroll
            for (int nb = 0; nb < 2; nb++) {
                unsigned bh[4], bl[4];
                if (BT) {
                    const int n = nw * 32 + nb * 16 + lrow;
                    const unsigned off = SWZ(n * 64 + ks * 32 + lkh);
                    LDSM4(bh, st + 16384 + off);
                    LDSM4(bl, st + 16384 + BSZ + off);
                } else {
                    const int kr = ks * 16 + trow;
                    const unsigned off = SWZ(kr * BSTRIDE0 + (nw * 32 + nb * 16) * 2 + tnh);
                    LDSM4T(bh, st + 16384 + off);
                    LDSM4T(bl, st + 16384 + BSZ + off);
                }
                unsigned beh[2] = {bh[0], bh[2]}, boh[2] = {bh[1], bh[3]};
                unsigned bel[2] = {bl[0], bl[2]}, bol[2] = {bl[1], bl[3]};
#pragma unroll
                for (int mi = 0; mi < 4; mi++) {
                    mma16816(acc[mi][2 * nb],     ah[mi], beh);
                    mma16816(acc[mi][2 * nb],     ah[mi], bel);
                    if (!AS) mma16816(acc[mi][2 * nb], al[mi], beh);
                    mma16816(acc[mi][2 * nb + 1], ah[mi], boh);
                    mma16816(acc[mi][2 * nb + 1], ah[mi], bol);
                    if (!AS) mma16816(acc[mi][2 * nb + 1], al[mi], boh);
                }
            }
        }
    };

    issue(0);
    for (int c = 0; c < nch; c++) {
        if (c + 1 < nch) { issue(c + 1); cpwait1(); } else { cpwait0(); }
        __syncthreads();
        compute(c);
        __syncthreads();
    }

    float* outp = outf + (size_t)blockIdx.z * zstride;
    float srow0[4] = {0.f, 0.f, 0.f, 0.f}, srow1[4] = {0.f, 0.f, 0.f, 0.f};
#pragma unroll
    for (int mi = 0; mi < 4; mi++) {
        const int r = row0 + mw * 64 + mi * 16 + g;
#pragma unroll
        for (int ni = 0; ni < 4; ni++) {
            const int colG = col0 + nw * 32 + ni * 8 + 2 * tig;
            float v0 = acc[mi][ni][0], v1 = acc[mi][ni][1];
            float v2 = acc[mi][ni][2], v3 = acc[mi][ni][3];
            if (EPI & EPI_BIAS) {
                float2 bb = *(const float2*)(bias + colG);
                v0 += bb.x; v1 += bb.y; v2 += bb.x; v3 += bb.y;
            }
            if (EPI & EPI_GELU) {
                v0 = geluf(v0); v1 = geluf(v1); v2 = geluf(v2); v3 = geluf(v3);
            }
            if (EPI & EPI_RESIDP) {
                unsigned uh0 = *(const unsigned*)(resH + (size_t)r * 256 + colG);
                unsigned ul0 = *(const unsigned*)(resL + (size_t)r * 256 + colG);
                unsigned uh1 = *(const unsigned*)(resH + (size_t)(r + 8) * 256 + colG);
                unsigned ul1 = *(const unsigned*)(resL + (size_t)(r + 8) * 256 + colG);
                v0 += upk_lo(uh0) + upk_lo(ul0); v1 += upk_hi(uh0) + upk_hi(ul0);
                v2 += upk_lo(uh1) + upk_lo(ul1); v3 += upk_hi(uh1) + upk_hi(ul1);
            }
            if (EPI & EPI_CSCALE) {
                float2 cs = *(const float2*)(cscale + colG);
                v0 *= cs.x; v1 *= cs.y; v2 *= cs.x; v3 *= cs.y;
            }
            if (EPI & EPI_OUTF32) {
                *(float2*)(outp + (size_t)r * ldout + colG)       = make_float2(v0, v1);
                *(float2*)(outp + (size_t)(r + 8) * ldout + colG) = make_float2(v2, v3);
            }
            if (EPI & EPI_SSQ) {
                srow0[mi] += v0 * v0 + v1 * v1;
                srow1[mi] += v2 * v2 + v3 * v3;
            }
            if (EPI & EPI_EXP1) {
                // single-bf16 softmax weights; spart from ROUNDED values so
                // numerator (agg) and denominator (spart) stay consistent.
                __nv_bfloat16 h0 = __float2bfloat16(__expf(v0));
                __nv_bfloat16 h1 = __float2bfloat16(__expf(v1));
                __nv_bfloat16 h2 = __float2bfloat16(__expf(v2));
                __nv_bfloat16 h3 = __float2bfloat16(__expf(v3));
                if (EPI & EPI_SPART) {
                    srow0[mi] += __bfloat162float(h0) + __bfloat162float(h1);
                    srow1[mi] += __bfloat162float(h2) + __bfloat162float(h3);
                }
                *(unsigned*)(oh + (size_t)r * opitch + colG)       = pack2(h0, h1);
                *(unsigned*)(oh + (size_t)(r + 8) * opitch + colG) = pack2(h2, h3);
            }
            if (EPI & EPI_OUTPAIR) {
                __nv_bfloat16 h0, l0, h1, l1;
                split2(v0, h0, l0); split2(v1, h1, l1);
                *(unsigned*)(oh + (size_t)r * opitch + colG) = pack2(h0, h1);
                *(unsigned*)(ol + (size_t)r * opitch + colG) = pack2(l0, l1);
                split2(v2, h0, l0); split2(v3, h1, l1);
                *(unsigned*)(oh + (size_t)(r + 8) * opitch + colG) = pack2(h0, h1);
                *(unsigned*)(ol + (size_t)(r + 8) * opitch + colG) = pack2(l0, l1);
            }
        }
    }
    if (EPI & (EPI_SPART | EPI_SSQ)) {
        float (*spp)[128] = (float(*)[128])sp;
#pragma unroll
        for (int mi = 0; mi < 4; mi++) {
            float s0 = srow0[mi], s1 = srow1[mi];
            s0 += __shfl_xor_sync(0xffffffffu, s0, 1);
            s0 += __shfl_xor_sync(0xffffffffu, s0, 2);
            s1 += __shfl_xor_sync(0xffffffffu, s1, 1);
            s1 += __shfl_xor_sync(0xffffffffu, s1, 2);
            if (tig == 0) {
                spp[nw][mw * 64 + mi * 16 + g]     = s0;
                spp[nw][mw * 64 + mi * 16 + g + 8] = s1;
            }
        }
        __syncthreads();
        if (tid < 128)
            spart[(size_t)blockIdx.y * spitch + row0 + tid] =
                spp[0][tid] + spp[1][tid] + spp[2][tid] + spp[3][tid];
    }
}

// ---------------------------------------------------------------------------
// Legacy fp32-input GEMM (query/score path only). LN on A input only.
// ---------------------------------------------------------------------------
enum { AOP_ID = 0, AOP_LN = 1 };
#define LEPI_BIAS  1
#define LEPI_GELU  2
#define LEPI_RESID 4

template <int AOP, int EPI>
__global__ __launch_bounds__(256)
void tlegacy(const float* __restrict__ A, int lda,
             const float* __restrict__ B, int ldb,
             const float* __restrict__ bias,
             float* __restrict__ out, size_t ldout, int Kblk,
             const float* __restrict__ mean, const float* __restrict__ rstd,
             const float* __restrict__ lng, const float* __restrict__ lnb,
             const float* __restrict__ resid)
{
    __shared__ __align__(1024) unsigned char sm[16384 + 2 * 9216];
    const uint32_t sb = smem_u32(sm);
    const int tid = threadIdx.x;
    const int row0 = blockIdx.x * 128;
    const int col0 = blockIdx.y * 128;
    const int nch = Kblk >> 5;

    __shared__ float sgam[256], sbet[256];
    if (AOP == AOP_LN) {
        if (tid < Kblk) { sgam[tid] = lng[tid]; sbet[tid] = lnb[tid]; }
    }

    const int arow = tid >> 1, ak0 = (tid & 1) * 16;
    float mr = 0.f, rr = 0.f;
    if (AOP == AOP_LN) { mr = mean[row0 + arow]; rr = rstd[row0 + arow]; }
    const float* Ap = A + (size_t)(row0 + arow) * lda;
    const int bkr = tid >> 3, bn0 = (tid & 7) * 16;
    const float* Bp0 = B + (size_t)bkr * ldb + col0 + bn0;

    const int lane = tid & 31, w = tid >> 5;
    const int mw = w >> 2, nw = w & 3;
    const int g = lane >> 2, tig = lane & 3;
    const int lrow = (lane & 7) + ((lane >> 3) & 1) * 8;
    const int lkh = (lane >> 4) * 16;
    const int trow = (lane & 7) + ((lane >> 4) & 1) * 8;
    const int tnh = ((lane >> 3) & 1) * 16;

    float acc[4][4][4];
#pragma unroll
    for (int mi = 0; mi < 4; mi++)
#pragma unroll
        for (int ni = 0; ni < 4; ni++)
#pragma unroll
            for (int e = 0; e < 4; e++) acc[mi][ni][e] = 0.f;

    for (int c = 0; c < nch; c++) {
        const int kc = c * 32;
        __syncthreads();
#pragma unroll
        for (int i = 0; i < 4; i++) {
            float4 t = *(const float4*)(Ap + kc + ak0 + i * 4);
            float v[4] = {t.x, t.y, t.z, t.w};
            if (AOP == AOP_LN) {
#pragma unroll
                for (int j = 0; j < 4; j++) {
                    const int kg = kc + ak0 + i * 4 + j;
                    v[j] = (v[j] - mr) * rr * sgam[kg] + sbet[kg];
                }
            }
            const unsigned base = arow * 64 + (ak0 + i * 4) * 2;
            __nv_bfloat16 h0, l0, h1, l1;
            split2(v[0], h0, l0); split2(v[1], h1, l1);
            *(unsigned*)(sm + SWZ(base)) = pack2(h0, h1);
            *(unsigned*)(sm + 8192 + SWZ(base)) = pack2(l0, l1);
            split2(v[2], h0, l0); split2(v[3], h1, l1);
            *(unsigned*)(sm + SWZ(base + 4)) = pack2(h0, h1);
            *(unsigned*)(sm + 8192 + SWZ(base + 4)) = pack2(l0, l1);
        }
#pragma unroll
        for (int i = 0; i < 4; i++) {
            float4 t = *(const float4*)(Bp0 + (size_t)kc * ldb + i * 4);
            float v[4] = {t.x, t.y, t.z, t.w};
            const unsigned base = bkr * BSTRIDE0 + (bn0 + i * 4) * 2;
            __nv_bfloat16 h0, l0, h1, l1;
            split2(v[0], h0, l0); split2(v[1], h1, l1);
            *(unsigned*)(sm + 16384 + SWZ(base)) = pack2(h0, h1);
            *(unsigned*)(sm + 16384 + 9216 + SWZ(base)) = pack2(l0, l1);
            split2(v[2], h0, l0); split2(v[3], h1, l1);
            *(unsigned*)(sm + 16384 + SWZ(base + 4)) = pack2(h0, h1);
            *(unsigned*)(sm + 16384 + 9216 + SWZ(base + 4)) = pack2(l0, l1);
        }
        __syncthreads();
#pragma unroll
        for (int ks = 0; ks < 2; ks++) {
            unsigned ah[4][4], al[4][4];
#pragma unroll
            for (int mi = 0; mi < 4; mi++) {
                const int r = mw * 64 + mi * 16 + lrow;
                const unsigned off = SWZ(r * 64 + ks * 32 + lkh);
                LDSM4(ah[mi], sb + off);
                LDSM4(al[mi], sb + 8192 + off);
            }
#pragma unroll
            for (int nb = 0; nb < 2; nb++) {
                unsigned bh[4], bl[4];
                const int kr = ks * 16 + trow;
                const unsigned off = SWZ(kr * BSTRIDE0 + (nw * 32 + nb * 16) * 2 + tnh);
                LDSM4T(bh, sb + 16384 + off);
                LDSM4T(bl, sb + 16384 + 9216 + off);
                unsigned beh[2] = {bh[0], bh[2]}, boh[2] = {bh[1], bh[3]};
                unsigned bel[2] = {bl[0], bl[2]}, bol[2] = {bl[1], bl[3]};
#pragma unroll
                for (int mi = 0; mi < 4; mi++) {
                    mma16816(acc[mi][2 * nb],     ah[mi], beh);
                    mma16816(acc[mi][2 * nb],     ah[mi], bel);
                    mma16816(acc[mi][2 * nb],     al[mi], beh);
                    mma16816(acc[mi][2 * nb + 1], ah[mi], boh);
                    mma16816(acc[mi][2 * nb + 1], ah[mi], bol);
                    mma16816(acc[mi][2 * nb + 1], al[mi], boh);
                }
            }
        }
    }

#pragma unroll
    for (int mi = 0; mi < 4; mi++) {
        const int r = row0 + mw * 64 + mi * 16 + g;
#pragma unroll
        for (int ni = 0; ni < 4; ni++) {
            const int colG = col0 + nw * 32 + ni * 8 + 2 * tig;
            float v0 = acc[mi][ni][0], v1 = acc[mi][ni][1];
            float v2 = acc[mi][ni][2], v3 = acc[mi][ni][3];
            if (EPI & LEPI_BIAS) {
                float2 bb = *(const float2*)(bias + colG);
                v0 += bb.x; v1 += bb.y; v2 += bb.x; v3 += bb.y;
            }
            if (EPI & LEPI_GELU) {
                v0 = geluf(v0); v1 = geluf(v1); v2 = geluf(v2); v3 = geluf(v3);
            }
            if (EPI & LEPI_RESID) {
                float2 ra = *(const float2*)(resid + (size_t)r * 256 + colG);
                float2 rb = *(const float2*)(resid + (size_t)(r + 8) * 256 + colG);
                v0 += ra.x; v1 += ra.y; v2 += rb.x; v3 += rb.y;
            }
            *(float2*)(out + (size_t)r * ldout + colG)       = make_float2(v0, v1);
            *(float2*)(out + (size_t)(r + 8) * ldout + colG) = make_float2(v2, v3);
        }
    }
}

// ---------------- prep kernels ----------------------------------------------
__global__ void prep_pf(const float* __restrict__ pf,
                        __nv_bfloat16* __restrict__ H, __nv_bfloat16* __restrict__ L, int N)
{
    int idx = blockIdx.x * 256 + threadIdx.x;
    int row = idx / 12, c8 = (idx % 12) * 8;
    if (row >= N) return;
    __nv_bfloat16 h[8], l[8];
#pragma unroll
    for (int j = 0; j < 8; j++) {
        int k = c8 + j;
        float v = (k < 72) ? pf[(size_t)row * 72 + k] : 0.f;
        split2(v, h[j], l[j]);
    }
    *(uint4*)(H + (size_t)row * 96 + c8) = *(uint4*)h;
    *(uint4*)(L + (size_t)row * 96 + c8) = *(uint4*)l;
}

__global__ void prep_w(const float* __restrict__ W,
                       __nv_bfloat16* __restrict__ H, __nv_bfloat16* __restrict__ L,
                       int rows, int realrows)
{
    int idx = blockIdx.x * 256 + threadIdx.x;
    int row = idx / 32, c8 = (idx % 32) * 8;
    if (row >= rows) return;
    __nv_bfloat16 h[8], l[8];
#pragma unroll
    for (int j = 0; j < 8; j++) {
        float v = (row < realrows) ? W[(size_t)row * 256 + c8 + j] : 0.f;
        split2(v, h[j], l[j]);
    }
    *(uint4*)(H + (size_t)row * 256 + c8) = *(uint4*)h;
    *(uint4*)(L + (size_t)row * 256 + c8) = *(uint4*)l;
}

__global__ void prep_wT(const float* __restrict__ W,
                        __nv_bfloat16* __restrict__ H, __nv_bfloat16* __restrict__ L,
                        int kpad, int realk)
{
    int idx = blockIdx.x * 256 + threadIdx.x;
    int n = idx / (kpad / 8), c8 = (idx % (kpad / 8)) * 8;
    if (n >= 256) return;
    __nv_bfloat16 h[8], l[8];
#pragma unroll
    for (int j = 0; j < 8; j++) {
        int k = c8 + j;
        float v = (k < realk) ? W[(size_t)k * 256 + n] : 0.f;
        split2(v, h[j], l[j]);
    }
    *(uint4*)(H + (size_t)n * kpad + c8) = *(uint4*)h;
    *(uint4*)(L + (size_t)n * kpad + c8) = *(uint4*)l;
}

template <bool GELU>
__global__ __launch_bounds__(256)
void lnprep(const __nv_bfloat16* __restrict__ inH, const __nv_bfloat16* __restrict__ inL,
            const float* __restrict__ gam, const float* __restrict__ bet,
            __nv_bfloat16* __restrict__ outH, __nv_bfloat16* __restrict__ outL, int M)
{
    const int wid = threadIdx.x >> 5, lane = threadIdx.x & 31;
    const int row = blockIdx.x * 8 + wid;
    if (row >= M) return;
    const int c8 = lane * 8;
    uint4 uh = *(const uint4*)(inH + (size_t)row * 256 + c8);
    uint4 ul = *(const uint4*)(inL + (size_t)row * 256 + c8);
    const __nv_bfloat16* ph = (const __nv_bfloat16*)&uh;
    const __nv_bfloat16* pl = (const __nv_bfloat16*)&ul;
    float v[8];
    float s = 0.f, ss = 0.f;
#pragma unroll
    for (int j = 0; j < 8; j++) {
        v[j] = __bfloat162float(ph[j]) + __bfloat162float(pl[j]);
        s += v[j]; ss += v[j] * v[j];
    }
#pragma unroll
    for (int o = 16; o; o >>= 1) {
        s  += __shfl_xor_sync(0xffffffffu, s, o);
        ss += __shfl_xor_sync(0xffffffffu, ss, o);
    }
    const float m = s * (1.0f / 256.0f);
    const float r = rsqrtf(ss * (1.0f / 256.0f) - m * m + 1e-5f);
    float4 g0 = *(const float4*)(gam + c8), g1 = *(const float4*)(gam + c8 + 4);
    float4 b0 = *(const float4*)(bet + c8), b1 = *(const float4*)(bet + c8 + 4);
    float gg[8] = {g0.x, g0.y, g0.z, g0.w, g1.x, g1.y, g1.z, g1.w};
    float bb[8] = {b0.x, b0.y, b0.z, b0.w, b1.x, b1.y, b1.z, b1.w};
    __nv_bfloat16 oh[8], ol[8];
#pragma unroll
    for (int j = 0; j < 8; j++) {
        float x = (v[j] - m) * r * gg[j] + bb[j];
        if (GELU) x = geluf(x);
        split2(x, oh[j], ol[j]);
    }
    *(uint4*)(outH + (size_t)row * 256 + c8) = *(uint4*)oh;
    *(uint4*)(outL + (size_t)row * 256 + c8) = *(uint4*)ol;
}

// ---------------- misc small kernels ----------------------------------------
__global__ __launch_bounds__(256)
void ln_stats(const float* __restrict__ X, float* __restrict__ mean,
              float* __restrict__ rstd, int M)
{
    int warp = (blockIdx.x * blockDim.x + threadIdx.x) >> 5;
    if (warp >= M) return;
    int lane = threadIdx.x & 31;
    const float* row = X + (size_t)warp * 256;
    float s = 0.f, ss = 0.f;
#pragma unroll
    for (int j = 0; j < 8; j++) { float v = row[lane + 32 * j]; s += v; ss += v * v; }
#pragma unroll
    for (int o = 16; o; o >>= 1) {
        s  += __shfl_xor_sync(0xffffffffu, s, o);
        ss += __shfl_xor_sync(0xffffffffu, ss, o);
    }
    if (lane == 0) {
        float m = s * (1.0f / 256.0f);
        mean[warp] = m;
        rstd[warp] = rsqrtf(ss * (1.0f / 256.0f) - m * m + 1e-5f);
    }
}

__global__ __launch_bounds__(256)
void rownorm(const float* __restrict__ X, float* __restrict__ inv, int M)
{
    int warp = (blockIdx.x * blockDim.x + threadIdx.x) >> 5;
    if (warp >= M) return;
    int lane = threadIdx.x & 31;
    const float* row = X + (size_t)warp * 256;
    float ss = 0.f;
#pragma unroll
    for (int j = 0; j < 8; j++) { float v = row[lane + 32 * j]; ss += v * v; }
#pragma unroll
    for (int o = 16; o; o >>= 1) ss += __shfl_xor_sync(0xffffffffu, ss, o);
    if (lane == 0) inv[warp] = 1.0f / fmaxf(sqrtf(ss), 1e-12f);
}

__global__ void combine_ssq(const float* __restrict__ ssqp, float* __restrict__ inv, int N)
{
    int i = blockIdx.x * 256 + threadIdx.x;
    if (i < N) inv[i] = 1.0f / fmaxf(sqrtf(ssqp[i] + ssqp[(size_t)N + i]), 1e-12f);
}

__global__ void qmpair(const float* __restrict__ qe, const float* __restrict__ invq,
                       const float* __restrict__ lsc,
                       __nv_bfloat16* __restrict__ H, __nv_bfloat16* __restrict__ L)
{
    int idx = blockIdx.x * 256 + threadIdx.x;
    int r = idx >> 8;
    float v = qe[idx] * invq[r] * expf(lsc[0]);
    __nv_bfloat16 h, l;
    split2(v, h, l);
    H[idx] = h; L[idx] = l;
}

__global__ __launch_bounds__(256)
void reduce_refined(const float* __restrict__ Ppart, const float* __restrict__ spart,
                    const float* __restrict__ qe, float* __restrict__ refined,
                    int CH, int NB)
{
    const int q = blockIdx.x;
    const int d = threadIdx.x;
    __shared__ float sh[256];
    float s = 0.f;
    for (int i = d; i < NB; i += 256) s += spart[(size_t)i * 128 + q];
    sh[d] = s;
    __syncthreads();
    for (int o = 128; o; o >>= 1) {
        if (d < o) sh[d] += sh[d + o];
        __syncthreads();
    }
    const float stot = sh[0];
    float p = 0.f;
    for (int c = 0; c < CH; c++) p += Ppart[((size_t)c * 128 + q) * 256 + d];
    refined[(size_t)q * 256 + d] = qe[(size_t)q * 256 + d] + p / stot;
}

__global__ __launch_bounds__(256)
void score_kernel(const float* __restrict__ A2s, const float* __restrict__ w2,
                  const float* __restrict__ b2, float* __restrict__ out)
{
    const int q = blockIdx.x;
    const int d = threadIdx.x;
    __shared__ float sh[256];
    sh[d] = A2s[(size_t)q * 256 + d] * w2[d];
    __syncthreads();
    for (int o = 128; o; o >>= 1) {
        if (d < o) sh[d] += sh[d + o];
        __syncthreads();
    }
    if (d == 0) out[q] = sh[0] + b2[0];
}

// ---------------------------------------------------------------------------
extern "C" void kernel_launch(void* const* d_in, const int* in_sizes, int n_in,
                              void* d_out, int out_size)
{
    const float* point_feat = (const float*)d_in[0];
    const float* ip_w1 = (const float*)d_in[1];
    const float* ip_b1 = (const float*)d_in[2];
    const float* ip_ln_g = (const float*)d_in[3];
    const float* ip_ln_b = (const float*)d_in[4];
    const float* ip_w2 = (const float*)d_in[5];
    const float* ip_b2 = (const float*)d_in[6];
    const float* ph_ln_g = (const float*)d_in[7];
    const float* ph_ln_b = (const float*)d_in[8];
    const float* ph_w1 = (const float*)d_in[9];
    const float* ph_b1 = (const float*)d_in[10];
    const float* ph_w2 = (const float*)d_in[11];
    const float* ph_b2 = (const float*)d_in[12];
    const float* q_embed = (const float*)d_in[13];
    const float* qh_ln_g = (const float*)d_in[14];
    const float* qh_ln_b = (const float*)d_in[15];
    const float* qh_w1 = (const float*)d_in[16];
    const float* qh_b1 = (const float*)d_in[17];
    const float* qh_w2 = (const float*)d_in[18];
    const float* qh_b2 = (const float*)d_in[19];
    const float* sh_ln_g = (const float*)d_in[20];
    const float* sh_ln_b = (const float*)d_in[21];
    const float* sh_w1 = (const float*)d_in[22];
    const float* sh_b1 = (const float*)d_in[23];
    const float* sh_w2 = (const float*)d_in[24];
    const float* sh_b2 = (const float*)d_in[25];
    const float* logit_scale = (const float*)d_in[26];

    const int N = in_sizes[0] / 72;

    float* out = (float*)d_out;
    const size_t offScore = (size_t)128 * N;
    const size_t offPE = offScore + 128;
    const size_t offRef = offPE + (size_t)N * 256;
    float* mask = out;
    float* score = out + offScore;
    float* pe = out + offPE;
    float* refined = out + offRef;

    __nv_bfloat16 *pfH, *pfL, *xH, *xL, *aH, *aL, *hH, *hL, *peH, *peL, *emH;
    __nv_bfloat16 *w1H, *w1L, *w2H, *w2L, *w3H, *w3L, *w4H, *w4L, *qmH, *qmL;
    float *invpe, *meanQ, *rstdQ, *A2q, *qe, *invq, *spart, *Ppart;
    cudaGetSymbolAddress((void**)&pfH, g_pfH); cudaGetSymbolAddress((void**)&pfL, g_pfL);
    cudaGetSymbolAddress((void**)&xH, g_xH);   cudaGetSymbolAddress((void**)&xL, g_xL);
    cudaGetSymbolAddress((void**)&aH, g_aH);   cudaGetSymbolAddress((void**)&aL, g_aL);
    cudaGetSymbolAddress((void**)&hH, g_hH);   cudaGetSymbolAddress((void**)&hL, g_hL);
    cudaGetSymbolAddress((void**)&peH, g_peH); cudaGetSymbolAddress((void**)&peL, g_peL);
    cudaGetSymbolAddress((void**)&emH, g_emH);
    cudaGetSymbolAddress((void**)&w1H, g_w1H); cudaGetSymbolAddress((void**)&w1L, g_w1L);
    cudaGetSymbolAddress((void**)&w2H, g_w2H); cudaGetSymbolAddress((void**)&w2L, g_w2L);
    cudaGetSymbolAddress((void**)&w3H, g_w3H); cudaGetSymbolAddress((void**)&w3L, g_w3L);
    cudaGetSymbolAddress((void**)&w4H, g_w4H); cudaGetSymbolAddress((void**)&w4L, g_w4L);
    cudaGetSymbolAddress((void**)&qmH, g_qmH); cudaGetSymbolAddress((void**)&qmL, g_qmL);
    cudaGetSymbolAddress((void**)&invpe, g_invpe);
    cudaGetSymbolAddress((void**)&meanQ, g_meanQ); cudaGetSymbolAddress((void**)&rstdQ, g_rstdQ);
    cudaGetSymbolAddress((void**)&A2q, g_A2q); cudaGetSymbolAddress((void**)&qe, g_qe);
    cudaGetSymbolAddress((void**)&invq, g_invq);
    cudaGetSymbolAddress((void**)&spart, g_spart); cudaGetSymbolAddress((void**)&Ppart, g_Ppart);

    // dynamic smem opt-in
    const int SMEM_BT0 = 2 * (16384 + 2 * 9216) + 2048;   // 71680
    const int SMEM_BT1 = 2 * (16384 + 2 * 8192) + 2048;   // 67584
    cudaFuncSetAttribute(tpair256<EPI_BIAS | EPI_LNPAIR | EPI_LNGELU>,
                         cudaFuncAttributeMaxDynamicSharedMemorySize, SMEM256);
    cudaFuncSetAttribute(tpair<EPI_BIAS | EPI_OUTPAIR, 0>,
                         cudaFuncAttributeMaxDynamicSharedMemorySize, SMEM_BT0);
    cudaFuncSetAttribute(tpair<EPI_BIAS | EPI_GELU | EPI_OUTPAIR, 0>,
                         cudaFuncAttributeMaxDynamicSharedMemorySize, SMEM_BT0);
    cudaFuncSetAttribute(tpair<EPI_BIAS | EPI_RESIDP | EPI_OUTF32 | EPI_OUTPAIR | EPI_SSQ, 0>,
                         cudaFuncAttributeMaxDynamicSharedMemorySize, SMEM_BT0);
    cudaFuncSetAttribute(tpair<EPI_CSCALE | EPI_OUTF32 | EPI_EXP1 | EPI_SPART, 1>,
                         cudaFuncAttributeMaxDynamicSharedMemorySize, SMEM_BT1);
    cudaFuncSetAttribute(tpair<EPI_OUTF32, 0, 1>,
                         cudaFuncAttributeMaxDynamicSharedMemorySize, SMEM_BT0);

    // -------- preps --------
    prep_pf<<<(N * 12 + 255) / 256, 256>>>(point_feat, pfH, pfL, N);
    prep_wT<<<12, 256>>>(ip_w1, w1H, w1L, 96, 72);
    prep_w<<<32, 256>>>(ip_w2, w2H, w2L, 256, 256);
    prep_w<<<32, 256>>>(ph_w1, w3H, w3L, 256, 256);
    prep_w<<<32, 256>>>(ph_w2, w4H, w4L, 256, 256);

    const dim3 gBig(N / 128, 2);

    // -------- point pipeline --------
    // a = gelu(LN(pf @ ip_w1 + ip_b1))  (fused; R12-verified)
    tpair256<EPI_BIAS | EPI_LNPAIR | EPI_LNGELU><<<N / 128, 512, SMEM256>>>(
        pfH, pfL, 96, w1H, w1L, 96, ip_b1,
        nullptr, 0, nullptr, nullptr, aH, aL,
        nullptr, nullptr, ip_ln_g, ip_ln_b, nullptr, 96);
    // h = a @ ip_w2 + ip_b2 (pairs)
    tpair<EPI_BIAS | EPI_OUTPAIR, 0><<<gBig, 256, SMEM_BT0>>>(
        aH, aL, 256, w2H, w2L, 256, ip_b2,
        nullptr, 0, 0, hH, hL, 256, nullptr, nullptr, nullptr, nullptr, 0, 256);
    // a = LN(h) (pairs)
    lnprep<false><<<N / 8, 256>>>(hH, hL, ph_ln_g, ph_ln_b, aH, aL, N);
    // x = gelu(a @ ph_w1 + ph_b1) (pairs)
    tpair<EPI_BIAS | EPI_GELU | EPI_OUTPAIR, 0><<<gBig, 256, SMEM_BT0>>>(
        aH, aL, 256, w3H, w3L, 256, ph_b1,
        nullptr, 0, 0, xH, xL, 256, nullptr, nullptr, nullptr, nullptr, 0, 256);
    // pe = h + x @ ph_w2 + ph_b2 (fp32 to d_out + pairs + fused row-SSQ)
    tpair<EPI_BIAS | EPI_RESIDP | EPI_OUTF32 | EPI_OUTPAIR | EPI_SSQ, 0><<<gBig, 256, SMEM_BT0>>>(
        xH, xL, 256, w4H, w4L, 256, ph_b2,
        pe, 256, 0, peH, peL, 256, hH, hL, nullptr, spart, (size_t)N, 256);
    combine_ssq<<<(N + 255) / 256, 256>>>(spart, invpe, N);

    // -------- query pipeline (legacy, tiny) --------
    ln_stats<<<16, 256>>>(q_embed, meanQ, rstdQ, 128);
    tlegacy<AOP_LN, LEPI_BIAS | LEPI_GELU><<<dim3(1, 2), 256>>>(
        q_embed, 256, qh_w1, 256, qh_b1, A2q, 256, 256,
        meanQ, rstdQ, qh_ln_g, qh_ln_b, nullptr);
    tlegacy<AOP_ID, LEPI_BIAS | LEPI_RESID><<<dim3(1, 2), 256>>>(
        A2q, 256, qh_w2, 256, qh_b2, qe, 256, 256,
        nullptr, nullptr, nullptr, nullptr, q_embed);
    rownorm<<<16, 256>>>(qe, invq, 128);
    qmpair<<<128, 256>>>(qe, invq, logit_scale, qmH, qmL);

    // -------- mask logits + single-bf16 em + CONSISTENT softmax partials ----
    tpair<EPI_CSCALE | EPI_OUTF32 | EPI_EXP1 | EPI_SPART, 1><<<dim3(1, N / 128), 256, SMEM_BT1>>>(
        qmH, qmL, 256, peH, peL, 256, nullptr,
        mask, (size_t)N, 0, emH, nullptr, (size_t)N, nullptr, nullptr, invpe, spart, 128, 256);

    // -------- weighted aggregation (2-term, A-single): Ppart[z] = em @ pe ---
    tpair<EPI_OUTF32, 0, 1><<<dim3(1, 2, 256), 256, SMEM_BT0>>>(
        emH, nullptr, N, peH, peL, 256, nullptr,
        Ppart, 256, (size_t)128 * 256, nullptr, nullptr, 0,
        nullptr, nullptr, nullptr, nullptr, 0, 1024);
    reduce_refined<<<128, 256>>>(Ppart, spart, qe, refined, 256, N / 128);

    // -------- score head (legacy) --------
    ln_stats<<<16, 256>>>(refined, meanQ, rstdQ, 128);
    tlegacy<AOP_LN, LEPI_BIAS | LEPI_GELU><<<dim3(1, 2), 256>>>(
        refined, 256, sh_w1, 256, sh_b1, A2q, 256, 256,
        meanQ, rstdQ, sh_ln_g, sh_ln_b, nullptr);
    score_kernel<<<128, 256>>>(A2q, sh_w2, sh_b2, score);
}

// round 15
// speedup vs baseline: 1.1171x; 1.0073x over previous
#include <cuda_runtime.h>
#include <cuda_bf16.h>
#include <math.h>
#include <stdint.h>

// ---------------------------------------------------------------------------
// QueryInstanceDecoder: bf16 split-precision mma.sync pipeline, v8.
// = R13 (best passing) + term-major MMA ordering (break accumulator RAW
//   chains), MLP-4 reduce_refined, agg z-split 256->128.
// N=262144, C_IN=72, D=256, Q=128.
// d_out (floats): mask_logits[128*N] | score[128] | point_embed[N*256] | refined[128*256]
// ---------------------------------------------------------------------------

#define DEVI __device__ __forceinline__

DEVI float geluf(float x) { return 0.5f * x * (1.0f + erff(x * 0.70710678118654752f)); }

DEVI unsigned pack2(__nv_bfloat16 a, __nv_bfloat16 b) {
    return (unsigned)__bfloat16_as_ushort(a) | ((unsigned)__bfloat16_as_ushort(b) << 16);
}
DEVI void split2(float x, __nv_bfloat16& h, __nv_bfloat16& l) {
    h = __float2bfloat16(x);
    l = __float2bfloat16(x - __bfloat162float(h));
}
DEVI float upk_lo(unsigned u) { return __bfloat162float(__ushort_as_bfloat16((unsigned short)(u & 0xffff))); }
DEVI float upk_hi(unsigned u) { return __bfloat162float(__ushort_as_bfloat16((unsigned short)(u >> 16))); }

DEVI void mma16816(float* c, const unsigned* a, const unsigned* b) {
    asm volatile(
        "mma.sync.aligned.m16n8k16.row.col.f32.bf16.bf16.f32 "
        "{%0,%1,%2,%3},{%4,%5,%6,%7},{%8,%9},{%0,%1,%2,%3};"
        : "+f"(c[0]), "+f"(c[1]), "+f"(c[2]), "+f"(c[3])
        : "r"(a[0]), "r"(a[1]), "r"(a[2]), "r"(a[3]), "r"(b[0]), "r"(b[1]));
}
DEVI uint32_t smem_u32(const void* p) {
    uint32_t a;
    asm("{ .reg .u64 t; cvta.to.shared.u64 t, %1; cvt.u32.u64 %0, t; }" : "=r"(a) : "l"(p));
    return a;
}
#define LDSM4(r, a) \
    asm volatile("ldmatrix.sync.aligned.m8n8.x4.shared.b16 {%0,%1,%2,%3},[%4];" \
        : "=r"((r)[0]), "=r"((r)[1]), "=r"((r)[2]), "=r"((r)[3]) : "r"(a))
#define LDSM4T(r, a) \
    asm volatile("ldmatrix.sync.aligned.m8n8.x4.trans.shared.b16 {%0,%1,%2,%3},[%4];" \
        : "=r"((r)[0]), "=r"((r)[1]), "=r"((r)[2]), "=r"((r)[3]) : "r"(a))

DEVI void cpasync16(uint32_t dst, const void* src) {
    asm volatile("cp.async.cg.shared.global [%0], [%1], 16;" :: "r"(dst), "l"(src));
}
DEVI void cpcommit() { asm volatile("cp.async.commit_group;"); }
DEVI void cpwait1()  { asm volatile("cp.async.wait_group 1;"); }
DEVI void cpwait0()  { asm volatile("cp.async.wait_group 0;"); }

#define SWZ(o) ((unsigned)(o) ^ ((((unsigned)(o)) >> 3) & 0x70))
#define BSTRIDE0 288

// ---------------- scratch (static device memory; no allocations) -----------
#define NMAX 262144
__device__ __nv_bfloat16 g_pfH[(size_t)NMAX * 96], g_pfL[(size_t)NMAX * 96];
__device__ __nv_bfloat16 g_xH[(size_t)NMAX * 256], g_xL[(size_t)NMAX * 256];
__device__ __nv_bfloat16 g_aH[(size_t)NMAX * 256], g_aL[(size_t)NMAX * 256];
__device__ __nv_bfloat16 g_hH[(size_t)NMAX * 256], g_hL[(size_t)NMAX * 256];
__device__ __nv_bfloat16 g_peH[(size_t)NMAX * 256], g_peL[(size_t)NMAX * 256];
__device__ __nv_bfloat16 g_emH[(size_t)128 * NMAX];
__device__ __nv_bfloat16 g_w1H[96 * 256], g_w1L[96 * 256];     // [n=256][k=96] transposed
__device__ __nv_bfloat16 g_w2H[256 * 256], g_w2L[256 * 256];   // [k][n]
__device__ __nv_bfloat16 g_w3H[256 * 256], g_w3L[256 * 256];
__device__ __nv_bfloat16 g_w4H[256 * 256], g_w4L[256 * 256];
__device__ __nv_bfloat16 g_qmH[128 * 256], g_qmL[128 * 256];
__device__ float g_invpe[NMAX];
__device__ float g_meanQ[128], g_rstdQ[128];
__device__ float g_A2q[128 * 256];
__device__ float g_qe[128 * 256];
__device__ float g_invq[128];
__device__ float g_spart[(size_t)2 * NMAX];
__device__ float g_Ppart[256 * 128 * 256];

// ---------------- epilogue flags --------------------------------------------
#define EPI_BIAS    1
#define EPI_GELU    2
#define EPI_RESIDP  4
#define EPI_OUTF32  8
#define EPI_OUTPAIR 16
#define EPI_SPART   32
#define EPI_CSCALE  64
#define EPI_SSQ     256
#define EPI_LNPAIR  512
#define EPI_LNGELU  1024
#define EPI_EXP1    2048    // store bf16(exp(v)) single; spart from ROUNDED values

// =============================================================================
// tpair256: C[128x256] = A_pairs @ B_pairs^T (B image [n][k]). 512 threads,
// 16 warps (2x8), warp 64x32, 2-stage cp.async. Used only for GEMM1 (K=96).
// =============================================================================
#define STG256 49152
#define SP_OFF (2 * STG256)
#define SMEM256 (SP_OFF + 4096 + 4096 + 512 + 512 + 1024 + 1024)

template <int EPI>
__global__ __launch_bounds__(512, 1)
void tpair256(const __nv_bfloat16* __restrict__ Ah, const __nv_bfloat16* __restrict__ Al, int lda,
              const __nv_bfloat16* __restrict__ Bh, const __nv_bfloat16* __restrict__ Bl, int ldb,
              const float* __restrict__ bias,
              float* __restrict__ outf, size_t ldout,
              __nv_bfloat16* __restrict__ oh, __nv_bfloat16* __restrict__ ol,
              __nv_bfloat16* __restrict__ o2h, __nv_bfloat16* __restrict__ o2l,
              const __nv_bfloat16* __restrict__ resH, const __nv_bfloat16* __restrict__ resL,
              const float* __restrict__ gam, const float* __restrict__ bet,
              float* __restrict__ invout, int Kblk)
{
    extern __shared__ __align__(1024) unsigned char sm[];
    const uint32_t sb = smem_u32(sm);
    float* spS  = (float*)(sm + SP_OFF);
    float* spSS = (float*)(sm + SP_OFF + 4096);
    float* marr = (float*)(sm + SP_OFF + 8192);
    float* rarr = (float*)(sm + SP_OFF + 8704);
    float* sgam = (float*)(sm + SP_OFF + 9216);
    float* sbet = (float*)(sm + SP_OFF + 10240);

    const int tid  = threadIdx.x;
    const int row0 = blockIdx.x * 128;
    const int nch  = Kblk >> 5;

    if (EPI & EPI_LNPAIR) {
        if (tid < 256) { sgam[tid] = gam[tid]; sbet[tid] = bet[tid]; }
    }

    const int arow = tid >> 2, ak0 = (tid & 3) * 8;
    const int brow = tid >> 1, bk0 = (tid & 1) * 16;
    const unsigned dA  = SWZ(arow * 64 + ak0 * 2);
    const unsigned dB  = SWZ(brow * 64 + bk0 * 2);
    const unsigned dB2 = SWZ(brow * 64 + bk0 * 2 + 16);
    const __nv_bfloat16* ApH = Ah + (size_t)(row0 + arow) * lda + ak0;
    const __nv_bfloat16* ApL = Al + (size_t)(row0 + arow) * lda + ak0;
    const __nv_bfloat16* BpH = Bh + (size_t)brow * ldb + bk0;
    const __nv_bfloat16* BpL = Bl + (size_t)brow * ldb + bk0;

    auto issue = [&](int c) {
        const int kc = c * 32;
        const uint32_t st = sb + (c & 1) * STG256;
        cpasync16(st + dA, ApH + kc);
        cpasync16(st + 8192 + dA, ApL + kc);
        cpasync16(st + 16384 + dB,  BpH + kc);
        cpasync16(st + 16384 + dB2, BpH + kc + 8);
        cpasync16(st + 32768 + dB,  BpL + kc);
        cpasync16(st + 32768 + dB2, BpL + kc + 8);
        cpcommit();
    };

    const int lane = tid & 31, w = tid >> 5;
    const int mw = w >> 3, nw = w & 7;
    const int g = lane >> 2, tig = lane & 3;
    const int lrow = (lane & 7) + ((lane >> 3) & 1) * 8;
    const int lkh  = (lane >> 4) * 16;

    float acc[4][4][4];
#pragma unroll
    for (int mi = 0; mi < 4; mi++)
#pragma unroll
        for (int ni = 0; ni < 4; ni++)
#pragma unroll
            for (int e = 0; e < 4; e++) acc[mi][ni][e] = 0.f;

    auto compute = [&](int c) {
        const uint32_t st = sb + (c & 1) * STG256;
#pragma unroll
        for (int ks = 0; ks < 2; ks++) {
            unsigned ah[4][4], al[4][4];
#pragma unroll
            for (int mi = 0; mi < 4; mi++) {
                const int r = mw * 64 + mi * 16 + lrow;
                const unsigned off = SWZ(r * 64 + ks * 32 + lkh);
                LDSM4(ah[mi], st + off);
                LDSM4(al[mi], st + 8192 + off);
            }
#pragma unroll
            for (int nb = 0; nb < 2; nb++) {
                unsigned bh[4], bl[4];
                const int n = nw * 32 + nb * 16 + lrow;
                const unsigned off = SWZ(n * 64 + ks * 32 + lkh);
                LDSM4(bh, st + 16384 + off);
                LDSM4(bl, st + 32768 + off);
                unsigned beh[2] = {bh[0], bh[2]}, boh[2] = {bh[1], bh[3]};
                unsigned bel[2] = {bl[0], bl[2]}, bol[2] = {bl[1], bl[3]};
                // term-major ordering: consecutive MMAs hit different acc regs
#pragma unroll
                for (int mi = 0; mi < 4; mi++) mma16816(acc[mi][2 * nb],     ah[mi], beh);
#pragma unroll
                for (int mi = 0; mi < 4; mi++) mma16816(acc[mi][2 * nb + 1], ah[mi], boh);
#pragma unroll
                for (int mi = 0; mi < 4; mi++) mma16816(acc[mi][2 * nb],     ah[mi], bel);
#pragma unroll
                for (int mi = 0; mi < 4; mi++) mma16816(acc[mi][2 * nb + 1], ah[mi], bol);
#pragma unroll
                for (int mi = 0; mi < 4; mi++) mma16816(acc[mi][2 * nb],     al[mi], beh);
#pragma unroll
                for (int mi = 0; mi < 4; mi++) mma16816(acc[mi][2 * nb + 1], al[mi], boh);
            }
        }
    };

    issue(0);
    for (int c = 0; c < nch; c++) {
        if (c + 1 < nch) { issue(c + 1); cpwait1(); } else { cpwait0(); }
        __syncthreads();
        compute(c);
        __syncthreads();
    }

    // pass A: finalize, stats
    float sS0[4], sS1[4], sSS0[4], sSS1[4];
#pragma unroll
    for (int mi = 0; mi < 4; mi++) { sS0[mi] = sS1[mi] = sSS0[mi] = sSS1[mi] = 0.f; }

#pragma unroll
    for (int mi = 0; mi < 4; mi++) {
        const int r = row0 + mw * 64 + mi * 16 + g;
#pragma unroll
        for (int ni = 0; ni < 4; ni++) {
            const int colG = nw * 32 + ni * 8 + 2 * tig;
            float v0 = acc[mi][ni][0], v1 = acc[mi][ni][1];
            float v2 = acc[mi][ni][2], v3 = acc[mi][ni][3];
            if (EPI & EPI_BIAS) {
                float2 bb = *(const float2*)(bias + colG);
                v0 += bb.x; v1 += bb.y; v2 += bb.x; v3 += bb.y;
            }
            if (EPI & EPI_GELU) {
                v0 = geluf(v0); v1 = geluf(v1); v2 = geluf(v2); v3 = geluf(v3);
            }
            if (EPI & EPI_RESIDP) {
                unsigned uh0 = *(const unsigned*)(resH + (size_t)r * 256 + colG);
                unsigned ul0 = *(const unsigned*)(resL + (size_t)r * 256 + colG);
                unsigned uh1 = *(const unsigned*)(resH + (size_t)(r + 8) * 256 + colG);
                unsigned ul1 = *(const unsigned*)(resL + (size_t)(r + 8) * 256 + colG);
                v0 += upk_lo(uh0) + upk_lo(ul0); v1 += upk_hi(uh0) + upk_hi(ul0);
                v2 += upk_lo(uh1) + upk_lo(ul1); v3 += upk_hi(uh1) + upk_hi(ul1);
            }
            if (EPI & EPI_OUTF32) {
                *(float2*)(outf + (size_t)r * ldout + colG)       = make_float2(v0, v1);
                *(float2*)(outf + (size_t)(r + 8) * ldout + colG) = make_float2(v2, v3);
            }
            if (EPI & EPI_LNPAIR) { sS0[mi] += v0 + v1; sS1[mi] += v2 + v3; }
            if (EPI & (EPI_SSQ | EPI_LNPAIR)) {
                sSS0[mi] += v0 * v0 + v1 * v1;
                sSS1[mi] += v2 * v2 + v3 * v3;
            }
            acc[mi][ni][0] = v0; acc[mi][ni][1] = v1;
            acc[mi][ni][2] = v2; acc[mi][ni][3] = v3;
        }
    }

    if (EPI & (EPI_SSQ | EPI_LNPAIR)) {
#pragma unroll
        for (int mi = 0; mi < 4; mi++) {
            float a0 = sS0[mi], a1 = sS1[mi], b0 = sSS0[mi], b1 = sSS1[mi];
            a0 += __shfl_xor_sync(0xffffffffu, a0, 1); a0 += __shfl_xor_sync(0xffffffffu, a0, 2);
            a1 += __shfl_xor_sync(0xffffffffu, a1, 1); a1 += __shfl_xor_sync(0xffffffffu, a1, 2);
            b0 += __shfl_xor_sync(0xffffffffu, b0, 1); b0 += __shfl_xor_sync(0xffffffffu, b0, 2);
            b1 += __shfl_xor_sync(0xffffffffu, b1, 1); b1 += __shfl_xor_sync(0xffffffffu, b1, 2);
            if (tig == 0) {
                const int lr = mw * 64 + mi * 16 + g;
                spS[nw * 128 + lr]      = a0;
                spS[nw * 128 + lr + 8]  = a1;
                spSS[nw * 128 + lr]     = b0;
                spSS[nw * 128 + lr + 8] = b1;
            }
        }
        __syncthreads();
        if (tid < 128) {
            float s = 0.f, ss = 0.f;
#pragma unroll
            for (int ww = 0; ww < 8; ww++) {
                s  += spS[ww * 128 + tid];
                ss += spSS[ww * 128 + tid];
            }
            if (EPI & EPI_LNPAIR) {
                float m = s * (1.0f / 256.0f);
                marr[tid] = m;
                rarr[tid] = rsqrtf(ss * (1.0f / 256.0f) - m * m + 1e-5f);
            }
            if (EPI & EPI_SSQ)
                invout[row0 + tid] = 1.0f / fmaxf(sqrtf(ss), 1e-12f);
        }
        __syncthreads();
    }

    if (EPI & (EPI_OUTPAIR | EPI_LNPAIR)) {
#pragma unroll
        for (int mi = 0; mi < 4; mi++) {
            const int lr = mw * 64 + mi * 16 + g;
            const int r = row0 + lr;
            float m0 = 0.f, r0 = 0.f, m1 = 0.f, r1 = 0.f;
            if (EPI & EPI_LNPAIR) {
                m0 = marr[lr]; r0 = rarr[lr];
                m1 = marr[lr + 8]; r1 = rarr[lr + 8];
            }
#pragma unroll
            for (int ni = 0; ni < 4; ni++) {
                const int colG = nw * 32 + ni * 8 + 2 * tig;
                float v0 = acc[mi][ni][0], v1 = acc[mi][ni][1];
                float v2 = acc[mi][ni][2], v3 = acc[mi][ni][3];
                if (EPI & EPI_OUTPAIR) {
                    __nv_bfloat16 h0, l0, h1, l1;
                    split2(v0, h0, l0); split2(v1, h1, l1);
                    *(unsigned*)(oh + (size_t)r * 256 + colG) = pack2(h0, h1);
                    *(unsigned*)(ol + (size_t)r * 256 + colG) = pack2(l0, l1);
                    split2(v2, h0, l0); split2(v3, h1, l1);
                    *(unsigned*)(oh + (size_t)(r + 8) * 256 + colG) = pack2(h0, h1);
                    *(unsigned*)(ol + (size_t)(r + 8) * 256 + colG) = pack2(l0, l1);
                }
                if (EPI & EPI_LNPAIR) {
                    const float g0 = sgam[colG], g1 = sgam[colG + 1];
                    const float b0 = sbet[colG], b1 = sbet[colG + 1];
                    float t0 = (v0 - m0) * r0 * g0 + b0;
                    float t1 = (v1 - m0) * r0 * g1 + b1;
                    float t2 = (v2 - m1) * r1 * g0 + b0;
                    float t3 = (v3 - m1) * r1 * g1 + b1;
                    if (EPI & EPI_LNGELU) {
                        t0 = geluf(t0); t1 = geluf(t1); t2 = geluf(t2); t3 = geluf(t3);
                    }
                    __nv_bfloat16 h0, l0, h1, l1;
                    split2(t0, h0, l0); split2(t1, h1, l1);
                    *(unsigned*)(o2h + (size_t)r * 256 + colG) = pack2(h0, h1);
                    *(unsigned*)(o2l + (size_t)r * 256 + colG) = pack2(l0, l1);
                    split2(t2, h0, l0); split2(t3, h1, l1);
                    *(unsigned*)(o2h + (size_t)(r + 8) * 256 + colG) = pack2(h0, h1);
                    *(unsigned*)(o2l + (size_t)(r + 8) * 256 + colG) = pack2(l0, l1);
                }
            }
        }
    }
}

// =============================================================================
// R9 pair GEMM (2-stage, 2 CTAs/SM). AS=1: A-single image (2-term split).
// Term-major MMA ordering (v8).
// =============================================================================
template <int EPI, int BT, int AS = 0>
__global__ __launch_bounds__(256, 2)
void tpair(const __nv_bfloat16* __restrict__ Ah, const __nv_bfloat16* __restrict__ Al, int lda,
           const __nv_bfloat16* __restrict__ Bh, const __nv_bfloat16* __restrict__ Bl, int ldb,
           const float* __restrict__ bias,
           float* __restrict__ outf, size_t ldout, size_t zstride,
           __nv_bfloat16* __restrict__ oh, __nv_bfloat16* __restrict__ ol, size_t opitch,
           const __nv_bfloat16* __restrict__ resH, const __nv_bfloat16* __restrict__ resL,
           const float* __restrict__ cscale, float* __restrict__ spart, size_t spitch,
           int Kblk)
{
    constexpr int BSZ = BT ? 8192 : 9216;
    constexpr int STG = 16384 + 2 * BSZ;
    extern __shared__ __align__(1024) unsigned char sm[];
    const uint32_t sb = smem_u32(sm);
    float* sp = (float*)(sm + 2 * STG);

    const int tid  = threadIdx.x;
    const int row0 = blockIdx.x * 128;
    const int col0 = blockIdx.y * 128;
    const int kz   = blockIdx.z * Kblk;
    const int nch  = Kblk >> 5;

    const int arow = tid >> 1, ak0 = (tid & 1) * 16;
    const int brow = tid >> 1, bk0 = (tid & 1) * 16;
    const int bkr = tid >> 3, bn0 = (tid & 7) * 16;
    const unsigned dA  = SWZ(arow * 64 + ak0 * 2);
    const unsigned dA2 = SWZ(arow * 64 + ak0 * 2 + 16);
    const unsigned dB  = BT ? SWZ(brow * 64 + bk0 * 2)      : SWZ(bkr * BSTRIDE0 + bn0 * 2);
    const unsigned dB2 = BT ? SWZ(brow * 64 + bk0 * 2 + 16) : SWZ(bkr * BSTRIDE0 + bn0 * 2 + 16);
    const __nv_bfloat16* ApH = Ah + (size_t)(row0 + arow) * lda + kz + ak0;
    const __nv_bfloat16* ApL = AS ? nullptr : Al + (size_t)(row0 + arow) * lda + kz + ak0;
    const __nv_bfloat16* BpH = BT ? Bh + (size_t)(col0 + brow) * ldb + kz + bk0
                                  : Bh + (size_t)(kz + bkr) * ldb + col0 + bn0;
    const __nv_bfloat16* BpL = BT ? Bl + (size_t)(col0 + brow) * ldb + kz + bk0
                                  : Bl + (size_t)(kz + bkr) * ldb + col0 + bn0;

    auto issue = [&](int c) {
        const int kc = c * 32;
        const uint32_t st = sb + (c & 1) * STG;
        cpasync16(st + dA, ApH + kc);            cpasync16(st + dA2, ApH + kc + 8);
        if (!AS) {
            cpasync16(st + 8192 + dA, ApL + kc);
            cpasync16(st + 8192 + dA2, ApL + kc + 8);
        }
        const size_t boff = BT ? (size_t)kc : (size_t)kc * ldb;
        cpasync16(st + 16384 + dB, BpH + boff);        cpasync16(st + 16384 + dB2, BpH + boff + 8);
        cpasync16(st + 16384 + BSZ + dB, BpL + boff);  cpasync16(st + 16384 + BSZ + dB2, BpL + boff + 8);
        cpcommit();
    };

    const int lane = tid & 31, w = tid >> 5;
    const int mw = w >> 2, nw = w & 3;
    const int g = lane >> 2, tig = lane & 3;
    const int lrow = (lane & 7) + ((lane >> 3) & 1) * 8;
    const int lkh  = (lane >> 4) * 16;
    const int trow = (lane & 7) + ((lane >> 4) & 1) * 8;
    const int tnh  = ((lane >> 3) & 1) * 16;

    float acc[4][4][4];
#pragma unroll
    for (int mi = 0; mi < 4; mi++)
#pragma unroll
        for (int ni = 0; ni < 4; ni++)
#pragma unroll
            for (int e = 0; e < 4; e++) acc[mi][ni][e] = 0.f;

    auto compute = [&](int c) {
        const uint32_t st = sb + (c & 1) * STG;
#pragma unroll
        for (int ks = 0; ks < 2; ks++) {
            unsigned ah[4][4], al[4][4];
#pragma unroll
            for (int mi = 0; mi < 4; mi++) {
                const int r = mw * 64 + mi * 16 + lrow;
                const unsigned off = SWZ(r * 64 + ks * 32 + lkh);
                LDSM4(ah[mi], st + off);
                if (!AS) LDSM4(al[mi], st + 8192 + off);
            }
#pragma unroll
            for (int nb = 0; nb < 2; nb++) {
                unsigned bh[4], bl[4];
                if (BT) {
                    const int n = nw * 32 + nb * 16 + lrow;
                    const unsigned off = SWZ(n * 64 + ks * 32 + lkh);
                    LDSM4(bh, st + 16384 + off);
                    LDSM4(bl, st + 16384 + BSZ + off);
                } else {
                    const int kr = ks * 16 + trow;
                    const unsigned off = SWZ(kr * BSTRIDE0 + (nw * 32 + nb * 16) * 2 + tnh);
                    LDSM4T(bh, st + 16384 + off);
                    LDSM4T(bl, st + 16384 + BSZ + off);
                }
                unsigned beh[2] = {bh[0], bh[2]}, boh[2] = {bh[1], bh[3]};
                unsigned bel[2] = {bl[0], bl[2]}, bol[2] = {bl[1], bl[3]};
                // term-major ordering: consecutive MMAs hit different acc regs
#pragma unroll
                for (int mi = 0; mi < 4; mi++) mma16816(acc[mi][2 * nb],     ah[mi], beh);
#pragma unroll
                for (int mi = 0; mi < 4; mi++) mma16816(acc[mi][2 * nb + 1], ah[mi], boh);
#pragma unroll
                for (int mi = 0; mi < 4; mi++) mma16816(acc[mi][2 * nb],     ah[mi], bel);
#pragma unroll
                for (int mi = 0; mi < 4; mi++) mma16816(acc[mi][2 * nb + 1], ah[mi], bol);
                if (!AS) {
#pragma unroll
                    for (int mi = 0; mi < 4; mi++) mma16816(acc[mi][2 * nb],     al[mi], beh);
#pragma unroll
                    for (int mi = 0; mi < 4; mi++) mma16816(acc[mi][2 * nb + 1], al[mi], boh);
                }
            }
        }
    };

    issue(0);
    for (int c = 0; c < nch; c++) {
        if (c + 1 < nch) { issue(c + 1); cpwait1(); } else { cpwait0(); }
        __syncthreads();
        compute(c);
        __syncthreads();
    }

    float* outp = outf + (size_t)blockIdx.z * zstride;
    float srow0[4] = {0.f, 0.f, 0.f, 0.f}, srow1[4] = {0.f, 0.f, 0.f, 0.f};
#pragma unroll
    for (int mi = 0; mi < 4; mi++) {
        const int r = row0 + mw * 64 + mi * 16 + g;
#pragma unroll
        for (int ni = 0; ni < 4; ni++) {
            const int colG = col0 + nw * 32 + ni * 8 + 2 * tig;
            float v0 = acc[mi][ni][0], v1 = acc[mi][ni][1];
            float v2 = acc[mi][ni][2], v3 = acc[mi][ni][3];
            if (EPI & EPI_BIAS) {
                float2 bb = *(const float2*)(bias + colG);
                v0 += bb.x; v1 += bb.y; v2 += bb.x; v3 += bb.y;
            }
            if (EPI & EPI_GELU) {
                v0 = geluf(v0); v1 = geluf(v1); v2 = geluf(v2); v3 = geluf(v3);
            }
            if (EPI & EPI_RESIDP) {
                unsigned uh0 = *(const unsigned*)(resH + (size_t)r * 256 + colG);
                unsigned ul0 = *(const unsigned*)(resL + (size_t)r * 256 + colG);
                unsigned uh1 = *(const unsigned*)(resH + (size_t)(r + 8) * 256 + colG);
                unsigned ul1 = *(const unsigned*)(resL + (size_t)(r + 8) * 256 + colG);
                v0 += upk_lo(uh0) + upk_lo(ul0); v1 += upk_hi(uh0) + upk_hi(ul0);
                v2 += upk_lo(uh1) + upk_lo(ul1); v3 += upk_hi(uh1) + upk_hi(ul1);
            }
            if (EPI & EPI_CSCALE) {
                float2 cs = *(const float2*)(cscale + colG);
                v0 *= cs.x; v1 *= cs.y; v2 *= cs.x; v3 *= cs.y;
            }
            if (EPI & EPI_OUTF32) {
                *(float2*)(outp + (size_t)r * ldout + colG)       = make_float2(v0, v1);
                *(float2*)(outp + (size_t)(r + 8) * ldout + colG) = make_float2(v2, v3);
            }
            if (EPI & EPI_SSQ) {
                srow0[mi] += v0 * v0 + v1 * v1;
                srow1[mi] += v2 * v2 + v3 * v3;
            }
            if (EPI & EPI_EXP1) {
                __nv_bfloat16 h0 = __float2bfloat16(__expf(v0));
                __nv_bfloat16 h1 = __float2bfloat16(__expf(v1));
                __nv_bfloat16 h2 = __float2bfloat16(__expf(v2));
                __nv_bfloat16 h3 = __float2bfloat16(__expf(v3));
                if (EPI & EPI_SPART) {
                    srow0[mi] += __bfloat162float(h0) + __bfloat162float(h1);
                    srow1[mi] += __bfloat162float(h2) + __bfloat162float(h3);
                }
                *(unsigned*)(oh + (size_t)r * opitch + colG)       = pack2(h0, h1);
                *(unsigned*)(oh + (size_t)(r + 8) * opitch + colG) = pack2(h2, h3);
            }
            if (EPI & EPI_OUTPAIR) {
                __nv_bfloat16 h0, l0, h1, l1;
                split2(v0, h0, l0); split2(v1, h1, l1);
                *(unsigned*)(oh + (size_t)r * opitch + colG) = pack2(h0, h1);
                *(unsigned*)(ol + (size_t)r * opitch + colG) = pack2(l0, l1);
                split2(v2, h0, l0); split2(v3, h1, l1);
                *(unsigned*)(oh + (size_t)(r + 8) * opitch + colG) = pack2(h0, h1);
                *(unsigned*)(ol + (size_t)(r + 8) * opitch + colG) = pack2(l0, l1);
            }
        }
    }
    if (EPI & (EPI_SPART | EPI_SSQ)) {
        float (*spp)[128] = (float(*)[128])sp;
#pragma unroll
        for (int mi = 0; mi < 4; mi++) {
            float s0 = srow0[mi], s1 = srow1[mi];
            s0 += __shfl_xor_sync(0xffffffffu, s0, 1);
            s0 += __shfl_xor_sync(0xffffffffu, s0, 2);
            s1 += __shfl_xor_sync(0xffffffffu, s1, 1);
            s1 += __shfl_xor_sync(0xffffffffu, s1, 2);
            if (tig == 0) {
                spp[nw][mw * 64 + mi * 16 + g]     = s0;
                spp[nw][mw * 64 + mi * 16 + g + 8] = s1;
            }
        }
        __syncthreads();
        if (tid < 128)
            spart[(size_t)blockIdx.y * spitch + row0 + tid] =
                spp[0][tid] + spp[1][tid] + spp[2][tid] + spp[3][tid];
    }
}

// ---------------------------------------------------------------------------
// Legacy fp32-input GEMM (query/score path only). LN on A input only.
// ---------------------------------------------------------------------------
enum { AOP_ID = 0, AOP_LN = 1 };
#define LEPI_BIAS  1
#define LEPI_GELU  2
#define LEPI_RESID 4

template <int AOP, int EPI>
__global__ __launch_bounds__(256)
void tlegacy(const float* __restrict__ A, int lda,
             const float* __restrict__ B, int ldb,
             const float* __restrict__ bias,
             float* __restrict__ out, size_t ldout, int Kblk,
             const float* __restrict__ mean, const float* __restrict__ rstd,
             const float* __restrict__ lng, const float* __restrict__ lnb,
             const float* __restrict__ resid)
{
    __shared__ __align__(1024) unsigned char sm[16384 + 2 * 9216];
    const uint32_t sb = smem_u32(sm);
    const int tid = threadIdx.x;
    const int row0 = blockIdx.x * 128;
    const int col0 = blockIdx.y * 128;
    const int nch = Kblk >> 5;

    __shared__ float sgam[256], sbet[256];
    if (AOP == AOP_LN) {
        if (tid < Kblk) { sgam[tid] = lng[tid]; sbet[tid] = lnb[tid]; }
    }

    const int arow = tid >> 1, ak0 = (tid & 1) * 16;
    float mr = 0.f, rr = 0.f;
    if (AOP == AOP_LN) { mr = mean[row0 + arow]; rr = rstd[row0 + arow]; }
    const float* Ap = A + (size_t)(row0 + arow) * lda;
    const int bkr = tid >> 3, bn0 = (tid & 7) * 16;
    const float* Bp0 = B + (size_t)bkr * ldb + col0 + bn0;

    const int lane = tid & 31, w = tid >> 5;
    const int mw = w >> 2, nw = w & 3;
    const int g = lane >> 2, tig = lane & 3;
    const int lrow = (lane & 7) + ((lane >> 3) & 1) * 8;
    const int lkh = (lane >> 4) * 16;
    const int trow = (lane & 7) + ((lane >> 4) & 1) * 8;
    const int tnh = ((lane >> 3) & 1) * 16;

    float acc[4][4][4];
#pragma unroll
    for (int mi = 0; mi < 4; mi++)
#pragma unroll
        for (int ni = 0; ni < 4; ni++)
#pragma unroll
            for (int e = 0; e < 4; e++) acc[mi][ni][e] = 0.f;

    for (int c = 0; c < nch; c++) {
        const int kc = c * 32;
        __syncthreads();
#pragma unroll
        for (int i = 0; i < 4; i++) {
            float4 t = *(const float4*)(Ap + kc + ak0 + i * 4);
            float v[4] = {t.x, t.y, t.z, t.w};
            if (AOP == AOP_LN) {
#pragma unroll
                for (int j = 0; j < 4; j++) {
                    const int kg = kc + ak0 + i * 4 + j;
                    v[j] = (v[j] - mr) * rr * sgam[kg] + sbet[kg];
                }
            }
            const unsigned base = arow * 64 + (ak0 + i * 4) * 2;
            __nv_bfloat16 h0, l0, h1, l1;
            split2(v[0], h0, l0); split2(v[1], h1, l1);
            *(unsigned*)(sm + SWZ(base)) = pack2(h0, h1);
            *(unsigned*)(sm + 8192 + SWZ(base)) = pack2(l0, l1);
            split2(v[2], h0, l0); split2(v[3], h1, l1);
            *(unsigned*)(sm + SWZ(base + 4)) = pack2(h0, h1);
            *(unsigned*)(sm + 8192 + SWZ(base + 4)) = pack2(l0, l1);
        }
#pragma unroll
        for (int i = 0; i < 4; i++) {
            float4 t = *(const float4*)(Bp0 + (size_t)kc * ldb + i * 4);
            float v[4] = {t.x, t.y, t.z, t.w};
            const unsigned base = bkr * BSTRIDE0 + (bn0 + i * 4) * 2;
            __nv_bfloat16 h0, l0, h1, l1;
            split2(v[0], h0, l0); split2(v[1], h1, l1);
            *(unsigned*)(sm + 16384 + SWZ(base)) = pack2(h0, h1);
            *(unsigned*)(sm + 16384 + 9216 + SWZ(base)) = pack2(l0, l1);
            split2(v[2], h0, l0); split2(v[3], h1, l1);
            *(unsigned*)(sm + 16384 + SWZ(base + 4)) = pack2(h0, h1);
            *(unsigned*)(sm + 16384 + 9216 + SWZ(base + 4)) = pack2(l0, l1);
        }
        __syncthreads();
#pragma unroll
        for (int ks = 0; ks < 2; ks++) {
            unsigned ah[4][4], al[4][4];
#pragma unroll
            for (int mi = 0; mi < 4; mi++) {
                const int r = mw * 64 + mi * 16 + lrow;
                const unsigned off = SWZ(r * 64 + ks * 32 + lkh);
                LDSM4(ah[mi], sb + off);
                LDSM4(al[mi], sb + 8192 + off);
            }
#pragma unroll
            for (int nb = 0; nb < 2; nb++) {
                unsigned bh[4], bl[4];
                const int kr = ks * 16 + trow;
                const unsigned off = SWZ(kr * BSTRIDE0 + (nw * 32 + nb * 16) * 2 + tnh);
                LDSM4T(bh, sb + 16384 + off);
                LDSM4T(bl, sb + 16384 + 9216 + off);
                unsigned beh[2] = {bh[0], bh[2]}, boh[2] = {bh[1], bh[3]};
                unsigned bel[2] = {bl[0], bl[2]}, bol[2] = {bl[1], bl[3]};
#pragma unroll
                for (int mi = 0; mi < 4; mi++) mma16816(acc[mi][2 * nb],     ah[mi], beh);
#pragma unroll
                for (int mi = 0; mi < 4; mi++) mma16816(acc[mi][2 * nb + 1], ah[mi], boh);
#pragma unroll
                for (int mi = 0; mi < 4; mi++) mma16816(acc[mi][2 * nb],     ah[mi], bel);
#pragma unroll
                for (int mi = 0; mi < 4; mi++) mma16816(acc[mi][2 * nb + 1], ah[mi], bol);
#pragma unroll
                for (int mi = 0; mi < 4; mi++) mma16816(acc[mi][2 * nb],     al[mi], beh);
#pragma unroll
                for (int mi = 0; mi < 4; mi++) mma16816(acc[mi][2 * nb + 1], al[mi], boh);
            }
        }
    }

#pragma unroll
    for (int mi = 0; mi < 4; mi++) {
        const int r = row0 + mw * 64 + mi * 16 + g;
#pragma unroll
        for (int ni = 0; ni < 4; ni++) {
            const int colG = col0 + nw * 32 + ni * 8 + 2 * tig;
            float v0 = acc[mi][ni][0], v1 = acc[mi][ni][1];
            float v2 = acc[mi][ni][2], v3 = acc[mi][ni][3];
            if (EPI & LEPI_BIAS) {
                float2 bb = *(const float2*)(bias + colG);
                v0 += bb.x; v1 += bb.y; v2 += bb.x; v3 += bb.y;
            }
            if (EPI & LEPI_GELU) {
                v0 = geluf(v0); v1 = geluf(v1); v2 = geluf(v2); v3 = geluf(v3);
            }
            if (EPI & LEPI_RESID) {
                float2 ra = *(const float2*)(resid + (size_t)r * 256 + colG);
                float2 rb = *(const float2*)(resid + (size_t)(r + 8) * 256 + colG);
                v0 += ra.x; v1 += ra.y; v2 += rb.x; v3 += rb.y;
            }
            *(float2*)(out + (size_t)r * ldout + colG)       = make_float2(v0, v1);
            *(float2*)(out + (size_t)(r + 8) * ldout + colG) = make_float2(v2, v3);
        }
    }
}

// ---------------- prep kernels ----------------------------------------------
__global__ void prep_pf(const float* __restrict__ pf,
                        __nv_bfloat16* __restrict__ H, __nv_bfloat16* __restrict__ L, int N)
{
    int idx = blockIdx.x * 256 + threadIdx.x;
    int row = idx / 12, c8 = (idx % 12) * 8;
    if (row >= N) return;
    __nv_bfloat16 h[8], l[8];
#pragma unroll
    for (int j = 0; j < 8; j++) {
        int k = c8 + j;
        float v = (k < 72) ? pf[(size_t)row * 72 + k] : 0.f;
        split2(v, h[j], l[j]);
    }
    *(uint4*)(H + (size_t)row * 96 + c8) = *(uint4*)h;
    *(uint4*)(L + (size_t)row * 96 + c8) = *(uint4*)l;
}

__global__ void prep_w(const float* __restrict__ W,
                       __nv_bfloat16* __restrict__ H, __nv_bfloat16* __restrict__ L,
                       int rows, int realrows)
{
    int idx = blockIdx.x * 256 + threadIdx.x;
    int row = idx / 32, c8 = (idx % 32) * 8;
    if (row >= rows) return;
    __nv_bfloat16 h[8], l[8];
#pragma unroll
    for (int j = 0; j < 8; j++) {
        float v = (row < realrows) ? W[(size_t)row * 256 + c8 + j] : 0.f;
        split2(v, h[j], l[j]);
    }
    *(uint4*)(H + (size_t)row * 256 + c8) = *(uint4*)h;
    *(uint4*)(L + (size_t)row * 256 + c8) = *(uint4*)l;
}

__global__ void prep_wT(const float* __restrict__ W,
                        __nv_bfloat16* __restrict__ H, __nv_bfloat16* __restrict__ L,
                        int kpad, int realk)
{
    int idx = blockIdx.x * 256 + threadIdx.x;
    int n = idx / (kpad / 8), c8 = (idx % (kpad / 8)) * 8;
    if (n >= 256) return;
    __nv_bfloat16 h[8], l[8];
#pragma unroll
    for (int j = 0; j < 8; j++) {
        int k = c8 + j;
        float v = (k < realk) ? W[(size_t)k * 256 + n] : 0.f;
        split2(v, h[j], l[j]);
    }
    *(uint4*)(H + (size_t)n * kpad + c8) = *(uint4*)h;
    *(uint4*)(L + (size_t)n * kpad + c8) = *(uint4*)l;
}

template <bool GELU>
__global__ __launch_bounds__(256)
void lnprep(const __nv_bfloat16* __restrict__ inH, const __nv_bfloat16* __restrict__ inL,
            const float* __restrict__ gam, const float* __restrict__ bet,
            __nv_bfloat16* __restrict__ outH, __nv_bfloat16* __restrict__ outL, int M)
{
    const int wid = threadIdx.x >> 5, lane = threadIdx.x & 31;
    const int row = blockIdx.x * 8 + wid;
    if (row >= M) return;
    const int c8 = lane * 8;
    uint4 uh = *(const uint4*)(inH + (size_t)row * 256 + c8);
    uint4 ul = *(const uint4*)(inL + (size_t)row * 256 + c8);
    const __nv_bfloat16* ph = (const __nv_bfloat16*)&uh;
    const __nv_bfloat16* pl = (const __nv_bfloat16*)&ul;
    float v[8];
    float s = 0.f, ss = 0.f;
#pragma unroll
    for (int j = 0; j < 8; j++) {
        v[j] = __bfloat162float(ph[j]) + __bfloat162float(pl[j]);
        s += v[j]; ss += v[j] * v[j];
    }
#pragma unroll
    for (int o = 16; o; o >>= 1) {
        s  += __shfl_xor_sync(0xffffffffu, s, o);
        ss += __shfl_xor_sync(0xffffffffu, ss, o);
    }
    const float m = s * (1.0f / 256.0f);
    const float r = rsqrtf(ss * (1.0f / 256.0f) - m * m + 1e-5f);
    float4 g0 = *(const float4*)(gam + c8), g1 = *(const float4*)(gam + c8 + 4);
    float4 b0 = *(const float4*)(bet + c8), b1 = *(const float4*)(bet + c8 + 4);
    float gg[8] = {g0.x, g0.y, g0.z, g0.w, g1.x, g1.y, g1.z, g1.w};
    float bb[8] = {b0.x, b0.y, b0.z, b0.w, b1.x, b1.y, b1.z, b1.w};
    __nv_bfloat16 oh[8], ol[8];
#pragma unroll
    for (int j = 0; j < 8; j++) {
        float x = (v[j] - m) * r * gg[j] + bb[j];
        if (GELU) x = geluf(x);
        split2(x, oh[j], ol[j]);
    }
    *(uint4*)(outH + (size_t)row * 256 + c8) = *(uint4*)oh;
    *(uint4*)(outL + (size_t)row * 256 + c8) = *(uint4*)ol;
}

// ---------------- misc small kernels ----------------------------------------
__global__ __launch_bounds__(256)
void ln_stats(const float* __restrict__ X, float* __restrict__ mean,
              float* __restrict__ rstd, int M)
{
    int warp = (blockIdx.x * blockDim.x + threadIdx.x) >> 5;
    if (warp >= M) return;
    int lane = threadIdx.x & 31;
    const float* row = X + (size_t)warp * 256;
    float s = 0.f, ss = 0.f;
#pragma unroll
    for (int j = 0; j < 8; j++) { float v = row[lane + 32 * j]; s += v; ss += v * v; }
#pragma unroll
    for (int o = 16; o; o >>= 1) {
        s  += __shfl_xor_sync(0xffffffffu, s, o);
        ss += __shfl_xor_sync(0xffffffffu, ss, o);
    }
    if (lane == 0) {
        float m = s * (1.0f / 256.0f);
        mean[warp] = m;
        rstd[warp] = rsqrtf(ss * (1.0f / 256.0f) - m * m + 1e-5f);
    }
}

__global__ __launch_bounds__(256)
void rownorm(const float* __restrict__ X, float* __restrict__ inv, int M)
{
    int warp = (blockIdx.x * blockDim.x + threadIdx.x) >> 5;
    if (warp >= M) return;
    int lane = threadIdx.x & 31;
    const float* row = X + (size_t)warp * 256;
    float ss = 0.f;
#pragma unroll
    for (int j = 0; j < 8; j++) { float v = row[lane + 32 * j]; ss += v * v; }
#pragma unroll
    for (int o = 16; o; o >>= 1) ss += __shfl_xor_sync(0xffffffffu, ss, o);
    if (lane == 0) inv[warp] = 1.0f / fmaxf(sqrtf(ss), 1e-12f);
}

__global__ void combine_ssq(const float* __restrict__ ssqp, float* __restrict__ inv, int N)
{
    int i = blockIdx.x * 256 + threadIdx.x;
    if (i < N) inv[i] = 1.0f / fmaxf(sqrtf(ssqp[i] + ssqp[(size_t)N + i]), 1e-12f);
}

__global__ void qmpair(const float* __restrict__ qe, const float* __restrict__ invq,
                       const float* __restrict__ lsc,
                       __nv_bfloat16* __restrict__ H, __nv_bfloat16* __restrict__ L)
{
    int idx = blockIdx.x * 256 + threadIdx.x;
    int r = idx >> 8;
    float v = qe[idx] * invq[r] * expf(lsc[0]);
    __nv_bfloat16 h, l;
    split2(v, h, l);
    H[idx] = h; L[idx] = l;
}

__global__ __launch_bounds__(256)
void reduce_refined(const float* __restrict__ Ppart, const float* __restrict__ spart,
                    const float* __restrict__ qe, float* __restrict__ refined,
                    int CH, int NB)
{
    const int q = blockIdx.x;
    const int d = threadIdx.x;
    __shared__ float sh[256];
    float s = 0.f;
    for (int i = d; i < NB; i += 256) s += spart[(size_t)i * 128 + q];
    sh[d] = s;
    __syncthreads();
    for (int o = 128; o; o >>= 1) {
        if (d < o) sh[d] += sh[d + o];
        __syncthreads();
    }
    const float stot = sh[0];
    // MLP-4 chunk reduction (independent accumulators)
    float p0 = 0.f, p1 = 0.f, p2 = 0.f, p3 = 0.f;
    for (int c = 0; c < CH; c += 4) {
        p0 += Ppart[((size_t)(c + 0) * 128 + q) * 256 + d];
        p1 += Ppart[((size_t)(c + 1) * 128 + q) * 256 + d];
        p2 += Ppart[((size_t)(c + 2) * 128 + q) * 256 + d];
        p3 += Ppart[((size_t)(c + 3) * 128 + q) * 256 + d];
    }
    refined[(size_t)q * 256 + d] = qe[(size_t)q * 256 + d] + ((p0 + p1) + (p2 + p3)) / stot;
}

__global__ __launch_bounds__(256)
void score_kernel(const float* __restrict__ A2s, const float* __restrict__ w2,
                  const float* __restrict__ b2, float* __restrict__ out)
{
    const int q = blockIdx.x;
    const int d = threadIdx.x;
    __shared__ float sh[256];
    sh[d] = A2s[(size_t)q * 256 + d] * w2[d];
    __syncthreads();
    for (int o = 128; o; o >>= 1) {
        if (d < o) sh[d] += sh[d + o];
        __syncthreads();
    }
    if (d == 0) out[q] = sh[0] + b2[0];
}

// ---------------------------------------------------------------------------
extern "C" void kernel_launch(void* const* d_in, const int* in_sizes, int n_in,
                              void* d_out, int out_size)
{
    const float* point_feat = (const float*)d_in[0];
    const float* ip_w1 = (const float*)d_in[1];
    const float* ip_b1 = (const float*)d_in[2];
    const float* ip_ln_g = (const float*)d_in[3];
    const float* ip_ln_b = (const float*)d_in[4];
    const float* ip_w2 = (const float*)d_in[5];
    const float* ip_b2 = (const float*)d_in[6];
    const float* ph_ln_g = (const float*)d_in[7];
    const float* ph_ln_b = (const float*)d_in[8];
    const float* ph_w1 = (const float*)d_in[9];
    const float* ph_b1 = (const float*)d_in[10];
    const float* ph_w2 = (const float*)d_in[11];
    const float* ph_b2 = (const float*)d_in[12];
    const float* q_embed = (const float*)d_in[13];
    const float* qh_ln_g = (const float*)d_in[14];
    const float* qh_ln_b = (const float*)d_in[15];
    const float* qh_w1 = (const float*)d_in[16];
    const float* qh_b1 = (const float*)d_in[17];
    const float* qh_w2 = (const float*)d_in[18];
    const float* qh_b2 = (const float*)d_in[19];
    const float* sh_ln_g = (const float*)d_in[20];
    const float* sh_ln_b = (const float*)d_in[21];
    const float* sh_w1 = (const float*)d_in[22];
    const float* sh_b1 = (const float*)d_in[23];
    const float* sh_w2 = (const float*)d_in[24];
    const float* sh_b2 = (const float*)d_in[25];
    const float* logit_scale = (const float*)d_in[26];

    const int N = in_sizes[0] / 72;

    float* out = (float*)d_out;
    const size_t offScore = (size_t)128 * N;
    const size_t offPE = offScore + 128;
    const size_t offRef = offPE + (size_t)N * 256;
    float* mask = out;
    float* score = out + offScore;
    float* pe = out + offPE;
    float* refined = out + offRef;

    __nv_bfloat16 *pfH, *pfL, *xH, *xL, *aH, *aL, *hH, *hL, *peH, *peL, *emH;
    __nv_bfloat16 *w1H, *w1L, *w2H, *w2L, *w3H, *w3L, *w4H, *w4L, *qmH, *qmL;
    float *invpe, *meanQ, *rstdQ, *A2q, *qe, *invq, *spart, *Ppart;
    cudaGetSymbolAddress((void**)&pfH, g_pfH); cudaGetSymbolAddress((void**)&pfL, g_pfL);
    cudaGetSymbolAddress((void**)&xH, g_xH);   cudaGetSymbolAddress((void**)&xL, g_xL);
    cudaGetSymbolAddress((void**)&aH, g_aH);   cudaGetSymbolAddress((void**)&aL, g_aL);
    cudaGetSymbolAddress((void**)&hH, g_hH);   cudaGetSymbolAddress((void**)&hL, g_hL);
    cudaGetSymbolAddress((void**)&peH, g_peH); cudaGetSymbolAddress((void**)&peL, g_peL);
    cudaGetSymbolAddress((void**)&emH, g_emH);
    cudaGetSymbolAddress((void**)&w1H, g_w1H); cudaGetSymbolAddress((void**)&w1L, g_w1L);
    cudaGetSymbolAddress((void**)&w2H, g_w2H); cudaGetSymbolAddress((void**)&w2L, g_w2L);
    cudaGetSymbolAddress((void**)&w3H, g_w3H); cudaGetSymbolAddress((void**)&w3L, g_w3L);
    cudaGetSymbolAddress((void**)&w4H, g_w4H); cudaGetSymbolAddress((void**)&w4L, g_w4L);
    cudaGetSymbolAddress((void**)&qmH, g_qmH); cudaGetSymbolAddress((void**)&qmL, g_qmL);
    cudaGetSymbolAddress((void**)&invpe, g_invpe);
    cudaGetSymbolAddress((void**)&meanQ, g_meanQ); cudaGetSymbolAddress((void**)&rstdQ, g_rstdQ);
    cudaGetSymbolAddress((void**)&A2q, g_A2q); cudaGetSymbolAddress((void**)&qe, g_qe);
    cudaGetSymbolAddress((void**)&invq, g_invq);
    cudaGetSymbolAddress((void**)&spart, g_spart); cudaGetSymbolAddress((void**)&Ppart, g_Ppart);

    // dynamic smem opt-in
    const int SMEM_BT0 = 2 * (16384 + 2 * 9216) + 2048;   // 71680
    const int SMEM_BT1 = 2 * (16384 + 2 * 8192) + 2048;   // 67584
    cudaFuncSetAttribute(tpair256<EPI_BIAS | EPI_LNPAIR | EPI_LNGELU>,
                         cudaFuncAttributeMaxDynamicSharedMemorySize, SMEM256);
    cudaFuncSetAttribute(tpair<EPI_BIAS | EPI_OUTPAIR, 0>,
                         cudaFuncAttributeMaxDynamicSharedMemorySize, SMEM_BT0);
    cudaFuncSetAttribute(tpair<EPI_BIAS | EPI_GELU | EPI_OUTPAIR, 0>,
                         cudaFuncAttributeMaxDynamicSharedMemorySize, SMEM_BT0);
    cudaFuncSetAttribute(tpair<EPI_BIAS | EPI_RESIDP | EPI_OUTF32 | EPI_OUTPAIR | EPI_SSQ, 0>,
                         cudaFuncAttributeMaxDynamicSharedMemorySize, SMEM_BT0);
    cudaFuncSetAttribute(tpair<EPI_CSCALE | EPI_OUTF32 | EPI_EXP1 | EPI_SPART, 1>,
                         cudaFuncAttributeMaxDynamicSharedMemorySize, SMEM_BT1);
    cudaFuncSetAttribute(tpair<EPI_OUTF32, 0, 1>,
                         cudaFuncAttributeMaxDynamicSharedMemorySize, SMEM_BT0);

    // -------- preps --------
    prep_pf<<<(N * 12 + 255) / 256, 256>>>(point_feat, pfH, pfL, N);
    prep_wT<<<12, 256>>>(ip_w1, w1H, w1L, 96, 72);
    prep_w<<<32, 256>>>(ip_w2, w2H, w2L, 256, 256);
    prep_w<<<32, 256>>>(ph_w1, w3H, w3L, 256, 256);
    prep_w<<<32, 256>>>(ph_w2, w4H, w4L, 256, 256);

    const dim3 gBig(N / 128, 2);

    // -------- point pipeline --------
    // a = gelu(LN(pf @ ip_w1 + ip_b1))  (fused; verified)
    tpair256<EPI_BIAS | EPI_LNPAIR | EPI_LNGELU><<<N / 128, 512, SMEM256>>>(
        pfH, pfL, 96, w1H, w1L, 96, ip_b1,
        nullptr, 0, nullptr, nullptr, aH, aL,
        nullptr, nullptr, ip_ln_g, ip_ln_b, nullptr, 96);
    // h = a @ ip_w2 + ip_b2 (pairs)
    tpair<EPI_BIAS | EPI_OUTPAIR, 0><<<gBig, 256, SMEM_BT0>>>(
        aH, aL, 256, w2H, w2L, 256, ip_b2,
        nullptr, 0, 0, hH, hL, 256, nullptr, nullptr, nullptr, nullptr, 0, 256);
    // a = LN(h) (pairs)
    lnprep<false><<<N / 8, 256>>>(hH, hL, ph_ln_g, ph_ln_b, aH, aL, N);
    // x = gelu(a @ ph_w1 + ph_b1) (pairs)
    tpair<EPI_BIAS | EPI_GELU | EPI_OUTPAIR, 0><<<gBig, 256, SMEM_BT0>>>(
        aH, aL, 256, w3H, w3L, 256, ph_b1,
        nullptr, 0, 0, xH, xL, 256, nullptr, nullptr, nullptr, nullptr, 0, 256);
    // pe = h + x @ ph_w2 + ph_b2 (fp32 to d_out + pairs + fused row-SSQ)
    tpair<EPI_BIAS | EPI_RESIDP | EPI_OUTF32 | EPI_OUTPAIR | EPI_SSQ, 0><<<gBig, 256, SMEM_BT0>>>(
        xH, xL, 256, w4H, w4L, 256, ph_b2,
        pe, 256, 0, peH, peL, 256, hH, hL, nullptr, spart, (size_t)N, 256);
    combine_ssq<<<(N + 255) / 256, 256>>>(spart, invpe, N);

    // -------- query pipeline (legacy, tiny) --------
    ln_stats<<<16, 256>>>(q_embed, meanQ, rstdQ, 128);
    tlegacy<AOP_LN, LEPI_BIAS | LEPI_GELU><<<dim3(1, 2), 256>>>(
        q_embed, 256, qh_w1, 256, qh_b1, A2q, 256, 256,
        meanQ, rstdQ, qh_ln_g, qh_ln_b, nullptr);
    tlegacy<AOP_ID, LEPI_BIAS | LEPI_RESID><<<dim3(1, 2), 256>>>(
        A2q, 256, qh_w2, 256, qh_b2, qe, 256, 256,
        nullptr, nullptr, nullptr, nullptr, q_embed);
    rownorm<<<16, 256>>>(qe, invq, 128);
    qmpair<<<128, 256>>>(qe, invq, logit_scale, qmH, qmL);

    // -------- mask logits + single-bf16 em + CONSISTENT softmax partials ----
    tpair<EPI_CSCALE | EPI_OUTF32 | EPI_EXP1 | EPI_SPART, 1><<<dim3(1, N / 128), 256, SMEM_BT1>>>(
        qmH, qmL, 256, peH, peL, 256, nullptr,
        mask, (size_t)N, 0, emH, nullptr, (size_t)N, nullptr, nullptr, invpe, spart, 128, 256);

    // -------- weighted aggregation (2-term, A-single), z=128 ---------------
    tpair<EPI_OUTF32, 0, 1><<<dim3(1, 2, 128), 256, SMEM_BT0>>>(
        emH, nullptr, N, peH, peL, 256, nullptr,
        Ppart, 256, (size_t)128 * 256, nullptr, nullptr, 0,
        nullptr, nullptr, nullptr, nullptr, 0, 2048);
    reduce_refined<<<128, 256>>>(Ppart, spart, qe, refined, 128, N / 128);

    // -------- score head (legacy) --------
    ln_stats<<<16, 256>>>(refined, meanQ, rstdQ, 128);
    tlegacy<AOP_LN, LEPI_BIAS | LEPI_GELU><<<dim3(1, 2), 256>>>(
        refined, 256, sh_w1, 256, sh_b1, A2q, 256, 256,
        meanQ, rstdQ, sh_ln_g, sh_ln_b, nullptr);
    score_kernel<<<128, 256>>>(A2q, sh_w2, sh_b2, score);
}

// round 16
// speedup vs baseline: 1.1264x; 1.0083x over previous
#include <cuda_runtime.h>
#include <cuda_bf16.h>
#include <math.h>
#include <stdint.h>

// ---------------------------------------------------------------------------
// QueryInstanceDecoder: bf16 split-precision mma.sync pipeline, v9.
// = v8 (best passing) + merged weight preps (1 launch), fused rownorm+qmpair,
//   combine_ssq folded into the mask epilogue (EPI_CSSQ).
// N=262144, C_IN=72, D=256, Q=128.
// d_out (floats): mask_logits[128*N] | score[128] | point_embed[N*256] | refined[128*256]
// ---------------------------------------------------------------------------

#define DEVI __device__ __forceinline__

DEVI float geluf(float x) { return 0.5f * x * (1.0f + erff(x * 0.70710678118654752f)); }

DEVI unsigned pack2(__nv_bfloat16 a, __nv_bfloat16 b) {
    return (unsigned)__bfloat16_as_ushort(a) | ((unsigned)__bfloat16_as_ushort(b) << 16);
}
DEVI void split2(float x, __nv_bfloat16& h, __nv_bfloat16& l) {
    h = __float2bfloat16(x);
    l = __float2bfloat16(x - __bfloat162float(h));
}
DEVI float upk_lo(unsigned u) { return __bfloat162float(__ushort_as_bfloat16((unsigned short)(u & 0xffff))); }
DEVI float upk_hi(unsigned u) { return __bfloat162float(__ushort_as_bfloat16((unsigned short)(u >> 16))); }

DEVI void mma16816(float* c, const unsigned* a, const unsigned* b) {
    asm volatile(
        "mma.sync.aligned.m16n8k16.row.col.f32.bf16.bf16.f32 "
        "{%0,%1,%2,%3},{%4,%5,%6,%7},{%8,%9},{%0,%1,%2,%3};"
        : "+f"(c[0]), "+f"(c[1]), "+f"(c[2]), "+f"(c[3])
        : "r"(a[0]), "r"(a[1]), "r"(a[2]), "r"(a[3]), "r"(b[0]), "r"(b[1]));
}
DEVI uint32_t smem_u32(const void* p) {
    uint32_t a;
    asm("{ .reg .u64 t; cvta.to.shared.u64 t, %1; cvt.u32.u64 %0, t; }" : "=r"(a) : "l"(p));
    return a;
}
#define LDSM4(r, a) \
    asm volatile("ldmatrix.sync.aligned.m8n8.x4.shared.b16 {%0,%1,%2,%3},[%4];" \
        : "=r"((r)[0]), "=r"((r)[1]), "=r"((r)[2]), "=r"((r)[3]) : "r"(a))
#define LDSM4T(r, a) \
    asm volatile("ldmatrix.sync.aligned.m8n8.x4.trans.shared.b16 {%0,%1,%2,%3},[%4];" \
        : "=r"((r)[0]), "=r"((r)[1]), "=r"((r)[2]), "=r"((r)[3]) : "r"(a))

DEVI void cpasync16(uint32_t dst, const void* src) {
    asm volatile("cp.async.cg.shared.global [%0], [%1], 16;" :: "r"(dst), "l"(src));
}
DEVI void cpcommit() { asm volatile("cp.async.commit_group;"); }
DEVI void cpwait1()  { asm volatile("cp.async.wait_group 1;"); }
DEVI void cpwait0()  { asm volatile("cp.async.wait_group 0;"); }

#define SWZ(o) ((unsigned)(o) ^ ((((unsigned)(o)) >> 3) & 0x70))
#define BSTRIDE0 288

// ---------------- scratch (static device memory; no allocations) -----------
#define NMAX 262144
__device__ __nv_bfloat16 g_pfH[(size_t)NMAX * 96], g_pfL[(size_t)NMAX * 96];
__device__ __nv_bfloat16 g_xH[(size_t)NMAX * 256], g_xL[(size_t)NMAX * 256];
__device__ __nv_bfloat16 g_aH[(size_t)NMAX * 256], g_aL[(size_t)NMAX * 256];
__device__ __nv_bfloat16 g_hH[(size_t)NMAX * 256], g_hL[(size_t)NMAX * 256];
__device__ __nv_bfloat16 g_peH[(size_t)NMAX * 256], g_peL[(size_t)NMAX * 256];
__device__ __nv_bfloat16 g_emH[(size_t)128 * NMAX];
__device__ __nv_bfloat16 g_w1H[96 * 256], g_w1L[96 * 256];     // [n=256][k=96] transposed
__device__ __nv_bfloat16 g_w2H[256 * 256], g_w2L[256 * 256];   // [k][n]
__device__ __nv_bfloat16 g_w3H[256 * 256], g_w3L[256 * 256];
__device__ __nv_bfloat16 g_w4H[256 * 256], g_w4L[256 * 256];
__device__ __nv_bfloat16 g_qmH[128 * 256], g_qmL[128 * 256];
__device__ float g_meanQ[128], g_rstdQ[128];
__device__ float g_A2q[128 * 256];
__device__ float g_qe[128 * 256];
__device__ float g_spart[(size_t)2 * NMAX];          // GEMM4 row-SSQ partials [2][N]
__device__ float g_mpart[NMAX];                      // mask em-sum partials [N/128][128]
__device__ float g_Ppart[256 * 128 * 256];

// ---------------- epilogue flags --------------------------------------------
#define EPI_BIAS    1
#define EPI_GELU    2
#define EPI_RESIDP  4
#define EPI_OUTF32  8
#define EPI_OUTPAIR 16
#define EPI_SPART   32
#define EPI_CSCALE  64
#define EPI_SSQ     256
#define EPI_LNPAIR  512
#define EPI_LNGELU  1024
#define EPI_EXP1    2048    // store bf16(exp(v)) single; spart from ROUNDED values
#define EPI_CSSQ    4096    // column scale computed inline from SSQ partials (cscale = ssqp, size 2*ldout)

// =============================================================================
// tpair256: C[128x256] = A_pairs @ B_pairs^T (B image [n][k]). 512 threads,
// 16 warps (2x8), warp 64x32, 2-stage cp.async. Used only for GEMM1 (K=96).
// =============================================================================
#define STG256 49152
#define SP_OFF (2 * STG256)
#define SMEM256 (SP_OFF + 4096 + 4096 + 512 + 512 + 1024 + 1024)

template <int EPI>
__global__ __launch_bounds__(512, 1)
void tpair256(const __nv_bfloat16* __restrict__ Ah, const __nv_bfloat16* __restrict__ Al, int lda,
              const __nv_bfloat16* __restrict__ Bh, const __nv_bfloat16* __restrict__ Bl, int ldb,
              const float* __restrict__ bias,
              float* __restrict__ outf, size_t ldout,
              __nv_bfloat16* __restrict__ oh, __nv_bfloat16* __restrict__ ol,
              __nv_bfloat16* __restrict__ o2h, __nv_bfloat16* __restrict__ o2l,
              const __nv_bfloat16* __restrict__ resH, const __nv_bfloat16* __restrict__ resL,
              const float* __restrict__ gam, const float* __restrict__ bet,
              float* __restrict__ invout, int Kblk)
{
    extern __shared__ __align__(1024) unsigned char sm[];
    const uint32_t sb = smem_u32(sm);
    float* spS  = (float*)(sm + SP_OFF);
    float* spSS = (float*)(sm + SP_OFF + 4096);
    float* marr = (float*)(sm + SP_OFF + 8192);
    float* rarr = (float*)(sm + SP_OFF + 8704);
    float* sgam = (float*)(sm + SP_OFF + 9216);
    float* sbet = (float*)(sm + SP_OFF + 10240);

    const int tid  = threadIdx.x;
    const int row0 = blockIdx.x * 128;
    const int nch  = Kblk >> 5;

    if (EPI & EPI_LNPAIR) {
        if (tid < 256) { sgam[tid] = gam[tid]; sbet[tid] = bet[tid]; }
    }

    const int arow = tid >> 2, ak0 = (tid & 3) * 8;
    const int brow = tid >> 1, bk0 = (tid & 1) * 16;
    const unsigned dA  = SWZ(arow * 64 + ak0 * 2);
    const unsigned dB  = SWZ(brow * 64 + bk0 * 2);
    const unsigned dB2 = SWZ(brow * 64 + bk0 * 2 + 16);
    const __nv_bfloat16* ApH = Ah + (size_t)(row0 + arow) * lda + ak0;
    const __nv_bfloat16* ApL = Al + (size_t)(row0 + arow) * lda + ak0;
    const __nv_bfloat16* BpH = Bh + (size_t)brow * ldb + bk0;
    const __nv_bfloat16* BpL = Bl + (size_t)brow * ldb + bk0;

    auto issue = [&](int c) {
        const int kc = c * 32;
        const uint32_t st = sb + (c & 1) * STG256;
        cpasync16(st + dA, ApH + kc);
        cpasync16(st + 8192 + dA, ApL + kc);
        cpasync16(st + 16384 + dB,  BpH + kc);
        cpasync16(st + 16384 + dB2, BpH + kc + 8);
        cpasync16(st + 32768 + dB,  BpL + kc);
        cpasync16(st + 32768 + dB2, BpL + kc + 8);
        cpcommit();
    };

    const int lane = tid & 31, w = tid >> 5;
    const int mw = w >> 3, nw = w & 7;
    const int g = lane >> 2, tig = lane & 3;
    const int lrow = (lane & 7) + ((lane >> 3) & 1) * 8;
    const int lkh  = (lane >> 4) * 16;

    float acc[4][4][4];
#pragma unroll
    for (int mi = 0; mi < 4; mi++)
#pragma unroll
        for (int ni = 0; ni < 4; ni++)
#pragma unroll
            for (int e = 0; e < 4; e++) acc[mi][ni][e] = 0.f;

    auto compute = [&](int c) {
        const uint32_t st = sb + (c & 1) * STG256;
#pragma unroll
        for (int ks = 0; ks < 2; ks++) {
            unsigned ah[4][4], al[4][4];
#pragma unroll
            for (int mi = 0; mi < 4; mi++) {
                const int r = mw * 64 + mi * 16 + lrow;
                const unsigned off = SWZ(r * 64 + ks * 32 + lkh);
                LDSM4(ah[mi], st + off);
                LDSM4(al[mi], st + 8192 + off);
            }
#pragma unroll
            for (int nb = 0; nb < 2; nb++) {
                unsigned bh[4], bl[4];
                const int n = nw * 32 + nb * 16 + lrow;
                const unsigned off = SWZ(n * 64 + ks * 32 + lkh);
                LDSM4(bh, st + 16384 + off);
                LDSM4(bl, st + 32768 + off);
                unsigned beh[2] = {bh[0], bh[2]}, boh[2] = {bh[1], bh[3]};
                unsigned bel[2] = {bl[0], bl[2]}, bol[2] = {bl[1], bl[3]};
#pragma unroll
                for (int mi = 0; mi < 4; mi++) mma16816(acc[mi][2 * nb],     ah[mi], beh);
#pragma unroll
                for (int mi = 0; mi < 4; mi++) mma16816(acc[mi][2 * nb + 1], ah[mi], boh);
#pragma unroll
                for (int mi = 0; mi < 4; mi++) mma16816(acc[mi][2 * nb],     ah[mi], bel);
#pragma unroll
                for (int mi = 0; mi < 4; mi++) mma16816(acc[mi][2 * nb + 1], ah[mi], bol);
#pragma unroll
                for (int mi = 0; mi < 4; mi++) mma16816(acc[mi][2 * nb],     al[mi], beh);
#pragma unroll
                for (int mi = 0; mi < 4; mi++) mma16816(acc[mi][2 * nb + 1], al[mi], boh);
            }
        }
    };

    issue(0);
    for (int c = 0; c < nch; c++) {
        if (c + 1 < nch) { issue(c + 1); cpwait1(); } else { cpwait0(); }
        __syncthreads();
        compute(c);
        __syncthreads();
    }

    // pass A: finalize, stats
    float sS0[4], sS1[4], sSS0[4], sSS1[4];
#pragma unroll
    for (int mi = 0; mi < 4; mi++) { sS0[mi] = sS1[mi] = sSS0[mi] = sSS1[mi] = 0.f; }

#pragma unroll
    for (int mi = 0; mi < 4; mi++) {
        const int r = row0 + mw * 64 + mi * 16 + g;
#pragma unroll
        for (int ni = 0; ni < 4; ni++) {
            const int colG = nw * 32 + ni * 8 + 2 * tig;
            float v0 = acc[mi][ni][0], v1 = acc[mi][ni][1];
            float v2 = acc[mi][ni][2], v3 = acc[mi][ni][3];
            if (EPI & EPI_BIAS) {
                float2 bb = *(const float2*)(bias + colG);
                v0 += bb.x; v1 += bb.y; v2 += bb.x; v3 += bb.y;
            }
            if (EPI & EPI_GELU) {
                v0 = geluf(v0); v1 = geluf(v1); v2 = geluf(v2); v3 = geluf(v3);
            }
            if (EPI & EPI_RESIDP) {
                unsigned uh0 = *(const unsigned*)(resH + (size_t)r * 256 + colG);
                unsigned ul0 = *(const unsigned*)(resL + (size_t)r * 256 + colG);
                unsigned uh1 = *(const unsigned*)(resH + (size_t)(r + 8) * 256 + colG);
                unsigned ul1 = *(const unsigned*)(resL + (size_t)(r + 8) * 256 + colG);
                v0 += upk_lo(uh0) + upk_lo(ul0); v1 += upk_hi(uh0) + upk_hi(ul0);
                v2 += upk_lo(uh1) + upk_lo(ul1); v3 += upk_hi(uh1) + upk_hi(ul1);
            }
            if (EPI & EPI_OUTF32) {
                *(float2*)(outf + (size_t)r * ldout + colG)       = make_float2(v0, v1);
                *(float2*)(outf + (size_t)(r + 8) * ldout + colG) = make_float2(v2, v3);
            }
            if (EPI & EPI_LNPAIR) { sS0[mi] += v0 + v1; sS1[mi] += v2 + v3; }
            if (EPI & (EPI_SSQ | EPI_LNPAIR)) {
                sSS0[mi] += v0 * v0 + v1 * v1;
                sSS1[mi] += v2 * v2 + v3 * v3;
            }
            acc[mi][ni][0] = v0; acc[mi][ni][1] = v1;
            acc[mi][ni][2] = v2; acc[mi][ni][3] = v3;
        }
    }

    if (EPI & (EPI_SSQ | EPI_LNPAIR)) {
#pragma unroll
        for (int mi = 0; mi < 4; mi++) {
            float a0 = sS0[mi], a1 = sS1[mi], b0 = sSS0[mi], b1 = sSS1[mi];
            a0 += __shfl_xor_sync(0xffffffffu, a0, 1); a0 += __shfl_xor_sync(0xffffffffu, a0, 2);
            a1 += __shfl_xor_sync(0xffffffffu, a1, 1); a1 += __shfl_xor_sync(0xffffffffu, a1, 2);
            b0 += __shfl_xor_sync(0xffffffffu, b0, 1); b0 += __shfl_xor_sync(0xffffffffu, b0, 2);
            b1 += __shfl_xor_sync(0xffffffffu, b1, 1); b1 += __shfl_xor_sync(0xffffffffu, b1, 2);
            if (tig == 0) {
                const int lr = mw * 64 + mi * 16 + g;
                spS[nw * 128 + lr]      = a0;
                spS[nw * 128 + lr + 8]  = a1;
                spSS[nw * 128 + lr]     = b0;
                spSS[nw * 128 + lr + 8] = b1;
            }
        }
        __syncthreads();
        if (tid < 128) {
            float s = 0.f, ss = 0.f;
#pragma unroll
            for (int ww = 0; ww < 8; ww++) {
                s  += spS[ww * 128 + tid];
                ss += spSS[ww * 128 + tid];
            }
            if (EPI & EPI_LNPAIR) {
                float m = s * (1.0f / 256.0f);
                marr[tid] = m;
                rarr[tid] = rsqrtf(ss * (1.0f / 256.0f) - m * m + 1e-5f);
            }
            if (EPI & EPI_SSQ)
                invout[row0 + tid] = 1.0f / fmaxf(sqrtf(ss), 1e-12f);
        }
        __syncthreads();
    }

    if (EPI & (EPI_OUTPAIR | EPI_LNPAIR)) {
#pragma unroll
        for (int mi = 0; mi < 4; mi++) {
            const int lr = mw * 64 + mi * 16 + g;
            const int r = row0 + lr;
            float m0 = 0.f, r0 = 0.f, m1 = 0.f, r1 = 0.f;
            if (EPI & EPI_LNPAIR) {
                m0 = marr[lr]; r0 = rarr[lr];
                m1 = marr[lr + 8]; r1 = rarr[lr + 8];
            }
#pragma unroll
            for (int ni = 0; ni < 4; ni++) {
                const int colG = nw * 32 + ni * 8 + 2 * tig;
                float v0 = acc[mi][ni][0], v1 = acc[mi][ni][1];
                float v2 = acc[mi][ni][2], v3 = acc[mi][ni][3];
                if (EPI & EPI_OUTPAIR) {
                    __nv_bfloat16 h0, l0, h1, l1;
                    split2(v0, h0, l0); split2(v1, h1, l1);
                    *(unsigned*)(oh + (size_t)r * 256 + colG) = pack2(h0, h1);
                    *(unsigned*)(ol + (size_t)r * 256 + colG) = pack2(l0, l1);
                    split2(v2, h0, l0); split2(v3, h1, l1);
                    *(unsigned*)(oh + (size_t)(r + 8) * 256 + colG) = pack2(h0, h1);
                    *(unsigned*)(ol + (size_t)(r + 8) * 256 + colG) = pack2(l0, l1);
                }
                if (EPI & EPI_LNPAIR) {
                    const float g0 = sgam[colG], g1 = sgam[colG + 1];
                    const float b0 = sbet[colG], b1 = sbet[colG + 1];
                    float t0 = (v0 - m0) * r0 * g0 + b0;
                    float t1 = (v1 - m0) * r0 * g1 + b1;
                    float t2 = (v2 - m1) * r1 * g0 + b0;
                    float t3 = (v3 - m1) * r1 * g1 + b1;
                    if (EPI & EPI_LNGELU) {
                        t0 = geluf(t0); t1 = geluf(t1); t2 = geluf(t2); t3 = geluf(t3);
                    }
                    __nv_bfloat16 h0, l0, h1, l1;
                    split2(t0, h0, l0); split2(t1, h1, l1);
                    *(unsigned*)(o2h + (size_t)r * 256 + colG) = pack2(h0, h1);
                    *(unsigned*)(o2l + (size_t)r * 256 + colG) = pack2(l0, l1);
                    split2(t2, h0, l0); split2(t3, h1, l1);
                    *(unsigned*)(o2h + (size_t)(r + 8) * 256 + colG) = pack2(h0, h1);
                    *(unsigned*)(o2l + (size_t)(r + 8) * 256 + colG) = pack2(l0, l1);
                }
            }
        }
    }
}

// =============================================================================
// R9 pair GEMM (2-stage, 2 CTAs/SM). AS=1: A-single image (2-term split).
// Term-major MMA ordering. EPI_CSSQ: inline column inv-norm from SSQ partials.
// =============================================================================
template <int EPI, int BT, int AS = 0>
__global__ __launch_bounds__(256, 2)
void tpair(const __nv_bfloat16* __restrict__ Ah, const __nv_bfloat16* __restrict__ Al, int lda,
           const __nv_bfloat16* __restrict__ Bh, const __nv_bfloat16* __restrict__ Bl, int ldb,
           const float* __restrict__ bias,
           float* __restrict__ outf, size_t ldout, size_t zstride,
           __nv_bfloat16* __restrict__ oh, __nv_bfloat16* __restrict__ ol, size_t opitch,
           const __nv_bfloat16* __restrict__ resH, const __nv_bfloat16* __restrict__ resL,
           const float* __restrict__ cscale, float* __restrict__ spart, size_t spitch,
           int Kblk)
{
    constexpr int BSZ = BT ? 8192 : 9216;
    constexpr int STG = 16384 + 2 * BSZ;
    extern __shared__ __align__(1024) unsigned char sm[];
    const uint32_t sb = smem_u32(sm);
    float* sp = (float*)(sm + 2 * STG);

    const int tid  = threadIdx.x;
    const int row0 = blockIdx.x * 128;
    const int col0 = blockIdx.y * 128;
    const int kz   = blockIdx.z * Kblk;
    const int nch  = Kblk >> 5;

    const int arow = tid >> 1, ak0 = (tid & 1) * 16;
    const int brow = tid >> 1, bk0 = (tid & 1) * 16;
    const int bkr = tid >> 3, bn0 = (tid & 7) * 16;
    const unsigned dA  = SWZ(arow * 64 + ak0 * 2);
    const unsigned dA2 = SWZ(arow * 64 + ak0 * 2 + 16);
    const unsigned dB  = BT ? SWZ(brow * 64 + bk0 * 2)      : SWZ(bkr * BSTRIDE0 + bn0 * 2);
    const unsigned dB2 = BT ? SWZ(brow * 64 + bk0 * 2 + 16) : SWZ(bkr * BSTRIDE0 + bn0 * 2 + 16);
    const __nv_bfloat16* ApH = Ah + (size_t)(row0 + arow) * lda + kz + ak0;
    const __nv_bfloat16* ApL = AS ? nullptr : Al + (size_t)(row0 + arow) * lda + kz + ak0;
    const __nv_bfloat16* BpH = BT ? Bh + (size_t)(col0 + brow) * ldb + kz + bk0
                                  : Bh + (size_t)(kz + bkr) * ldb + col0 + bn0;
    const __nv_bfloat16* BpL = BT ? Bl + (size_t)(col0 + brow) * ldb + kz + bk0
                                  : Bl + (size_t)(kz + bkr) * ldb + col0 + bn0;

    auto issue = [&](int c) {
        const int kc = c * 32;
        const uint32_t st = sb + (c & 1) * STG;
        cpasync16(st + dA, ApH + kc);            cpasync16(st + dA2, ApH + kc + 8);
        if (!AS) {
            cpasync16(st + 8192 + dA, ApL + kc);
            cpasync16(st + 8192 + dA2, ApL + kc + 8);
        }
        const size_t boff = BT ? (size_t)kc : (size_t)kc * ldb;
        cpasync16(st + 16384 + dB, BpH + boff);        cpasync16(st + 16384 + dB2, BpH + boff + 8);
        cpasync16(st + 16384 + BSZ + dB, BpL + boff);  cpasync16(st + 16384 + BSZ + dB2, BpL + boff + 8);
        cpcommit();
    };

    const int lane = tid & 31, w = tid >> 5;
    const int mw = w >> 2, nw = w & 3;
    const int g = lane >> 2, tig = lane & 3;
    const int lrow = (lane & 7) + ((lane >> 3) & 1) * 8;
    const int lkh  = (lane >> 4) * 16;
    const int trow = (lane & 7) + ((lane >> 4) & 1) * 8;
    const int tnh  = ((lane >> 3) & 1) * 16;

    float acc[4][4][4];
#pragma unroll
    for (int mi = 0; mi < 4; mi++)
#pragma unroll
        for (int ni = 0; ni < 4; ni++)
#pragma unroll
            for (int e = 0; e < 4; e++) acc[mi][ni][e] = 0.f;

    auto compute = [&](int c) {
        const uint32_t st = sb + (c & 1) * STG;
#pragma unroll
        for (int ks = 0; ks < 2; ks++) {
            unsigned ah[4][4], al[4][4];
#pragma unroll
            for (int mi = 0; mi < 4; mi++) {
                const int r = mw * 64 + mi * 16 + lrow;
                const unsigned off = SWZ(r * 64 + ks * 32 + lkh);
                LDSM4(ah[mi], st + off);
                if (!AS) LDSM4(al[mi], st + 8192 + off);
            }
#pragma unroll
            for (int nb = 0; nb < 2; nb++) {
                unsigned bh[4], bl[4];
                if (BT) {
                    const int n = nw * 32 + nb * 16 + lrow;
                    const unsigned off = SWZ(n * 64 + ks * 32 + lkh);
                    LDSM4(bh, st + 16384 + off);
                    LDSM4(bl, st + 16384 + BSZ + off);
                } else {
                    const int kr = ks * 16 + trow;
                    const unsigned off = SWZ(kr * BSTRIDE0 + (nw * 32 + nb * 16) * 2 + tnh);
                    LDSM4T(bh, st + 16384 + off);
                    LDSM4T(bl, st + 16384 + BSZ + off);
                }
                unsigned beh[2] = {bh[0], bh[2]}, boh[2] = {bh[1], bh[3]};
                unsigned bel[2] = {bl[0], bl[2]}, bol[2] = {bl[1], bl[3]};
#pragma unroll
                for (int mi = 0; mi < 4; mi++) mma16816(acc[mi][2 * nb],     ah[mi], beh);
#pragma unroll
                for (int mi = 0; mi < 4; mi++) mma16816(acc[mi][2 * nb + 1], ah[mi], boh);
#pragma unroll
                for (int mi = 0; mi < 4; mi++) mma16816(acc[mi][2 * nb],     ah[mi], bel);
#pragma unroll
                for (int mi = 0; mi < 4; mi++) mma16816(acc[mi][2 * nb + 1], ah[mi], bol);
                if (!AS) {
#pragma unroll
                    for (int mi = 0; mi < 4; mi++) mma16816(acc[mi][2 * nb],     al[mi], beh);
#pragma unroll
                    for (int mi = 0; mi < 4; mi++) mma16816(acc[mi][2 * nb + 1], al[mi], boh);
                }
            }
        }
    };

    issue(0);
    for (int c = 0; c < nch; c++) {
        if (c + 1 < nch) { issue(c + 1); cpwait1(); } else { cpwait0(); }
        __syncthreads();
        compute(c);
        __syncthreads();
    }

    float* outp = outf + (size_t)blockIdx.z * zstride;
    float srow0[4] = {0.f, 0.f, 0.f, 0.f}, srow1[4] = {0.f, 0.f, 0.f, 0.f};
#pragma unroll
    for (int mi = 0; mi < 4; mi++) {
        const int r = row0 + mw * 64 + mi * 16 + g;
#pragma unroll
        for (int ni = 0; ni < 4; ni++) {
            const int colG = col0 + nw * 32 + ni * 8 + 2 * tig;
            float v0 = acc[mi][ni][0], v1 = acc[mi][ni][1];
            float v2 = acc[mi][ni][2], v3 = acc[mi][ni][3];
            if (EPI & EPI_BIAS) {
                float2 bb = *(const float2*)(bias + colG);
                v0 += bb.x; v1 += bb.y; v2 += bb.x; v3 += bb.y;
            }
            if (EPI & EPI_GELU) {
                v0 = geluf(v0); v1 = geluf(v1); v2 = geluf(v2); v3 = geluf(v3);
            }
            if (EPI & EPI_RESIDP) {
                unsigned uh0 = *(const unsigned*)(resH + (size_t)r * 256 + colG);
                unsigned ul0 = *(const unsigned*)(resL + (size_t)r * 256 + colG);
                unsigned uh1 = *(const unsigned*)(resH + (size_t)(r + 8) * 256 + colG);
                unsigned ul1 = *(const unsigned*)(resL + (size_t)(r + 8) * 256 + colG);
                v0 += upk_lo(uh0) + upk_lo(ul0); v1 += upk_hi(uh0) + upk_hi(ul0);
                v2 += upk_lo(uh1) + upk_lo(ul1); v3 += upk_hi(uh1) + upk_hi(ul1);
            }
            if (EPI & EPI_CSCALE) {
                float2 cs = *(const float2*)(cscale + colG);
                v0 *= cs.x; v1 *= cs.y; v2 *= cs.x; v3 *= cs.y;
            }
            if (EPI & EPI_CSSQ) {
                // inline inv pe-norm from GEMM4's SSQ partials (cscale = ssqp[2][ldout])
                const float s0 = cscale[colG]     + cscale[ldout + colG];
                const float s1 = cscale[colG + 1] + cscale[ldout + colG + 1];
                const float i0 = 1.0f / fmaxf(sqrtf(s0), 1e-12f);
                const float i1 = 1.0f / fmaxf(sqrtf(s1), 1e-12f);
                v0 *= i0; v1 *= i1; v2 *= i0; v3 *= i1;
            }
            if (EPI & EPI_OUTF32) {
                *(float2*)(outp + (size_t)r * ldout + colG)       = make_float2(v0, v1);
                *(float2*)(outp + (size_t)(r + 8) * ldout + colG) = make_float2(v2, v3);
            }
            if (EPI & EPI_SSQ) {
                srow0[mi] += v0 * v0 + v1 * v1;
                srow1[mi] += v2 * v2 + v3 * v3;
            }
            if (EPI & EPI_EXP1) {
                __nv_bfloat16 h0 = __float2bfloat16(__expf(v0));
                __nv_bfloat16 h1 = __float2bfloat16(__expf(v1));
                __nv_bfloat16 h2 = __float2bfloat16(__expf(v2));
                __nv_bfloat16 h3 = __float2bfloat16(__expf(v3));
                if (EPI & EPI_SPART) {
                    srow0[mi] += __bfloat162float(h0) + __bfloat162float(h1);
                    srow1[mi] += __bfloat162float(h2) + __bfloat162float(h3);
                }
                *(unsigned*)(oh + (size_t)r * opitch + colG)       = pack2(h0, h1);
                *(unsigned*)(oh + (size_t)(r + 8) * opitch + colG) = pack2(h2, h3);
            }
            if (EPI & EPI_OUTPAIR) {
                __nv_bfloat16 h0, l0, h1, l1;
                split2(v0, h0, l0); split2(v1, h1, l1);
                *(unsigned*)(oh + (size_t)r * opitch + colG) = pack2(h0, h1);
                *(unsigned*)(ol + (size_t)r * opitch + colG) = pack2(l0, l1);
                split2(v2, h0, l0); split2(v3, h1, l1);
                *(unsigned*)(oh + (size_t)(r + 8) * opitch + colG) = pack2(h0, h1);
                *(unsigned*)(ol + (size_t)(r + 8) * opitch + colG) = pack2(l0, l1);
            }
        }
    }
    if (EPI & (EPI_SPART | EPI_SSQ)) {
        float (*spp)[128] = (float(*)[128])sp;
#pragma unroll
        for (int mi = 0; mi < 4; mi++) {
            float s0 = srow0[mi], s1 = srow1[mi];
            s0 += __shfl_xor_sync(0xffffffffu, s0, 1);
            s0 += __shfl_xor_sync(0xffffffffu, s0, 2);
            s1 += __shfl_xor_sync(0xffffffffu, s1, 1);
            s1 += __shfl_xor_sync(0xffffffffu, s1, 2);
            if (tig == 0) {
                spp[nw][mw * 64 + mi * 16 + g]     = s0;
                spp[nw][mw * 64 + mi * 16 + g + 8] = s1;
            }
        }
        __syncthreads();
        if (tid < 128)
            spart[(size_t)blockIdx.y * spitch + row0 + tid] =
                spp[0][tid] + spp[1][tid] + spp[2][tid] + spp[3][tid];
    }
}

// ---------------------------------------------------------------------------
// Legacy fp32-input GEMM (query/score path only). LN on A input only.
// ---------------------------------------------------------------------------
enum { AOP_ID = 0, AOP_LN = 1 };
#define LEPI_BIAS  1
#define LEPI_GELU  2
#define LEPI_RESID 4

template <int AOP, int EPI>
__global__ __launch_bounds__(256)
void tlegacy(const float* __restrict__ A, int lda,
             const float* __restrict__ B, int ldb,
             const float* __restrict__ bias,
             float* __restrict__ out, size_t ldout, int Kblk,
             const float* __restrict__ mean, const float* __restrict__ rstd,
             const float* __restrict__ lng, const float* __restrict__ lnb,
             const float* __restrict__ resid)
{
    __shared__ __align__(1024) unsigned char sm[16384 + 2 * 9216];
    const uint32_t sb = smem_u32(sm);
    const int tid = threadIdx.x;
    const int row0 = blockIdx.x * 128;
    const int col0 = blockIdx.y * 128;
    const int nch = Kblk >> 5;

    __shared__ float sgam[256], sbet[256];
    if (AOP == AOP_LN) {
        if (tid < Kblk) { sgam[tid] = lng[tid]; sbet[tid] = lnb[tid]; }
    }

    const int arow = tid >> 1, ak0 = (tid & 1) * 16;
    float mr = 0.f, rr = 0.f;
    if (AOP == AOP_LN) { mr = mean[row0 + arow]; rr = rstd[row0 + arow]; }
    const float* Ap = A + (size_t)(row0 + arow) * lda;
    const int bkr = tid >> 3, bn0 = (tid & 7) * 16;
    const float* Bp0 = B + (size_t)bkr * ldb + col0 + bn0;

    const int lane = tid & 31, w = tid >> 5;
    const int mw = w >> 2, nw = w & 3;
    const int g = lane >> 2, tig = lane & 3;
    const int lrow = (lane & 7) + ((lane >> 3) & 1) * 8;
    const int lkh = (lane >> 4) * 16;
    const int trow = (lane & 7) + ((lane >> 4) & 1) * 8;
    const int tnh = ((lane >> 3) & 1) * 16;

    float acc[4][4][4];
#pragma unroll
    for (int mi = 0; mi < 4; mi++)
#pragma unroll
        for (int ni = 0; ni < 4; ni++)
#pragma unroll
            for (int e = 0; e < 4; e++) acc[mi][ni][e] = 0.f;

    for (int c = 0; c < nch; c++) {
        const int kc = c * 32;
        __syncthreads();
#pragma unroll
        for (int i = 0; i < 4; i++) {
            float4 t = *(const float4*)(Ap + kc + ak0 + i * 4);
            float v[4] = {t.x, t.y, t.z, t.w};
            if (AOP == AOP_LN) {
#pragma unroll
                for (int j = 0; j < 4; j++) {
                    const int kg = kc + ak0 + i * 4 + j;
                    v[j] = (v[j] - mr) * rr * sgam[kg] + sbet[kg];
                }
            }
            const unsigned base = arow * 64 + (ak0 + i * 4) * 2;
            __nv_bfloat16 h0, l0, h1, l1;
            split2(v[0], h0, l0); split2(v[1], h1, l1);
            *(unsigned*)(sm + SWZ(base)) = pack2(h0, h1);
            *(unsigned*)(sm + 8192 + SWZ(base)) = pack2(l0, l1);
            split2(v[2], h0, l0); split2(v[3], h1, l1);
            *(unsigned*)(sm + SWZ(base + 4)) = pack2(h0, h1);
            *(unsigned*)(sm + 8192 + SWZ(base + 4)) = pack2(l0, l1);
        }
#pragma unroll
        for (int i = 0; i < 4; i++) {
            float4 t = *(const float4*)(Bp0 + (size_t)kc * ldb + i * 4);
            float v[4] = {t.x, t.y, t.z, t.w};
            const unsigned base = bkr * BSTRIDE0 + (bn0 + i * 4) * 2;
            __nv_bfloat16 h0, l0, h1, l1;
            split2(v[0], h0, l0); split2(v[1], h1, l1);
            *(unsigned*)(sm + 16384 + SWZ(base)) = pack2(h0, h1);
            *(unsigned*)(sm + 16384 + 9216 + SWZ(base)) = pack2(l0, l1);
            split2(v[2], h0, l0); split2(v[3], h1, l1);
            *(unsigned*)(sm + 16384 + SWZ(base + 4)) = pack2(h0, h1);
            *(unsigned*)(sm + 16384 + 9216 + SWZ(base + 4)) = pack2(l0, l1);
        }
        __syncthreads();
#pragma unroll
        for (int ks = 0; ks < 2; ks++) {
            unsigned ah[4][4], al[4][4];
#pragma unroll
            for (int mi = 0; mi < 4; mi++) {
                const int r = mw * 64 + mi * 16 + lrow;
                const unsigned off = SWZ(r * 64 + ks * 32 + lkh);
                LDSM4(ah[mi], sb + off);
                LDSM4(al[mi], sb + 8192 + off);
            }
#pragma unroll
            for (int nb = 0; nb < 2; nb++) {
                unsigned bh[4], bl[4];
                const int kr = ks * 16 + trow;
                const unsigned off = SWZ(kr * BSTRIDE0 + (nw * 32 + nb * 16) * 2 + tnh);
                LDSM4T(bh, sb + 16384 + off);
                LDSM4T(bl, sb + 16384 + 9216 + off);
                unsigned beh[2] = {bh[0], bh[2]}, boh[2] = {bh[1], bh[3]};
                unsigned bel[2] = {bl[0], bl[2]}, bol[2] = {bl[1], bl[3]};
#pragma unroll
                for (int mi = 0; mi < 4; mi++) mma16816(acc[mi][2 * nb],     ah[mi], beh);
#pragma unroll
                for (int mi = 0; mi < 4; mi++) mma16816(acc[mi][2 * nb + 1], ah[mi], boh);
#pragma unroll
                for (int mi = 0; mi < 4; mi++) mma16816(acc[mi][2 * nb],     ah[mi], bel);
#pragma unroll
                for (int mi = 0; mi < 4; mi++) mma16816(acc[mi][2 * nb + 1], ah[mi], bol);
#pragma unroll
                for (int mi = 0; mi < 4; mi++) mma16816(acc[mi][2 * nb],     al[mi], beh);
#pragma unroll
                for (int mi = 0; mi < 4; mi++) mma16816(acc[mi][2 * nb + 1], al[mi], boh);
            }
        }
    }

#pragma unroll
    for (int mi = 0; mi < 4; mi++) {
        const int r = row0 + mw * 64 + mi * 16 + g;
#pragma unroll
        for (int ni = 0; ni < 4; ni++) {
            const int colG = col0 + nw * 32 + ni * 8 + 2 * tig;
            float v0 = acc[mi][ni][0], v1 = acc[mi][ni][1];
            float v2 = acc[mi][ni][2], v3 = acc[mi][ni][3];
            if (EPI & LEPI_BIAS) {
                float2 bb = *(const float2*)(bias + colG);
                v0 += bb.x; v1 += bb.y; v2 += bb.x; v3 += bb.y;
            }
            if (EPI & LEPI_GELU) {
                v0 = geluf(v0); v1 = geluf(v1); v2 = geluf(v2); v3 = geluf(v3);
            }
            if (EPI & LEPI_RESID) {
                float2 ra = *(const float2*)(resid + (size_t)r * 256 + colG);
                float2 rb = *(const float2*)(resid + (size_t)(r + 8) * 256 + colG);
                v0 += ra.x; v1 += ra.y; v2 += rb.x; v3 += rb.y;
            }
            *(float2*)(out + (size_t)r * ldout + colG)       = make_float2(v0, v1);
            *(float2*)(out + (size_t)(r + 8) * ldout + colG) = make_float2(v2, v3);
        }
    }
}

// ---------------- prep kernels ----------------------------------------------
__global__ void prep_pf(const float* __restrict__ pf,
                        __nv_bfloat16* __restrict__ H, __nv_bfloat16* __restrict__ L, int N)
{
    int idx = blockIdx.x * 256 + threadIdx.x;
    int row = idx / 12, c8 = (idx % 12) * 8;
    if (row >= N) return;
    __nv_bfloat16 h[8], l[8];
#pragma unroll
    for (int j = 0; j < 8; j++) {
        int k = c8 + j;
        float v = (k < 72) ? pf[(size_t)row * 72 + k] : 0.f;
        split2(v, h[j], l[j]);
    }
    *(uint4*)(H + (size_t)row * 96 + c8) = *(uint4*)h;
    *(uint4*)(L + (size_t)row * 96 + c8) = *(uint4*)l;
}

// ALL weight preps in one launch: blocks [0,12) = w1 transposed [256][96];
// blocks [12,44)=w2, [44,76)=w3, [76,108)=w4 as [k][n] pair images.
__global__ void prep_weights(
    const float* __restrict__ w1, __nv_bfloat16* __restrict__ w1H, __nv_bfloat16* __restrict__ w1L,
    const float* __restrict__ w2, __nv_bfloat16* __restrict__ w2H, __nv_bfloat16* __restrict__ w2L,
    const float* __restrict__ w3, __nv_bfloat16* __restrict__ w3H, __nv_bfloat16* __restrict__ w3L,
    const float* __restrict__ w4, __nv_bfloat16* __restrict__ w4H, __nv_bfloat16* __restrict__ w4L)
{
    const int bx = blockIdx.x, tid = threadIdx.x;
    __nv_bfloat16 h[8], l[8];
    if (bx < 12) {
        // w1: [k=72][n=256] fp32 -> transposed pairs [n=256][kpad=96]
        int idx = bx * 256 + tid;
        int n = idx / 12, c8 = (idx % 12) * 8;
        if (n >= 256) return;
#pragma unroll
        for (int j = 0; j < 8; j++) {
            int k = c8 + j;
            float v = (k < 72) ? w1[(size_t)k * 256 + n] : 0.f;
            split2(v, h[j], l[j]);
        }
        *(uint4*)(w1H + (size_t)n * 96 + c8) = *(uint4*)h;
        *(uint4*)(w1L + (size_t)n * 96 + c8) = *(uint4*)l;
    } else {
        const int which = (bx - 12) >> 5;
        const int b2 = (bx - 12) & 31;
        const float* W = (which == 0) ? w2 : (which == 1) ? w3 : w4;
        __nv_bfloat16* H = (which == 0) ? w2H : (which == 1) ? w3H : w4H;
        __nv_bfloat16* L = (which == 0) ? w2L : (which == 1) ? w3L : w4L;
        int idx = b2 * 256 + tid;
        int row = idx / 32, c8 = (idx % 32) * 8;
#pragma unroll
        for (int j = 0; j < 8; j++) {
            split2(W[(size_t)row * 256 + c8 + j], h[j], l[j]);
        }
        *(uint4*)(H + (size_t)row * 256 + c8) = *(uint4*)h;
        *(uint4*)(L + (size_t)row * 256 + c8) = *(uint4*)l;
    }
}

template <bool GELU>
__global__ __launch_bounds__(256)
void lnprep(const __nv_bfloat16* __restrict__ inH, const __nv_bfloat16* __restrict__ inL,
            const float* __restrict__ gam, const float* __restrict__ bet,
            __nv_bfloat16* __restrict__ outH, __nv_bfloat16* __restrict__ outL, int M)
{
    const int wid = threadIdx.x >> 5, lane = threadIdx.x & 31;
    const int row = blockIdx.x * 8 + wid;
    if (row >= M) return;
    const int c8 = lane * 8;
    uint4 uh = *(const uint4*)(inH + (size_t)row * 256 + c8);
    uint4 ul = *(const uint4*)(inL + (size_t)row * 256 + c8);
    const __nv_bfloat16* ph = (const __nv_bfloat16*)&uh;
    const __nv_bfloat16* pl = (const __nv_bfloat16*)&ul;
    float v[8];
    float s = 0.f, ss = 0.f;
#pragma unroll
    for (int j = 0; j < 8; j++) {
        v[j] = __bfloat162float(ph[j]) + __bfloat162float(pl[j]);
        s += v[j]; ss += v[j] * v[j];
    }
#pragma unroll
    for (int o = 16; o; o >>= 1) {
        s  += __shfl_xor_sync(0xffffffffu, s, o);
        ss += __shfl_xor_sync(0xffffffffu, ss, o);
    }
    const float m = s * (1.0f / 256.0f);
    const float r = rsqrtf(ss * (1.0f / 256.0f) - m * m + 1e-5f);
    float4 g0 = *(const float4*)(gam + c8), g1 = *(const float4*)(gam + c8 + 4);
    float4 b0 = *(const float4*)(bet + c8), b1 = *(const float4*)(bet + c8 + 4);
    float gg[8] = {g0.x, g0.y, g0.z, g0.w, g1.x, g1.y, g1.z, g1.w};
    float bb[8] = {b0.x, b0.y, b0.z, b0.w, b1.x, b1.y, b1.z, b1.w};
    __nv_bfloat16 oh[8], ol[8];
#pragma unroll
    for (int j = 0; j < 8; j++) {
        float x = (v[j] - m) * r * gg[j] + bb[j];
        if (GELU) x = geluf(x);
        split2(x, oh[j], ol[j]);
    }
    *(uint4*)(outH + (size_t)row * 256 + c8) = *(uint4*)oh;
    *(uint4*)(outL + (size_t)row * 256 + c8) = *(uint4*)ol;
}

// ---------------- misc small kernels ----------------------------------------
__global__ __launch_bounds__(256)
void ln_stats(const float* __restrict__ X, float* __restrict__ mean,
              float* __restrict__ rstd, int M)
{
    int warp = (blockIdx.x * blockDim.x + threadIdx.x) >> 5;
    if (warp >= M) return;
    int lane = threadIdx.x & 31;
    const float* row = X + (size_t)warp * 256;
    float s = 0.f, ss = 0.f;
#pragma unroll
    for (int j = 0; j < 8; j++) { float v = row[lane + 32 * j]; s += v; ss += v * v; }
#pragma unroll
    for (int o = 16; o; o >>= 1) {
        s  += __shfl_xor_sync(0xffffffffu, s, o);
        ss += __shfl_xor_sync(0xffffffffu, ss, o);
    }
    if (lane == 0) {
        float m = s * (1.0f / 256.0f);
        mean[warp] = m;
        rstd[warp] = rsqrtf(ss * (1.0f / 256.0f) - m * m + 1e-5f);
    }
}

// fused: invq row-norm + qm pair write (one block per query row)
__global__ __launch_bounds__(256)
void qnormpair(const float* __restrict__ qe, const float* __restrict__ lsc,
               __nv_bfloat16* __restrict__ H, __nv_bfloat16* __restrict__ L)
{
    const int q = blockIdx.x;
    const int d = threadIdx.x;
    const float v = qe[(size_t)q * 256 + d];
    __shared__ float sh[256];
    sh[d] = v * v;
    __syncthreads();
    for (int o = 128; o; o >>= 1) {
        if (d < o) sh[d] += sh[d + o];
        __syncthreads();
    }
    const float inv = 1.0f / fmaxf(sqrtf(sh[0]), 1e-12f);
    const float x = v * inv * expf(lsc[0]);
    __nv_bfloat16 h, l;
    split2(x, h, l);
    H[(size_t)q * 256 + d] = h;
    L[(size_t)q * 256 + d] = l;
}

__global__ __launch_bounds__(256)
void reduce_refined(const float* __restrict__ Ppart, const float* __restrict__ spart,
                    const float* __restrict__ qe, float* __restrict__ refined,
                    int CH, int NB)
{
    const int q = blockIdx.x;
    const int d = threadIdx.x;
    __shared__ float sh[256];
    float s = 0.f;
    for (int i = d; i < NB; i += 256) s += spart[(size_t)i * 128 + q];
    sh[d] = s;
    __syncthreads();
    for (int o = 128; o; o >>= 1) {
        if (d < o) sh[d] += sh[d + o];
        __syncthreads();
    }
    const float stot = sh[0];
    float p0 = 0.f, p1 = 0.f, p2 = 0.f, p3 = 0.f;
    for (int c = 0; c < CH; c += 4) {
        p0 += Ppart[((size_t)(c + 0) * 128 + q) * 256 + d];
        p1 += Ppart[((size_t)(c + 1) * 128 + q) * 256 + d];
        p2 += Ppart[((size_t)(c + 2) * 128 + q) * 256 + d];
        p3 += Ppart[((size_t)(c + 3) * 128 + q) * 256 + d];
    }
    refined[(size_t)q * 256 + d] = qe[(size_t)q * 256 + d] + ((p0 + p1) + (p2 + p3)) / stot;
}

__global__ __launch_bounds__(256)
void score_kernel(const float* __restrict__ A2s, const float* __restrict__ w2,
                  const float* __restrict__ b2, float* __restrict__ out)
{
    const int q = blockIdx.x;
    const int d = threadIdx.x;
    __shared__ float sh[256];
    sh[d] = A2s[(size_t)q * 256 + d] * w2[d];
    __syncthreads();
    for (int o = 128; o; o >>= 1) {
        if (d < o) sh[d] += sh[d + o];
        __syncthreads();
    }
    if (d == 0) out[q] = sh[0] + b2[0];
}

// ---------------------------------------------------------------------------
extern "C" void kernel_launch(void* const* d_in, const int* in_sizes, int n_in,
                              void* d_out, int out_size)
{
    const float* point_feat = (const float*)d_in[0];
    const float* ip_w1 = (const float*)d_in[1];
    const float* ip_b1 = (const float*)d_in[2];
    const float* ip_ln_g = (const float*)d_in[3];
    const float* ip_ln_b = (const float*)d_in[4];
    const float* ip_w2 = (const float*)d_in[5];
    const float* ip_b2 = (const float*)d_in[6];
    const float* ph_ln_g = (const float*)d_in[7];
    const float* ph_ln_b = (const float*)d_in[8];
    const float* ph_w1 = (const float*)d_in[9];
    const float* ph_b1 = (const float*)d_in[10];
    const float* ph_w2 = (const float*)d_in[11];
    const float* ph_b2 = (const float*)d_in[12];
    const float* q_embed = (const float*)d_in[13];
    const float* qh_ln_g = (const float*)d_in[14];
    const float* qh_ln_b = (const float*)d_in[15];
    const float* qh_w1 = (const float*)d_in[16];
    const float* qh_b1 = (const float*)d_in[17];
    const float* qh_w2 = (const float*)d_in[18];
    const float* qh_b2 = (const float*)d_in[19];
    const float* sh_ln_g = (const float*)d_in[20];
    const float* sh_ln_b = (const float*)d_in[21];
    const float* sh_w1 = (const float*)d_in[22];
    const float* sh_b1 = (const float*)d_in[23];
    const float* sh_w2 = (const float*)d_in[24];
    const float* sh_b2 = (const float*)d_in[25];
    const float* logit_scale = (const float*)d_in[26];

    const int N = in_sizes[0] / 72;

    float* out = (float*)d_out;
    const size_t offScore = (size_t)128 * N;
    const size_t offPE = offScore + 128;
    const size_t offRef = offPE + (size_t)N * 256;
    float* mask = out;
    float* score = out + offScore;
    float* pe = out + offPE;
    float* refined = out + offRef;

    __nv_bfloat16 *pfH, *pfL, *xH, *xL, *aH, *aL, *hH, *hL, *peH, *peL, *emH;
    __nv_bfloat16 *w1H, *w1L, *w2H, *w2L, *w3H, *w3L, *w4H, *w4L, *qmH, *qmL;
    float *meanQ, *rstdQ, *A2q, *qe, *spart, *mpart, *Ppart;
    cudaGetSymbolAddress((void**)&pfH, g_pfH); cudaGetSymbolAddress((void**)&pfL, g_pfL);
    cudaGetSymbolAddress((void**)&xH, g_xH);   cudaGetSymbolAddress((void**)&xL, g_xL);
    cudaGetSymbolAddress((void**)&aH, g_aH);   cudaGetSymbolAddress((void**)&aL, g_aL);
    cudaGetSymbolAddress((void**)&hH, g_hH);   cudaGetSymbolAddress((void**)&hL, g_hL);
    cudaGetSymbolAddress((void**)&peH, g_peH); cudaGetSymbolAddress((void**)&peL, g_peL);
    cudaGetSymbolAddress((void**)&emH, g_emH);
    cudaGetSymbolAddress((void**)&w1H, g_w1H); cudaGetSymbolAddress((void**)&w1L, g_w1L);
    cudaGetSymbolAddress((void**)&w2H, g_w2H); cudaGetSymbolAddress((void**)&w2L, g_w2L);
    cudaGetSymbolAddress((void**)&w3H, g_w3H); cudaGetSymbolAddress((void**)&w3L, g_w3L);
    cudaGetSymbolAddress((void**)&w4H, g_w4H); cudaGetSymbolAddress((void**)&w4L, g_w4L);
    cudaGetSymbolAddress((void**)&qmH, g_qmH); cudaGetSymbolAddress((void**)&qmL, g_qmL);
    cudaGetSymbolAddress((void**)&meanQ, g_meanQ); cudaGetSymbolAddress((void**)&rstdQ, g_rstdQ);
    cudaGetSymbolAddress((void**)&A2q, g_A2q); cudaGetSymbolAddress((void**)&qe, g_qe);
    cudaGetSymbolAddress((void**)&spart, g_spart);
    cudaGetSymbolAddress((void**)&mpart, g_mpart);
    cudaGetSymbolAddress((void**)&Ppart, g_Ppart);

    // dynamic smem opt-in
    const int SMEM_BT0 = 2 * (16384 + 2 * 9216) + 2048;   // 71680
    const int SMEM_BT1 = 2 * (16384 + 2 * 8192) + 2048;   // 67584
    cudaFuncSetAttribute(tpair256<EPI_BIAS | EPI_LNPAIR | EPI_LNGELU>,
                         cudaFuncAttributeMaxDynamicSharedMemorySize, SMEM256);
    cudaFuncSetAttribute(tpair<EPI_BIAS | EPI_OUTPAIR, 0>,
                         cudaFuncAttributeMaxDynamicSharedMemorySize, SMEM_BT0);
    cudaFuncSetAttribute(tpair<EPI_BIAS | EPI_GELU | EPI_OUTPAIR, 0>,
                         cudaFuncAttributeMaxDynamicSharedMemorySize, SMEM_BT0);
    cudaFuncSetAttribute(tpair<EPI_BIAS | EPI_RESIDP | EPI_OUTF32 | EPI_OUTPAIR | EPI_SSQ, 0>,
                         cudaFuncAttributeMaxDynamicSharedMemorySize, SMEM_BT0);
    cudaFuncSetAttribute(tpair<EPI_CSSQ | EPI_OUTF32 | EPI_EXP1 | EPI_SPART, 1>,
                         cudaFuncAttributeMaxDynamicSharedMemorySize, SMEM_BT1);
    cudaFuncSetAttribute(tpair<EPI_OUTF32, 0, 1>,
                         cudaFuncAttributeMaxDynamicSharedMemorySize, SMEM_BT0);

    // -------- preps (2 launches total) --------
    prep_pf<<<(N * 12 + 255) / 256, 256>>>(point_feat, pfH, pfL, N);
    prep_weights<<<108, 256>>>(ip_w1, w1H, w1L, ip_w2, w2H, w2L,
                               ph_w1, w3H, w3L, ph_w2, w4H, w4L);

    const dim3 gBig(N / 128, 2);

    // -------- point pipeline --------
    // a = gelu(LN(pf @ ip_w1 + ip_b1))  (fused; verified)
    tpair256<EPI_BIAS | EPI_LNPAIR | EPI_LNGELU><<<N / 128, 512, SMEM256>>>(
        pfH, pfL, 96, w1H, w1L, 96, ip_b1,
        nullptr, 0, nullptr, nullptr, aH, aL,
        nullptr, nullptr, ip_ln_g, ip_ln_b, nullptr, 96);
    // h = a @ ip_w2 + ip_b2 (pairs)
    tpair<EPI_BIAS | EPI_OUTPAIR, 0><<<gBig, 256, SMEM_BT0>>>(
        aH, aL, 256, w2H, w2L, 256, ip_b2,
        nullptr, 0, 0, hH, hL, 256, nullptr, nullptr, nullptr, nullptr, 0, 256);
    // a = LN(h) (pairs)
    lnprep<false><<<N / 8, 256>>>(hH, hL, ph_ln_g, ph_ln_b, aH, aL, N);
    // x = gelu(a @ ph_w1 + ph_b1) (pairs)
    tpair<EPI_BIAS | EPI_GELU | EPI_OUTPAIR, 0><<<gBig, 256, SMEM_BT0>>>(
        aH, aL, 256, w3H, w3L, 256, ph_b1,
        nullptr, 0, 0, xH, xL, 256, nullptr, nullptr, nullptr, nullptr, 0, 256);
    // pe = h + x @ ph_w2 + ph_b2 (fp32 to d_out + pairs + fused row-SSQ partials)
    tpair<EPI_BIAS | EPI_RESIDP | EPI_OUTF32 | EPI_OUTPAIR | EPI_SSQ, 0><<<gBig, 256, SMEM_BT0>>>(
        xH, xL, 256, w4H, w4L, 256, ph_b2,
        pe, 256, 0, peH, peL, 256, hH, hL, nullptr, spart, (size_t)N, 256);

    // -------- query pipeline (legacy, tiny) --------
    ln_stats<<<16, 256>>>(q_embed, meanQ, rstdQ, 128);
    tlegacy<AOP_LN, LEPI_BIAS | LEPI_GELU><<<dim3(1, 2), 256>>>(
        q_embed, 256, qh_w1, 256, qh_b1, A2q, 256, 256,
        meanQ, rstdQ, qh_ln_g, qh_ln_b, nullptr);
    tlegacy<AOP_ID, LEPI_BIAS | LEPI_RESID><<<dim3(1, 2), 256>>>(
        A2q, 256, qh_w2, 256, qh_b2, qe, 256, 256,
        nullptr, nullptr, nullptr, nullptr, q_embed);
    qnormpair<<<128, 256>>>(qe, logit_scale, qmH, qmL);

    // -------- mask logits + em + softmax partials; invpe inline from SSQ ----
    tpair<EPI_CSSQ | EPI_OUTF32 | EPI_EXP1 | EPI_SPART, 1><<<dim3(1, N / 128), 256, SMEM_BT1>>>(
        qmH, qmL, 256, peH, peL, 256, nullptr,
        mask, (size_t)N, 0, emH, nullptr, (size_t)N, nullptr, nullptr, spart, mpart, 128, 256);

    // -------- weighted aggregation (2-term, A-single), z=128 ---------------
    tpair<EPI_OUTF32, 0, 1><<<dim3(1, 2, 128), 256, SMEM_BT0>>>(
        emH, nullptr, N, peH, peL, 256, nullptr,
        Ppart, 256, (size_t)128 * 256, nullptr, nullptr, 0,
        nullptr, nullptr, nullptr, nullptr, 0, 2048);
    reduce_refined<<<128, 256>>>(Ppart, mpart, qe, refined, 128, N / 128);

    // -------- score head (legacy) --------
    ln_stats<<<16, 256>>>(refined, meanQ, rstdQ, 128);
    tlegacy<AOP_LN, LEPI_BIAS | LEPI_GELU><<<dim3(1, 2), 256>>>(
        refined, 256, sh_w1, 256, sh_b1, A2q, 256, 256,
        meanQ, rstdQ, sh_ln_g, sh_ln_b, nullptr);
    score_kernel<<<128, 256>>>(A2q, sh_w2, sh_b2, score);
}

// round 17
// speedup vs baseline: 1.1606x; 1.0304x over previous
#include <cuda_runtime.h>
#include <cuda_bf16.h>
#include <math.h>
#include <stdint.h>

// ---------------------------------------------------------------------------
// QueryInstanceDecoder: bf16 split-precision mma.sync pipeline, v10.
// = v9 (best passing) + lnprep eliminated algebraically:
//   LN(h)@W = r*(h@(gamma.W)) - (m*r)*colsum(gamma.W) + (beta@W + b)
//   GEMM2 emits row sum/ssq partials (EPI_STAT2) -> combine_stats -> GEMM3
//   runs on h-pairs with folded weights + EPI_ROWLN epilogue.
// N=262144, C_IN=72, D=256, Q=128.
// d_out (floats): mask_logits[128*N] | score[128] | point_embed[N*256] | refined[128*256]
// ---------------------------------------------------------------------------

#define DEVI __device__ __forceinline__

DEVI float geluf(float x) { return 0.5f * x * (1.0f + erff(x * 0.70710678118654752f)); }

DEVI unsigned pack2(__nv_bfloat16 a, __nv_bfloat16 b) {
    return (unsigned)__bfloat16_as_ushort(a) | ((unsigned)__bfloat16_as_ushort(b) << 16);
}
DEVI void split2(float x, __nv_bfloat16& h, __nv_bfloat16& l) {
    h = __float2bfloat16(x);
    l = __float2bfloat16(x - __bfloat162float(h));
}
DEVI float upk_lo(unsigned u) { return __bfloat162float(__ushort_as_bfloat16((unsigned short)(u & 0xffff))); }
DEVI float upk_hi(unsigned u) { return __bfloat162float(__ushort_as_bfloat16((unsigned short)(u >> 16))); }

DEVI void mma16816(float* c, const unsigned* a, const unsigned* b) {
    asm volatile(
        "mma.sync.aligned.m16n8k16.row.col.f32.bf16.bf16.f32 "
        "{%0,%1,%2,%3},{%4,%5,%6,%7},{%8,%9},{%0,%1,%2,%3};"
        : "+f"(c[0]), "+f"(c[1]), "+f"(c[2]), "+f"(c[3])
        : "r"(a[0]), "r"(a[1]), "r"(a[2]), "r"(a[3]), "r"(b[0]), "r"(b[1]));
}
DEVI uint32_t smem_u32(const void* p) {
    uint32_t a;
    asm("{ .reg .u64 t; cvta.to.shared.u64 t, %1; cvt.u32.u64 %0, t; }" : "=r"(a) : "l"(p));
    return a;
}
#define LDSM4(r, a) \
    asm volatile("ldmatrix.sync.aligned.m8n8.x4.shared.b16 {%0,%1,%2,%3},[%4];" \
        : "=r"((r)[0]), "=r"((r)[1]), "=r"((r)[2]), "=r"((r)[3]) : "r"(a))
#define LDSM4T(r, a) \
    asm volatile("ldmatrix.sync.aligned.m8n8.x4.trans.shared.b16 {%0,%1,%2,%3},[%4];" \
        : "=r"((r)[0]), "=r"((r)[1]), "=r"((r)[2]), "=r"((r)[3]) : "r"(a))

DEVI void cpasync16(uint32_t dst, const void* src) {
    asm volatile("cp.async.cg.shared.global [%0], [%1], 16;" :: "r"(dst), "l"(src));
}
DEVI void cpcommit() { asm volatile("cp.async.commit_group;"); }
DEVI void cpwait1()  { asm volatile("cp.async.wait_group 1;"); }
DEVI void cpwait0()  { asm volatile("cp.async.wait_group 0;"); }

#define SWZ(o) ((unsigned)(o) ^ ((((unsigned)(o)) >> 3) & 0x70))
#define BSTRIDE0 288

// ---------------- scratch (static device memory; no allocations) -----------
#define NMAX 262144
__device__ __nv_bfloat16 g_pfH[(size_t)NMAX * 96], g_pfL[(size_t)NMAX * 96];
__device__ __nv_bfloat16 g_xH[(size_t)NMAX * 256], g_xL[(size_t)NMAX * 256];
__device__ __nv_bfloat16 g_aH[(size_t)NMAX * 256], g_aL[(size_t)NMAX * 256];
__device__ __nv_bfloat16 g_hH[(size_t)NMAX * 256], g_hL[(size_t)NMAX * 256];
__device__ __nv_bfloat16 g_peH[(size_t)NMAX * 256], g_peL[(size_t)NMAX * 256];
__device__ __nv_bfloat16 g_emH[(size_t)128 * NMAX];
__device__ __nv_bfloat16 g_w1H[96 * 256], g_w1L[96 * 256];     // [n=256][k=96] transposed
__device__ __nv_bfloat16 g_w2H[256 * 256], g_w2L[256 * 256];   // [k][n]
__device__ __nv_bfloat16 g_w3H[256 * 256], g_w3L[256 * 256];   // gamma-folded [k][n]
__device__ __nv_bfloat16 g_w4H[256 * 256], g_w4L[256 * 256];
__device__ __nv_bfloat16 g_qmH[128 * 256], g_qmL[128 * 256];
__device__ float g_meanQ[128], g_rstdQ[128];
__device__ float g_A2q[128 * 256];
__device__ float g_qe[128 * 256];
__device__ float g_meanN[NMAX], g_rstdN[NMAX];
__device__ float g_c12[512];                         // c1[256] | c2'[256]
__device__ float g_spart[(size_t)4 * NMAX];          // GEMM2 S/SS partials or GEMM4 SSQ
__device__ float g_mpart[NMAX];                      // mask em-sum partials [N/128][128]
__device__ float g_Ppart[256 * 128 * 256];

// ---------------- epilogue flags --------------------------------------------
#define EPI_BIAS    1
#define EPI_GELU    2
#define EPI_RESIDP  4
#define EPI_OUTF32  8
#define EPI_OUTPAIR 16
#define EPI_SPART   32
#define EPI_CSCALE  64
#define EPI_SSQ     256
#define EPI_LNPAIR  512
#define EPI_LNGELU  1024
#define EPI_EXP1    2048
#define EPI_CSSQ    4096
#define EPI_STAT2   8192    // emit per-row sum AND ssq partials to spart[4][spitch]
#define EPI_ROWLN   16384   // v = rowr[r]*v - rowm[r]*rowr[r]*c1[col] + c2p[col] (cscale=[c1|c2p])

// =============================================================================
// tpair256: C[128x256] = A_pairs @ B_pairs^T (B image [n][k]). 512 threads,
// 16 warps (2x8), warp 64x32, 2-stage cp.async. Used only for GEMM1 (K=96).
// =============================================================================
#define STG256 49152
#define SP_OFF (2 * STG256)
#define SMEM256 (SP_OFF + 4096 + 4096 + 512 + 512 + 1024 + 1024)

template <int EPI>
__global__ __launch_bounds__(512, 1)
void tpair256(const __nv_bfloat16* __restrict__ Ah, const __nv_bfloat16* __restrict__ Al, int lda,
              const __nv_bfloat16* __restrict__ Bh, const __nv_bfloat16* __restrict__ Bl, int ldb,
              const float* __restrict__ bias,
              float* __restrict__ outf, size_t ldout,
              __nv_bfloat16* __restrict__ oh, __nv_bfloat16* __restrict__ ol,
              __nv_bfloat16* __restrict__ o2h, __nv_bfloat16* __restrict__ o2l,
              const __nv_bfloat16* __restrict__ resH, const __nv_bfloat16* __restrict__ resL,
              const float* __restrict__ gam, const float* __restrict__ bet,
              float* __restrict__ invout, int Kblk)
{
    extern __shared__ __align__(1024) unsigned char sm[];
    const uint32_t sb = smem_u32(sm);
    float* spS  = (float*)(sm + SP_OFF);
    float* spSS = (float*)(sm + SP_OFF + 4096);
    float* marr = (float*)(sm + SP_OFF + 8192);
    float* rarr = (float*)(sm + SP_OFF + 8704);
    float* sgam = (float*)(sm + SP_OFF + 9216);
    float* sbet = (float*)(sm + SP_OFF + 10240);

    const int tid  = threadIdx.x;
    const int row0 = blockIdx.x * 128;
    const int nch  = Kblk >> 5;

    if (EPI & EPI_LNPAIR) {
        if (tid < 256) { sgam[tid] = gam[tid]; sbet[tid] = bet[tid]; }
    }

    const int arow = tid >> 2, ak0 = (tid & 3) * 8;
    const int brow = tid >> 1, bk0 = (tid & 1) * 16;
    const unsigned dA  = SWZ(arow * 64 + ak0 * 2);
    const unsigned dB  = SWZ(brow * 64 + bk0 * 2);
    const unsigned dB2 = SWZ(brow * 64 + bk0 * 2 + 16);
    const __nv_bfloat16* ApH = Ah + (size_t)(row0 + arow) * lda + ak0;
    const __nv_bfloat16* ApL = Al + (size_t)(row0 + arow) * lda + ak0;
    const __nv_bfloat16* BpH = Bh + (size_t)brow * ldb + bk0;
    const __nv_bfloat16* BpL = Bl + (size_t)brow * ldb + bk0;

    auto issue = [&](int c) {
        const int kc = c * 32;
        const uint32_t st = sb + (c & 1) * STG256;
        cpasync16(st + dA, ApH + kc);
        cpasync16(st + 8192 + dA, ApL + kc);
        cpasync16(st + 16384 + dB,  BpH + kc);
        cpasync16(st + 16384 + dB2, BpH + kc + 8);
        cpasync16(st + 32768 + dB,  BpL + kc);
        cpasync16(st + 32768 + dB2, BpL + kc + 8);
        cpcommit();
    };

    const int lane = tid & 31, w = tid >> 5;
    const int mw = w >> 3, nw = w & 7;
    const int g = lane >> 2, tig = lane & 3;
    const int lrow = (lane & 7) + ((lane >> 3) & 1) * 8;
    const int lkh  = (lane >> 4) * 16;

    float acc[4][4][4];
#pragma unroll
    for (int mi = 0; mi < 4; mi++)
#pragma unroll
        for (int ni = 0; ni < 4; ni++)
#pragma unroll
            for (int e = 0; e < 4; e++) acc[mi][ni][e] = 0.f;

    auto compute = [&](int c) {
        const uint32_t st = sb + (c & 1) * STG256;
#pragma unroll
        for (int ks = 0; ks < 2; ks++) {
            unsigned ah[4][4], al[4][4];
#pragma unroll
            for (int mi = 0; mi < 4; mi++) {
                const int r = mw * 64 + mi * 16 + lrow;
                const unsigned off = SWZ(r * 64 + ks * 32 + lkh);
                LDSM4(ah[mi], st + off);
                LDSM4(al[mi], st + 8192 + off);
            }
#pragma unroll
            for (int nb = 0; nb < 2; nb++) {
                unsigned bh[4], bl[4];
                const int n = nw * 32 + nb * 16 + lrow;
                const unsigned off = SWZ(n * 64 + ks * 32 + lkh);
                LDSM4(bh, st + 16384 + off);
                LDSM4(bl, st + 32768 + off);
                unsigned beh[2] = {bh[0], bh[2]}, boh[2] = {bh[1], bh[3]};
                unsigned bel[2] = {bl[0], bl[2]}, bol[2] = {bl[1], bl[3]};
#pragma unroll
                for (int mi = 0; mi < 4; mi++) mma16816(acc[mi][2 * nb],     ah[mi], beh);
#pragma unroll
                for (int mi = 0; mi < 4; mi++) mma16816(acc[mi][2 * nb + 1], ah[mi], boh);
#pragma unroll
                for (int mi = 0; mi < 4; mi++) mma16816(acc[mi][2 * nb],     ah[mi], bel);
#pragma unroll
                for (int mi = 0; mi < 4; mi++) mma16816(acc[mi][2 * nb + 1], ah[mi], bol);
#pragma unroll
                for (int mi = 0; mi < 4; mi++) mma16816(acc[mi][2 * nb],     al[mi], beh);
#pragma unroll
                for (int mi = 0; mi < 4; mi++) mma16816(acc[mi][2 * nb + 1], al[mi], boh);
            }
        }
    };

    issue(0);
    for (int c = 0; c < nch; c++) {
        if (c + 1 < nch) { issue(c + 1); cpwait1(); } else { cpwait0(); }
        __syncthreads();
        compute(c);
        __syncthreads();
    }

    float sS0[4], sS1[4], sSS0[4], sSS1[4];
#pragma unroll
    for (int mi = 0; mi < 4; mi++) { sS0[mi] = sS1[mi] = sSS0[mi] = sSS1[mi] = 0.f; }

#pragma unroll
    for (int mi = 0; mi < 4; mi++) {
        const int r = row0 + mw * 64 + mi * 16 + g;
#pragma unroll
        for (int ni = 0; ni < 4; ni++) {
            const int colG = nw * 32 + ni * 8 + 2 * tig;
            float v0 = acc[mi][ni][0], v1 = acc[mi][ni][1];
            float v2 = acc[mi][ni][2], v3 = acc[mi][ni][3];
            if (EPI & EPI_BIAS) {
                float2 bb = *(const float2*)(bias + colG);
                v0 += bb.x; v1 += bb.y; v2 += bb.x; v3 += bb.y;
            }
            if (EPI & EPI_GELU) {
                v0 = geluf(v0); v1 = geluf(v1); v2 = geluf(v2); v3 = geluf(v3);
            }
            if (EPI & EPI_RESIDP) {
                unsigned uh0 = *(const unsigned*)(resH + (size_t)r * 256 + colG);
                unsigned ul0 = *(const unsigned*)(resL + (size_t)r * 256 + colG);
                unsigned uh1 = *(const unsigned*)(resH + (size_t)(r + 8) * 256 + colG);
                unsigned ul1 = *(const unsigned*)(resL + (size_t)(r + 8) * 256 + colG);
                v0 += upk_lo(uh0) + upk_lo(ul0); v1 += upk_hi(uh0) + upk_hi(ul0);
                v2 += upk_lo(uh1) + upk_lo(ul1); v3 += upk_hi(uh1) + upk_hi(ul1);
            }
            if (EPI & EPI_OUTF32) {
                *(float2*)(outf + (size_t)r * ldout + colG)       = make_float2(v0, v1);
                *(float2*)(outf + (size_t)(r + 8) * ldout + colG) = make_float2(v2, v3);
            }
            if (EPI & EPI_LNPAIR) { sS0[mi] += v0 + v1; sS1[mi] += v2 + v3; }
            if (EPI & (EPI_SSQ | EPI_LNPAIR)) {
                sSS0[mi] += v0 * v0 + v1 * v1;
                sSS1[mi] += v2 * v2 + v3 * v3;
            }
            acc[mi][ni][0] = v0; acc[mi][ni][1] = v1;
            acc[mi][ni][2] = v2; acc[mi][ni][3] = v3;
        }
    }

    if (EPI & (EPI_SSQ | EPI_LNPAIR)) {
#pragma unroll
        for (int mi = 0; mi < 4; mi++) {
            float a0 = sS0[mi], a1 = sS1[mi], b0 = sSS0[mi], b1 = sSS1[mi];
            a0 += __shfl_xor_sync(0xffffffffu, a0, 1); a0 += __shfl_xor_sync(0xffffffffu, a0, 2);
            a1 += __shfl_xor_sync(0xffffffffu, a1, 1); a1 += __shfl_xor_sync(0xffffffffu, a1, 2);
            b0 += __shfl_xor_sync(0xffffffffu, b0, 1); b0 += __shfl_xor_sync(0xffffffffu, b0, 2);
            b1 += __shfl_xor_sync(0xffffffffu, b1, 1); b1 += __shfl_xor_sync(0xffffffffu, b1, 2);
            if (tig == 0) {
                const int lr = mw * 64 + mi * 16 + g;
                spS[nw * 128 + lr]      = a0;
                spS[nw * 128 + lr + 8]  = a1;
                spSS[nw * 128 + lr]     = b0;
                spSS[nw * 128 + lr + 8] = b1;
            }
        }
        __syncthreads();
        if (tid < 128) {
            float s = 0.f, ss = 0.f;
#pragma unroll
            for (int ww = 0; ww < 8; ww++) {
                s  += spS[ww * 128 + tid];
                ss += spSS[ww * 128 + tid];
            }
            if (EPI & EPI_LNPAIR) {
                float m = s * (1.0f / 256.0f);
                marr[tid] = m;
                rarr[tid] = rsqrtf(ss * (1.0f / 256.0f) - m * m + 1e-5f);
            }
            if (EPI & EPI_SSQ)
                invout[row0 + tid] = 1.0f / fmaxf(sqrtf(ss), 1e-12f);
        }
        __syncthreads();
    }

    if (EPI & (EPI_OUTPAIR | EPI_LNPAIR)) {
#pragma unroll
        for (int mi = 0; mi < 4; mi++) {
            const int lr = mw * 64 + mi * 16 + g;
            const int r = row0 + lr;
            float m0 = 0.f, r0 = 0.f, m1 = 0.f, r1 = 0.f;
            if (EPI & EPI_LNPAIR) {
                m0 = marr[lr]; r0 = rarr[lr];
                m1 = marr[lr + 8]; r1 = rarr[lr + 8];
            }
#pragma unroll
            for (int ni = 0; ni < 4; ni++) {
                const int colG = nw * 32 + ni * 8 + 2 * tig;
                float v0 = acc[mi][ni][0], v1 = acc[mi][ni][1];
                float v2 = acc[mi][ni][2], v3 = acc[mi][ni][3];
                if (EPI & EPI_OUTPAIR) {
                    __nv_bfloat16 h0, l0, h1, l1;
                    split2(v0, h0, l0); split2(v1, h1, l1);
                    *(unsigned*)(oh + (size_t)r * 256 + colG) = pack2(h0, h1);
                    *(unsigned*)(ol + (size_t)r * 256 + colG) = pack2(l0, l1);
                    split2(v2, h0, l0); split2(v3, h1, l1);
                    *(unsigned*)(oh + (size_t)(r + 8) * 256 + colG) = pack2(h0, h1);
                    *(unsigned*)(ol + (size_t)(r + 8) * 256 + colG) = pack2(l0, l1);
                }
                if (EPI & EPI_LNPAIR) {
                    const float g0 = sgam[colG], g1 = sgam[colG + 1];
                    const float b0 = sbet[colG], b1 = sbet[colG + 1];
                    float t0 = (v0 - m0) * r0 * g0 + b0;
                    float t1 = (v1 - m0) * r0 * g1 + b1;
                    float t2 = (v2 - m1) * r1 * g0 + b0;
                    float t3 = (v3 - m1) * r1 * g1 + b1;
                    if (EPI & EPI_LNGELU) {
                        t0 = geluf(t0); t1 = geluf(t1); t2 = geluf(t2); t3 = geluf(t3);
                    }
                    __nv_bfloat16 h0, l0, h1, l1;
                    split2(t0, h0, l0); split2(t1, h1, l1);
                    *(unsigned*)(o2h + (size_t)r * 256 + colG) = pack2(h0, h1);
                    *(unsigned*)(o2l + (size_t)r * 256 + colG) = pack2(l0, l1);
                    split2(t2, h0, l0); split2(t3, h1, l1);
                    *(unsigned*)(o2h + (size_t)(r + 8) * 256 + colG) = pack2(h0, h1);
                    *(unsigned*)(o2l + (size_t)(r + 8) * 256 + colG) = pack2(l0, l1);
                }
            }
        }
    }
}

// =============================================================================
// Pair GEMM (2-stage, 2 CTAs/SM). AS=1: A-single (2-term). Term-major MMAs.
// EPI_STAT2: emit row sum+ssq partials. EPI_ROWLN: fused LN-affine epilogue.
// =============================================================================
template <int EPI, int BT, int AS = 0>
__global__ __launch_bounds__(256, 2)
void tpair(const __nv_bfloat16* __restrict__ Ah, const __nv_bfloat16* __restrict__ Al, int lda,
           const __nv_bfloat16* __restrict__ Bh, const __nv_bfloat16* __restrict__ Bl, int ldb,
           const float* __restrict__ bias,
           float* __restrict__ outf, size_t ldout, size_t zstride,
           __nv_bfloat16* __restrict__ oh, __nv_bfloat16* __restrict__ ol, size_t opitch,
           const __nv_bfloat16* __restrict__ resH, const __nv_bfloat16* __restrict__ resL,
           const float* __restrict__ cscale, float* __restrict__ spart, size_t spitch,
           const float* __restrict__ rowm, const float* __restrict__ rowr,
           int Kblk)
{
    constexpr int BSZ = BT ? 8192 : 9216;
    constexpr int STG = 16384 + 2 * BSZ;
    extern __shared__ __align__(1024) unsigned char sm[];
    const uint32_t sb = smem_u32(sm);
    float* sp = (float*)(sm + 2 * STG);

    const int tid  = threadIdx.x;
    const int row0 = blockIdx.x * 128;
    const int col0 = blockIdx.y * 128;
    const int kz   = blockIdx.z * Kblk;
    const int nch  = Kblk >> 5;

    const int arow = tid >> 1, ak0 = (tid & 1) * 16;
    const int brow = tid >> 1, bk0 = (tid & 1) * 16;
    const int bkr = tid >> 3, bn0 = (tid & 7) * 16;
    const unsigned dA  = SWZ(arow * 64 + ak0 * 2);
    const unsigned dA2 = SWZ(arow * 64 + ak0 * 2 + 16);
    const unsigned dB  = BT ? SWZ(brow * 64 + bk0 * 2)      : SWZ(bkr * BSTRIDE0 + bn0 * 2);
    const unsigned dB2 = BT ? SWZ(brow * 64 + bk0 * 2 + 16) : SWZ(bkr * BSTRIDE0 + bn0 * 2 + 16);
    const __nv_bfloat16* ApH = Ah + (size_t)(row0 + arow) * lda + kz + ak0;
    const __nv_bfloat16* ApL = AS ? nullptr : Al + (size_t)(row0 + arow) * lda + kz + ak0;
    const __nv_bfloat16* BpH = BT ? Bh + (size_t)(col0 + brow) * ldb + kz + bk0
                                  : Bh + (size_t)(kz + bkr) * ldb + col0 + bn0;
    const __nv_bfloat16* BpL = BT ? Bl + (size_t)(col0 + brow) * ldb + kz + bk0
                                  : Bl + (size_t)(kz + bkr) * ldb + col0 + bn0;

    auto issue = [&](int c) {
        const int kc = c * 32;
        const uint32_t st = sb + (c & 1) * STG;
        cpasync16(st + dA, ApH + kc);            cpasync16(st + dA2, ApH + kc + 8);
        if (!AS) {
            cpasync16(st + 8192 + dA, ApL + kc);
            cpasync16(st + 8192 + dA2, ApL + kc + 8);
        }
        const size_t boff = BT ? (size_t)kc : (size_t)kc * ldb;
        cpasync16(st + 16384 + dB, BpH + boff);        cpasync16(st + 16384 + dB2, BpH + boff + 8);
        cpasync16(st + 16384 + BSZ + dB, BpL + boff);  cpasync16(st + 16384 + BSZ + dB2, BpL + boff + 8);
        cpcommit();
    };

    const int lane = tid & 31, w = tid >> 5;
    const int mw = w >> 2, nw = w & 3;
    const int g = lane >> 2, tig = lane & 3;
    const int lrow = (lane & 7) + ((lane >> 3) & 1) * 8;
    const int lkh  = (lane >> 4) * 16;
    const int trow = (lane & 7) + ((lane >> 4) & 1) * 8;
    const int tnh  = ((lane >> 3) & 1) * 16;

    float acc[4][4][4];
#pragma unroll
    for (int mi = 0; mi < 4; mi++)
#pragma unroll
        for (int ni = 0; ni < 4; ni++)
#pragma unroll
            for (int e = 0; e < 4; e++) acc[mi][ni][e] = 0.f;

    auto compute = [&](int c) {
        const uint32_t st = sb + (c & 1) * STG;
#pragma unroll
        for (int ks = 0; ks < 2; ks++) {
            unsigned ah[4][4], al[4][4];
#pragma unroll
            for (int mi = 0; mi < 4; mi++) {
                const int r = mw * 64 + mi * 16 + lrow;
                const unsigned off = SWZ(r * 64 + ks * 32 + lkh);
                LDSM4(ah[mi], st + off);
                if (!AS) LDSM4(al[mi], st + 8192 + off);
            }
#pragma unroll
            for (int nb = 0; nb < 2; nb++) {
                unsigned bh[4], bl[4];
                if (BT) {
                    const int n = nw * 32 + nb * 16 + lrow;
                    const unsigned off = SWZ(n * 64 + ks * 32 + lkh);
                    LDSM4(bh, st + 16384 + off);
                    LDSM4(bl, st + 16384 + BSZ + off);
                } else {
                    const int kr = ks * 16 + trow;
                    const unsigned off = SWZ(kr * BSTRIDE0 + (nw * 32 + nb * 16) * 2 + tnh);
                    LDSM4T(bh, st + 16384 + off);
                    LDSM4T(bl, st + 16384 + BSZ + off);
                }
                unsigned beh[2] = {bh[0], bh[2]}, boh[2] = {bh[1], bh[3]};
                unsigned bel[2] = {bl[0], bl[2]}, bol[2] = {bl[1], bl[3]};
#pragma unroll
                for (int mi = 0; mi < 4; mi++) mma16816(acc[mi][2 * nb],     ah[mi], beh);
#pragma unroll
                for (int mi = 0; mi < 4; mi++) mma16816(acc[mi][2 * nb + 1], ah[mi], boh);
#pragma unroll
                for (int mi = 0; mi < 4; mi++) mma16816(acc[mi][2 * nb],     ah[mi], bel);
#pragma unroll
                for (int mi = 0; mi < 4; mi++) mma16816(acc[mi][2 * nb + 1], ah[mi], bol);
                if (!AS) {
#pragma unroll
                    for (int mi = 0; mi < 4; mi++) mma16816(acc[mi][2 * nb],     al[mi], beh);
#pragma unroll
                    for (int mi = 0; mi < 4; mi++) mma16816(acc[mi][2 * nb + 1], al[mi], boh);
                }
            }
        }
    };

    issue(0);
    for (int c = 0; c < nch; c++) {
        if (c + 1 < nch) { issue(c + 1); cpwait1(); } else { cpwait0(); }
        __syncthreads();
        compute(c);
        __syncthreads();
    }

    float* outp = outf + (size_t)blockIdx.z * zstride;
    float srow0[4] = {0.f, 0.f, 0.f, 0.f}, srow1[4] = {0.f, 0.f, 0.f, 0.f};
    float tS0[4] = {0.f, 0.f, 0.f, 0.f}, tS1[4] = {0.f, 0.f, 0.f, 0.f};
#pragma unroll
    for (int mi = 0; mi < 4; mi++) {
        const int r = row0 + mw * 64 + mi * 16 + g;
        float lnm0 = 0.f, lnr0 = 0.f, lnm1 = 0.f, lnr1 = 0.f;
        if (EPI & EPI_ROWLN) {
            lnm0 = rowm[r]; lnr0 = rowr[r];
            lnm1 = rowm[r + 8]; lnr1 = rowr[r + 8];
        }
#pragma unroll
        for (int ni = 0; ni < 4; ni++) {
            const int colG = col0 + nw * 32 + ni * 8 + 2 * tig;
            float v0 = acc[mi][ni][0], v1 = acc[mi][ni][1];
            float v2 = acc[mi][ni][2], v3 = acc[mi][ni][3];
            if (EPI & EPI_BIAS) {
                float2 bb = *(const float2*)(bias + colG);
                v0 += bb.x; v1 += bb.y; v2 += bb.x; v3 += bb.y;
            }
            if (EPI & EPI_ROWLN) {
                const float c1a = cscale[colG], c1b = cscale[colG + 1];
                const float c2a = cscale[256 + colG], c2b = cscale[256 + colG + 1];
                v0 = lnr0 * v0 - lnm0 * lnr0 * c1a + c2a;
                v1 = lnr0 * v1 - lnm0 * lnr0 * c1b + c2b;
                v2 = lnr1 * v2 - lnm1 * lnr1 * c1a + c2a;
                v3 = lnr1 * v3 - lnm1 * lnr1 * c1b + c2b;
            }
            if (EPI & EPI_GELU) {
                v0 = geluf(v0); v1 = geluf(v1); v2 = geluf(v2); v3 = geluf(v3);
            }
            if (EPI & EPI_RESIDP) {
                unsigned uh0 = *(const unsigned*)(resH + (size_t)r * 256 + colG);
                unsigned ul0 = *(const unsigned*)(resL + (size_t)r * 256 + colG);
                unsigned uh1 = *(const unsigned*)(resH + (size_t)(r + 8) * 256 + colG);
                unsigned ul1 = *(const unsigned*)(resL + (size_t)(r + 8) * 256 + colG);
                v0 += upk_lo(uh0) + upk_lo(ul0); v1 += upk_hi(uh0) + upk_hi(ul0);
                v2 += upk_lo(uh1) + upk_lo(ul1); v3 += upk_hi(uh1) + upk_hi(ul1);
            }
            if (EPI & EPI_CSCALE) {
                float2 cs = *(const float2*)(cscale + colG);
                v0 *= cs.x; v1 *= cs.y; v2 *= cs.x; v3 *= cs.y;
            }
            if (EPI & EPI_CSSQ) {
                const float s0 = cscale[colG]     + cscale[ldout + colG];
                const float s1 = cscale[colG + 1] + cscale[ldout + colG + 1];
                const float i0 = 1.0f / fmaxf(sqrtf(s0), 1e-12f);
                const float i1 = 1.0f / fmaxf(sqrtf(s1), 1e-12f);
                v0 *= i0; v1 *= i1; v2 *= i0; v3 *= i1;
            }
            if (EPI & EPI_OUTF32) {
                *(float2*)(outp + (size_t)r * ldout + colG)       = make_float2(v0, v1);
                *(float2*)(outp + (size_t)(r + 8) * ldout + colG) = make_float2(v2, v3);
            }
            if (EPI & EPI_SSQ) {
                srow0[mi] += v0 * v0 + v1 * v1;
                srow1[mi] += v2 * v2 + v3 * v3;
            }
            if (EPI & EPI_STAT2) {
                tS0[mi] += v0 + v1;       tS1[mi] += v2 + v3;
                srow0[mi] += v0 * v0 + v1 * v1;
                srow1[mi] += v2 * v2 + v3 * v3;
            }
            if (EPI & EPI_EXP1) {
                __nv_bfloat16 h0 = __float2bfloat16(__expf(v0));
                __nv_bfloat16 h1 = __float2bfloat16(__expf(v1));
                __nv_bfloat16 h2 = __float2bfloat16(__expf(v2));
                __nv_bfloat16 h3 = __float2bfloat16(__expf(v3));
                if (EPI & EPI_SPART) {
                    srow0[mi] += __bfloat162float(h0) + __bfloat162float(h1);
                    srow1[mi] += __bfloat162float(h2) + __bfloat162float(h3);
                }
                *(unsigned*)(oh + (size_t)r * opitch + colG)       = pack2(h0, h1);
                *(unsigned*)(oh + (size_t)(r + 8) * opitch + colG) = pack2(h2, h3);
            }
            if (EPI & EPI_OUTPAIR) {
                __nv_bfloat16 h0, l0, h1, l1;
                split2(v0, h0, l0); split2(v1, h1, l1);
                *(unsigned*)(oh + (size_t)r * opitch + colG) = pack2(h0, h1);
                *(unsigned*)(ol + (size_t)r * opitch + colG) = pack2(l0, l1);
                split2(v2, h0, l0); split2(v3, h1, l1);
                *(unsigned*)(oh + (size_t)(r + 8) * opitch + colG) = pack2(h0, h1);
                *(unsigned*)(ol + (size_t)(r + 8) * opitch + colG) = pack2(l0, l1);
            }
        }
    }
    if (EPI & EPI_STAT2) {
        float (*spp)[128] = (float(*)[128])sp;
        // pass 1: sums
#pragma unroll
        for (int mi = 0; mi < 4; mi++) {
            float s0 = tS0[mi], s1 = tS1[mi];
            s0 += __shfl_xor_sync(0xffffffffu, s0, 1);
            s0 += __shfl_xor_sync(0xffffffffu, s0, 2);
            s1 += __shfl_xor_sync(0xffffffffu, s1, 1);
            s1 += __shfl_xor_sync(0xffffffffu, s1, 2);
            if (tig == 0) {
                spp[nw][mw * 64 + mi * 16 + g]     = s0;
                spp[nw][mw * 64 + mi * 16 + g + 8] = s1;
            }
        }
        __syncthreads();
        if (tid < 128)
            spart[((size_t)blockIdx.y * 2 + 0) * spitch + row0 + tid] =
                spp[0][tid] + spp[1][tid] + spp[2][tid] + spp[3][tid];
        __syncthreads();
        // pass 2: ssq
#pragma unroll
        for (int mi = 0; mi < 4; mi++) {
            float s0 = srow0[mi], s1 = srow1[mi];
            s0 += __shfl_xor_sync(0xffffffffu, s0, 1);
            s0 += __shfl_xor_sync(0xffffffffu, s0, 2);
            s1 += __shfl_xor_sync(0xffffffffu, s1, 1);
            s1 += __shfl_xor_sync(0xffffffffu, s1, 2);
            if (tig == 0) {
                spp[nw][mw * 64 + mi * 16 + g]     = s0;
                spp[nw][mw * 64 + mi * 16 + g + 8] = s1;
            }
        }
        __syncthreads();
        if (tid < 128)
            spart[((size_t)blockIdx.y * 2 + 1) * spitch + row0 + tid] =
                spp[0][tid] + spp[1][tid] + spp[2][tid] + spp[3][tid];
    } else if (EPI & (EPI_SPART | EPI_SSQ)) {
        float (*spp)[128] = (float(*)[128])sp;
#pragma unroll
        for (int mi = 0; mi < 4; mi++) {
            float s0 = srow0[mi], s1 = srow1[mi];
            s0 += __shfl_xor_sync(0xffffffffu, s0, 1);
            s0 += __shfl_xor_sync(0xffffffffu, s0, 2);
            s1 += __shfl_xor_sync(0xffffffffu, s1, 1);
            s1 += __shfl_xor_sync(0xffffffffu, s1, 2);
            if (tig == 0) {
                spp[nw][mw * 64 + mi * 16 + g]     = s0;
                spp[nw][mw * 64 + mi * 16 + g + 8] = s1;
            }
        }
        __syncthreads();
        if (tid < 128)
            spart[(size_t)blockIdx.y * spitch + row0 + tid] =
                spp[0][tid] + spp[1][tid] + spp[2][tid] + spp[3][tid];
    }
}

// ---------------------------------------------------------------------------
// Legacy fp32-input GEMM (query/score path only). LN on A input only.
// ---------------------------------------------------------------------------
enum { AOP_ID = 0, AOP_LN = 1 };
#define LEPI_BIAS  1
#define LEPI_GELU  2
#define LEPI_RESID 4

template <int AOP, int EPI>
__global__ __launch_bounds__(256)
void tlegacy(const float* __restrict__ A, int lda,
             const float* __restrict__ B, int ldb,
             const float* __restrict__ bias,
             float* __restrict__ out, size_t ldout, int Kblk,
             const float* __restrict__ mean, const float* __restrict__ rstd,
             const float* __restrict__ lng, const float* __restrict__ lnb,
             const float* __restrict__ resid)
{
    __shared__ __align__(1024) unsigned char sm[16384 + 2 * 9216];
    const uint32_t sb = smem_u32(sm);
    const int tid = threadIdx.x;
    const int row0 = blockIdx.x * 128;
    const int col0 = blockIdx.y * 128;
    const int nch = Kblk >> 5;

    __shared__ float sgam[256], sbet[256];
    if (AOP == AOP_LN) {
        if (tid < Kblk) { sgam[tid] = lng[tid]; sbet[tid] = lnb[tid]; }
    }

    const int arow = tid >> 1, ak0 = (tid & 1) * 16;
    float mr = 0.f, rr = 0.f;
    if (AOP == AOP_LN) { mr = mean[row0 + arow]; rr = rstd[row0 + arow]; }
    const float* Ap = A + (size_t)(row0 + arow) * lda;
    const int bkr = tid >> 3, bn0 = (tid & 7) * 16;
    const float* Bp0 = B + (size_t)bkr * ldb + col0 + bn0;

    const int lane = tid & 31, w = tid >> 5;
    const int mw = w >> 2, nw = w & 3;
    const int g = lane >> 2, tig = lane & 3;
    const int lrow = (lane & 7) + ((lane >> 3) & 1) * 8;
    const int lkh = (lane >> 4) * 16;
    const int trow = (lane & 7) + ((lane >> 4) & 1) * 8;
    const int tnh = ((lane >> 3) & 1) * 16;

    float acc[4][4][4];
#pragma unroll
    for (int mi = 0; mi < 4; mi++)
#pragma unroll
        for (int ni = 0; ni < 4; ni++)
#pragma unroll
            for (int e = 0; e < 4; e++) acc[mi][ni][e] = 0.f;

    for (int c = 0; c < nch; c++) {
        const int kc = c * 32;
        __syncthreads();
#pragma unroll
        for (int i = 0; i < 4; i++) {
            float4 t = *(const float4*)(Ap + kc + ak0 + i * 4);
            float v[4] = {t.x, t.y, t.z, t.w};
            if (AOP == AOP_LN) {
#pragma unroll
                for (int j = 0; j < 4; j++) {
                    const int kg = kc + ak0 + i * 4 + j;
                    v[j] = (v[j] - mr) * rr * sgam[kg] + sbet[kg];
                }
            }
            const unsigned base = arow * 64 + (ak0 + i * 4) * 2;
            __nv_bfloat16 h0, l0, h1, l1;
            split2(v[0], h0, l0); split2(v[1], h1, l1);
            *(unsigned*)(sm + SWZ(base)) = pack2(h0, h1);
            *(unsigned*)(sm + 8192 + SWZ(base)) = pack2(l0, l1);
            split2(v[2], h0, l0); split2(v[3], h1, l1);
            *(unsigned*)(sm + SWZ(base + 4)) = pack2(h0, h1);
            *(unsigned*)(sm + 8192 + SWZ(base + 4)) = pack2(l0, l1);
        }
#pragma unroll
        for (int i = 0; i < 4; i++) {
            float4 t = *(const float4*)(Bp0 + (size_t)kc * ldb + i * 4);
            float v[4] = {t.x, t.y, t.z, t.w};
            const unsigned base = bkr * BSTRIDE0 + (bn0 + i * 4) * 2;
            __nv_bfloat16 h0, l0, h1, l1;
            split2(v[0], h0, l0); split2(v[1], h1, l1);
            *(unsigned*)(sm + 16384 + SWZ(base)) = pack2(h0, h1);
            *(unsigned*)(sm + 16384 + 9216 + SWZ(base)) = pack2(l0, l1);
            split2(v[2], h0, l0); split2(v[3], h1, l1);
            *(unsigned*)(sm + 16384 + SWZ(base + 4)) = pack2(h0, h1);
            *(unsigned*)(sm + 16384 + 9216 + SWZ(base + 4)) = pack2(l0, l1);
        }
        __syncthreads();
#pragma unroll
        for (int ks = 0; ks < 2; ks++) {
            unsigned ah[4][4], al[4][4];
#pragma unroll
            for (int mi = 0; mi < 4; mi++) {
                const int r = mw * 64 + mi * 16 + lrow;
                const unsigned off = SWZ(r * 64 + ks * 32 + lkh);
                LDSM4(ah[mi], sb + off);
                LDSM4(al[mi], sb + 8192 + off);
            }
#pragma unroll
            for (int nb = 0; nb < 2; nb++) {
                unsigned bh[4], bl[4];
                const int kr = ks * 16 + trow;
                const unsigned off = SWZ(kr * BSTRIDE0 + (nw * 32 + nb * 16) * 2 + tnh);
                LDSM4T(bh, sb + 16384 + off);
                LDSM4T(bl, sb + 16384 + 9216 + off);
                unsigned beh[2] = {bh[0], bh[2]}, boh[2] = {bh[1], bh[3]};
                unsigned bel[2] = {bl[0], bl[2]}, bol[2] = {bl[1], bl[3]};
#pragma unroll
                for (int mi = 0; mi < 4; mi++) mma16816(acc[mi][2 * nb],     ah[mi], beh);
#pragma unroll
                for (int mi = 0; mi < 4; mi++) mma16816(acc[mi][2 * nb + 1], ah[mi], boh);
#pragma unroll
                for (int mi = 0; mi < 4; mi++) mma16816(acc[mi][2 * nb],     ah[mi], bel);
#pragma unroll
                for (int mi = 0; mi < 4; mi++) mma16816(acc[mi][2 * nb + 1], ah[mi], bol);
#pragma unroll
                for (int mi = 0; mi < 4; mi++) mma16816(acc[mi][2 * nb],     al[mi], beh);
#pragma unroll
                for (int mi = 0; mi < 4; mi++) mma16816(acc[mi][2 * nb + 1], al[mi], boh);
            }
        }
    }

#pragma unroll
    for (int mi = 0; mi < 4; mi++) {
        const int r = row0 + mw * 64 + mi * 16 + g;
#pragma unroll
        for (int ni = 0; ni < 4; ni++) {
            const int colG = col0 + nw * 32 + ni * 8 + 2 * tig;
            float v0 = acc[mi][ni][0], v1 = acc[mi][ni][1];
            float v2 = acc[mi][ni][2], v3 = acc[mi][ni][3];
            if (EPI & LEPI_BIAS) {
                float2 bb = *(const float2*)(bias + colG);
                v0 += bb.x; v1 += bb.y; v2 += bb.x; v3 += bb.y;
            }
            if (EPI & LEPI_GELU) {
                v0 = geluf(v0); v1 = geluf(v1); v2 = geluf(v2); v3 = geluf(v3);
            }
            if (EPI & LEPI_RESID) {
                float2 ra = *(const float2*)(resid + (size_t)r * 256 + colG);
                float2 rb = *(const float2*)(resid + (size_t)(r + 8) * 256 + colG);
                v0 += ra.x; v1 += ra.y; v2 += rb.x; v3 += rb.y;
            }
            *(float2*)(out + (size_t)r * ldout + colG)       = make_float2(v0, v1);
            *(float2*)(out + (size_t)(r + 8) * ldout + colG) = make_float2(v2, v3);
        }
    }
}

// ---------------- prep kernels ----------------------------------------------
__global__ void prep_pf(const float* __restrict__ pf,
                        __nv_bfloat16* __restrict__ H, __nv_bfloat16* __restrict__ L, int N)
{
    int idx = blockIdx.x * 256 + threadIdx.x;
    int row = idx / 12, c8 = (idx % 12) * 8;
    if (row >= N) return;
    __nv_bfloat16 h[8], l[8];
#pragma unroll
    for (int j = 0; j < 8; j++) {
        int k = c8 + j;
        float v = (k < 72) ? pf[(size_t)row * 72 + k] : 0.f;
        split2(v, h[j], l[j]);
    }
    *(uint4*)(H + (size_t)row * 96 + c8) = *(uint4*)h;
    *(uint4*)(L + (size_t)row * 96 + c8) = *(uint4*)l;
}

// ALL weight preps in one launch. w3 gets gamma folded in: W3' = diag(g3)@W3.
__global__ void prep_weights(
    const float* __restrict__ w1, __nv_bfloat16* __restrict__ w1H, __nv_bfloat16* __restrict__ w1L,
    const float* __restrict__ w2, __nv_bfloat16* __restrict__ w2H, __nv_bfloat16* __restrict__ w2L,
    const float* __restrict__ w3, __nv_bfloat16* __restrict__ w3H, __nv_bfloat16* __restrict__ w3L,
    const float* __restrict__ w4, __nv_bfloat16* __restrict__ w4H, __nv_bfloat16* __restrict__ w4L,
    const float* __restrict__ g3)
{
    const int bx = blockIdx.x, tid = threadIdx.x;
    __nv_bfloat16 h[8], l[8];
    if (bx < 12) {
        int idx = bx * 256 + tid;
        int n = idx / 12, c8 = (idx % 12) * 8;
        if (n >= 256) return;
#pragma unroll
        for (int j = 0; j < 8; j++) {
            int k = c8 + j;
            float v = (k < 72) ? w1[(size_t)k * 256 + n] : 0.f;
            split2(v, h[j], l[j]);
        }
        *(uint4*)(w1H + (size_t)n * 96 + c8) = *(uint4*)h;
        *(uint4*)(w1L + (size_t)n * 96 + c8) = *(uint4*)l;
    } else {
        const int which = (bx - 12) >> 5;
        const int b2 = (bx - 12) & 31;
        const float* W = (which == 0) ? w2 : (which == 1) ? w3 : w4;
        __nv_bfloat16* H = (which == 0) ? w2H : (which == 1) ? w3H : w4H;
        __nv_bfloat16* L = (which == 0) ? w2L : (which == 1) ? w3L : w4L;
        int idx = b2 * 256 + tid;
        int row = idx / 32, c8 = (idx % 32) * 8;
        const float scale = (which == 1) ? g3[row] : 1.0f;
#pragma unroll
        for (int j = 0; j < 8; j++) {
            split2(W[(size_t)row * 256 + c8 + j] * scale, h[j], l[j]);
        }
        *(uint4*)(H + (size_t)row * 256 + c8) = *(uint4*)h;
        *(uint4*)(L + (size_t)row * 256 + c8) = *(uint4*)l;
    }
}

// c1_j = sum_k gamma_k*W_kj ; c2p_j = sum_k beta_k*W_kj + b1_j   (1 block)
__global__ void prep_c12(const float* __restrict__ W, const float* __restrict__ gam,
                         const float* __restrict__ bet, const float* __restrict__ b1,
                         float* __restrict__ c12)
{
    const int j = threadIdx.x;
    float s1 = 0.f, s2 = 0.f;
    for (int k = 0; k < 256; k++) {
        const float wv = W[(size_t)k * 256 + j];
        s1 += gam[k] * wv;
        s2 += bet[k] * wv;
    }
    c12[j] = s1;
    c12[256 + j] = s2 + b1[j];
}

// combine GEMM2's [yb][S/SS] partials into mean/rstd per row
__global__ void combine_stats(const float* __restrict__ sp, float* __restrict__ mean,
                              float* __restrict__ rstd, int N)
{
    int i = blockIdx.x * 256 + threadIdx.x;
    if (i < N) {
        const float S = sp[i]            + sp[(size_t)2 * N + i];
        const float Q = sp[(size_t)N + i] + sp[(size_t)3 * N + i];
        const float m = S * (1.0f / 256.0f);
        mean[i] = m;
        rstd[i] = rsqrtf(Q * (1.0f / 256.0f) - m * m + 1e-5f);
    }
}

// ---------------- misc small kernels ----------------------------------------
__global__ __launch_bounds__(256)
void ln_stats(const float* __restrict__ X, float* __restrict__ mean,
              float* __restrict__ rstd, int M)
{
    int warp = (blockIdx.x * blockDim.x + threadIdx.x) >> 5;
    if (warp >= M) return;
    int lane = threadIdx.x & 31;
    const float* row = X + (size_t)warp * 256;
    float s = 0.f, ss = 0.f;
#pragma unroll
    for (int j = 0; j < 8; j++) { float v = row[lane + 32 * j]; s += v; ss += v * v; }
#pragma unroll
    for (int o = 16; o; o >>= 1) {
        s  += __shfl_xor_sync(0xffffffffu, s, o);
        ss += __shfl_xor_sync(0xffffffffu, ss, o);
    }
    if (lane == 0) {
        float m = s * (1.0f / 256.0f);
        mean[warp] = m;
        rstd[warp] = rsqrtf(ss * (1.0f / 256.0f) - m * m + 1e-5f);
    }
}

__global__ __launch_bounds__(256)
void qnormpair(const float* __restrict__ qe, const float* __restrict__ lsc,
               __nv_bfloat16* __restrict__ H, __nv_bfloat16* __restrict__ L)
{
    const int q = blockIdx.x;
    const int d = threadIdx.x;
    const float v = qe[(size_t)q * 256 + d];
    __shared__ float sh[256];
    sh[d] = v * v;
    __syncthreads();
    for (int o = 128; o; o >>= 1) {
        if (d < o) sh[d] += sh[d + o];
        __syncthreads();
    }
    const float inv = 1.0f / fmaxf(sqrtf(sh[0]), 1e-12f);
    const float x = v * inv * expf(lsc[0]);
    __nv_bfloat16 h, l;
    split2(x, h, l);
    H[(size_t)q * 256 + d] = h;
    L[(size_t)q * 256 + d] = l;
}

__global__ __launch_bounds__(256)
void reduce_refined(const float* __restrict__ Ppart, const float* __restrict__ spart,
                    const float* __restrict__ qe, float* __restrict__ refined,
                    int CH, int NB)
{
    const int q = blockIdx.x;
    const int d = threadIdx.x;
    __shared__ float sh[256];
    float s = 0.f;
    for (int i = d; i < NB; i += 256) s += spart[(size_t)i * 128 + q];
    sh[d] = s;
    __syncthreads();
    for (int o = 128; o; o >>= 1) {
        if (d < o) sh[d] += sh[d + o];
        __syncthreads();
    }
    const float stot = sh[0];
    float p0 = 0.f, p1 = 0.f, p2 = 0.f, p3 = 0.f;
    for (int c = 0; c < CH; c += 4) {
        p0 += Ppart[((size_t)(c + 0) * 128 + q) * 256 + d];
        p1 += Ppart[((size_t)(c + 1) * 128 + q) * 256 + d];
        p2 += Ppart[((size_t)(c + 2) * 128 + q) * 256 + d];
        p3 += Ppart[((size_t)(c + 3) * 128 + q) * 256 + d];
    }
    refined[(size_t)q * 256 + d] = qe[(size_t)q * 256 + d] + ((p0 + p1) + (p2 + p3)) / stot;
}

__global__ __launch_bounds__(256)
void score_kernel(const float* __restrict__ A2s, const float* __restrict__ w2,
                  const float* __restrict__ b2, float* __restrict__ out)
{
    const int q = blockIdx.x;
    const int d = threadIdx.x;
    __shared__ float sh[256];
    sh[d] = A2s[(size_t)q * 256 + d] * w2[d];
    __syncthreads();
    for (int o = 128; o; o >>= 1) {
        if (d < o) sh[d] += sh[d + o];
        __syncthreads();
    }
    if (d == 0) out[q] = sh[0] + b2[0];
}

// ---------------------------------------------------------------------------
extern "C" void kernel_launch(void* const* d_in, const int* in_sizes, int n_in,
                              void* d_out, int out_size)
{
    const float* point_feat = (const float*)d_in[0];
    const float* ip_w1 = (const float*)d_in[1];
    const float* ip_b1 = (const float*)d_in[2];
    const float* ip_ln_g = (const float*)d_in[3];
    const float* ip_ln_b = (const float*)d_in[4];
    const float* ip_w2 = (const float*)d_in[5];
    const float* ip_b2 = (const float*)d_in[6];
    const float* ph_ln_g = (const float*)d_in[7];
    const float* ph_ln_b = (const float*)d_in[8];
    const float* ph_w1 = (const float*)d_in[9];
    const float* ph_b1 = (const float*)d_in[10];
    const float* ph_w2 = (const float*)d_in[11];
    const float* ph_b2 = (const float*)d_in[12];
    const float* q_embed = (const float*)d_in[13];
    const float* qh_ln_g = (const float*)d_in[14];
    const float* qh_ln_b = (const float*)d_in[15];
    const float* qh_w1 = (const float*)d_in[16];
    const float* qh_b1 = (const float*)d_in[17];
    const float* qh_w2 = (const float*)d_in[18];
    const float* qh_b2 = (const float*)d_in[19];
    const float* sh_ln_g = (const float*)d_in[20];
    const float* sh_ln_b = (const float*)d_in[21];
    const float* sh_w1 = (const float*)d_in[22];
    const float* sh_b1 = (const float*)d_in[23];
    const float* sh_w2 = (const float*)d_in[24];
    const float* sh_b2 = (const float*)d_in[25];
    const float* logit_scale = (const float*)d_in[26];

    const int N = in_sizes[0] / 72;

    float* out = (float*)d_out;
    const size_t offScore = (size_t)128 * N;
    const size_t offPE = offScore + 128;
    const size_t offRef = offPE + (size_t)N * 256;
    float* mask = out;
    float* score = out + offScore;
    float* pe = out + offPE;
    float* refined = out + offRef;

    __nv_bfloat16 *pfH, *pfL, *xH, *xL, *aH, *aL, *hH, *hL, *peH, *peL, *emH;
    __nv_bfloat16 *w1H, *w1L, *w2H, *w2L, *w3H, *w3L, *w4H, *w4L, *qmH, *qmL;
    float *meanQ, *rstdQ, *A2q, *qe, *meanN, *rstdN, *c12, *spart, *mpart, *Ppart;
    cudaGetSymbolAddress((void**)&pfH, g_pfH); cudaGetSymbolAddress((void**)&pfL, g_pfL);
    cudaGetSymbolAddress((void**)&xH, g_xH);   cudaGetSymbolAddress((void**)&xL, g_xL);
    cudaGetSymbolAddress((void**)&aH, g_aH);   cudaGetSymbolAddress((void**)&aL, g_aL);
    cudaGetSymbolAddress((void**)&hH, g_hH);   cudaGetSymbolAddress((void**)&hL, g_hL);
    cudaGetSymbolAddress((void**)&peH, g_peH); cudaGetSymbolAddress((void**)&peL, g_peL);
    cudaGetSymbolAddress((void**)&emH, g_emH);
    cudaGetSymbolAddress((void**)&w1H, g_w1H); cudaGetSymbolAddress((void**)&w1L, g_w1L);
    cudaGetSymbolAddress((void**)&w2H, g_w2H); cudaGetSymbolAddress((void**)&w2L, g_w2L);
    cudaGetSymbolAddress((void**)&w3H, g_w3H); cudaGetSymbolAddress((void**)&w3L, g_w3L);
    cudaGetSymbolAddress((void**)&w4H, g_w4H); cudaGetSymbolAddress((void**)&w4L, g_w4L);
    cudaGetSymbolAddress((void**)&qmH, g_qmH); cudaGetSymbolAddress((void**)&qmL, g_qmL);
    cudaGetSymbolAddress((void**)&meanQ, g_meanQ); cudaGetSymbolAddress((void**)&rstdQ, g_rstdQ);
    cudaGetSymbolAddress((void**)&A2q, g_A2q); cudaGetSymbolAddress((void**)&qe, g_qe);
    cudaGetSymbolAddress((void**)&meanN, g_meanN); cudaGetSymbolAddress((void**)&rstdN, g_rstdN);
    cudaGetSymbolAddress((void**)&c12, g_c12);
    cudaGetSymbolAddress((void**)&spart, g_spart);
    cudaGetSymbolAddress((void**)&mpart, g_mpart);
    cudaGetSymbolAddress((void**)&Ppart, g_Ppart);

    // dynamic smem opt-in
    const int SMEM_BT0 = 2 * (16384 + 2 * 9216) + 2048;   // 71680
    const int SMEM_BT1 = 2 * (16384 + 2 * 8192) + 2048;   // 67584
    cudaFuncSetAttribute(tpair256<EPI_BIAS | EPI_LNPAIR | EPI_LNGELU>,
                         cudaFuncAttributeMaxDynamicSharedMemorySize, SMEM256);
    cudaFuncSetAttribute(tpair<EPI_BIAS | EPI_OUTPAIR | EPI_STAT2, 0>,
                         cudaFuncAttributeMaxDynamicSharedMemorySize, SMEM_BT0);
    cudaFuncSetAttribute(tpair<EPI_ROWLN | EPI_GELU | EPI_OUTPAIR, 0>,
                         cudaFuncAttributeMaxDynamicSharedMemorySize, SMEM_BT0);
    cudaFuncSetAttribute(tpair<EPI_BIAS | EPI_RESIDP | EPI_OUTF32 | EPI_OUTPAIR | EPI_SSQ, 0>,
                         cudaFuncAttributeMaxDynamicSharedMemorySize, SMEM_BT0);
    cudaFuncSetAttribute(tpair<EPI_CSSQ | EPI_OUTF32 | EPI_EXP1 | EPI_SPART, 1>,
                         cudaFuncAttributeMaxDynamicSharedMemorySize, SMEM_BT1);
    cudaFuncSetAttribute(tpair<EPI_OUTF32, 0, 1>,
                         cudaFuncAttributeMaxDynamicSharedMemorySize, SMEM_BT0);

    // -------- preps --------
    prep_pf<<<(N * 12 + 255) / 256, 256>>>(point_feat, pfH, pfL, N);
    prep_weights<<<108, 256>>>(ip_w1, w1H, w1L, ip_w2, w2H, w2L,
                               ph_w1, w3H, w3L, ph_w2, w4H, w4L, ph_ln_g);
    prep_c12<<<1, 256>>>(ph_w1, ph_ln_g, ph_ln_b, ph_b1, c12);

    const dim3 gBig(N / 128, 2);

    // -------- point pipeline --------
    // a = gelu(LN(pf @ ip_w1 + ip_b1))  (fused; verified)
    tpair256<EPI_BIAS | EPI_LNPAIR | EPI_LNGELU><<<N / 128, 512, SMEM256>>>(
        pfH, pfL, 96, w1H, w1L, 96, ip_b1,
        nullptr, 0, nullptr, nullptr, aH, aL,
        nullptr, nullptr, ip_ln_g, ip_ln_b, nullptr, 96);
    // h = a @ ip_w2 + ip_b2 (pairs) + row sum/ssq partials for LN stats
    tpair<EPI_BIAS | EPI_OUTPAIR | EPI_STAT2, 0><<<gBig, 256, SMEM_BT0>>>(
        aH, aL, 256, w2H, w2L, 256, ip_b2,
        nullptr, 0, 0, hH, hL, 256, nullptr, nullptr, nullptr, spart, (size_t)N,
        nullptr, nullptr, 256);
    combine_stats<<<(N + 255) / 256, 256>>>(spart, meanN, rstdN, N);
    // x = gelu(r*(h @ w3') - m*r*c1 + c2')  == gelu(LN(h) @ ph_w1 + ph_b1)
    tpair<EPI_ROWLN | EPI_GELU | EPI_OUTPAIR, 0><<<gBig, 256, SMEM_BT0>>>(
        hH, hL, 256, w3H, w3L, 256, nullptr,
        nullptr, 0, 0, xH, xL, 256, nullptr, nullptr, c12, nullptr, 0,
        meanN, rstdN, 256);
    // pe = h + x @ ph_w2 + ph_b2 (fp32 to d_out + pairs + fused row-SSQ partials)
    tpair<EPI_BIAS | EPI_RESIDP | EPI_OUTF32 | EPI_OUTPAIR | EPI_SSQ, 0><<<gBig, 256, SMEM_BT0>>>(
        xH, xL, 256, w4H, w4L, 256, ph_b2,
        pe, 256, 0, peH, peL, 256, hH, hL, nullptr, spart, (size_t)N,
        nullptr, nullptr, 256);

    // -------- query pipeline (legacy, tiny) --------
    ln_stats<<<16, 256>>>(q_embed, meanQ, rstdQ, 128);
    tlegacy<AOP_LN, LEPI_BIAS | LEPI_GELU><<<dim3(1, 2), 256>>>(
        q_embed, 256, qh_w1, 256, qh_b1, A2q, 256, 256,
        meanQ, rstdQ, qh_ln_g, qh_ln_b, nullptr);
    tlegacy<AOP_ID, LEPI_BIAS | LEPI_RESID><<<dim3(1, 2), 256>>>(
        A2q, 256, qh_w2, 256, qh_b2, qe, 256, 256,
        nullptr, nullptr, nullptr, nullptr, q_embed);
    qnormpair<<<128, 256>>>(qe, logit_scale, qmH, qmL);

    // -------- mask logits + em + softmax partials; invpe inline from SSQ ----
    tpair<EPI_CSSQ | EPI_OUTF32 | EPI_EXP1 | EPI_SPART, 1><<<dim3(1, N / 128), 256, SMEM_BT1>>>(
        qmH, qmL, 256, peH, peL, 256, nullptr,
        mask, (size_t)N, 0, emH, nullptr, (size_t)N, nullptr, nullptr, spart, mpart, 128,
        nullptr, nullptr, 256);

    // -------- weighted aggregation (2-term, A-single), z=128 ---------------
    tpair<EPI_OUTF32, 0, 1><<<dim3(1, 2, 128), 256, SMEM_BT0>>>(
        emH, nullptr, N, peH, peL, 256, nullptr,
        Ppart, 256, (size_t)128 * 256, nullptr, nullptr, 0,
        nullptr, nullptr, nullptr, nullptr, 0, nullptr, nullptr, 2048);
    reduce_refined<<<128, 256>>>(Ppart, mpart, qe, refined, 128, N / 128);

    // -------- score head (legacy) --------
    ln_stats<<<16, 256>>>(refined, meanQ, rstdQ, 128);
    tlegacy<AOP_LN, LEPI_BIAS | LEPI_GELU><<<dim3(1, 2), 256>>>(
        refined, 256, sh_w1, 256, sh_b1, A2q, 256, 256,
        meanQ, rstdQ, sh_ln_g, sh_ln_b, nullptr);
    score_kernel<<<128, 256>>>(A2q, sh_w2, sh_b2, score);
}